// round 9
// baseline (speedup 1.0000x reference)
#include <cuda_runtime.h>
#include <cuda_bf16.h>
#include <math.h>
#include <stdint.h>

// Problem constants
#define Bb    8
#define TQ    1024
#define TK    1024
#define DIMX  1024
#define NH    16
#define HD    64
#define SCALE 0.03125f
#define NEGV  -1.0e9f
#define MROWS (Bb * TQ)
#define SC2L  (0.03125f * 1.44269504088896f)

// ================= PTX helpers =================
__device__ __forceinline__ uint32_t smem_u32(const void* p) {
    uint32_t a;
    asm("{ .reg .u64 t; cvta.to.shared.u64 t, %1; cvt.u32.u64 %0, t; }"
        : "=r"(a) : "l"(p));
    return a;
}
#define CP_ASYNC16(dst_u32, src_ptr) \
    asm volatile("cp.async.cg.shared.global [%0], [%1], 16;" \
        :: "r"(dst_u32), "l"(src_ptr))
#define CP_COMMIT() asm volatile("cp.async.commit_group;" ::: "memory")
#define CP_WAIT(n)  asm volatile("cp.async.wait_group %0;" :: "n"(n) : "memory")

#define LDSM4(r, addr) \
    asm volatile("ldmatrix.sync.aligned.m8n8.x4.shared.b16 {%0,%1,%2,%3}, [%4];" \
        : "=r"((r)[0]), "=r"((r)[1]), "=r"((r)[2]), "=r"((r)[3]) : "r"(addr))
#define LDSM4T(r, addr) \
    asm volatile("ldmatrix.sync.aligned.m8n8.x4.trans.shared.b16 {%0,%1,%2,%3}, [%4];" \
        : "=r"((r)[0]), "=r"((r)[1]), "=r"((r)[2]), "=r"((r)[3]) : "r"(addr))

#define MMA16816(c, a, b0, b1) \
    asm volatile("mma.sync.aligned.m16n8k16.row.col.f32.bf16.bf16.f32 " \
        "{%0,%1,%2,%3}, {%4,%5,%6,%7}, {%8,%9}, {%0,%1,%2,%3};" \
        : "+f"((c)[0]), "+f"((c)[1]), "+f"((c)[2]), "+f"((c)[3]) \
        : "r"((a)[0]), "r"((a)[1]), "r"((a)[2]), "r"((a)[3]), "r"(b0), "r"(b1))

__device__ __forceinline__ uint32_t pbf2(float lo, float hi) {
    uint32_t d;
    asm("cvt.rn.bf16x2.f32 %0, %1, %2;" : "=r"(d) : "f"(hi), "f"(lo));
    return d;
}
__device__ __forceinline__ float ex2f(float x) {
    float y;
    asm("ex2.approx.ftz.f32 %0, %1;" : "=f"(y) : "f"(x));
    return y;
}

// ================= scratch =================
__device__ __align__(16) __nv_bfloat16 g_qph[(size_t)MROWS * DIMX];
__device__ __align__(16) __nv_bfloat16 g_kph[(size_t)MROWS * DIMX];
__device__ __align__(16) __nv_bfloat16 g_vph[(size_t)MROWS * DIMX];
__device__ __align__(16) __nv_bfloat16 g_vpl[(size_t)MROWS * DIMX];
__device__ __align__(16) __nv_bfloat16 g_ah[(size_t)24 * 1024 * 1024];  // acts q|k|v, or beta
__device__ __align__(16) __nv_bfloat16 g_al[(size_t)24 * 1024 * 1024];
__device__ __align__(16) __nv_bfloat16 g_bh[(size_t)3 * 1024 * 1024];
__device__ __align__(16) __nv_bfloat16 g_bl[(size_t)3 * 1024 * 1024];
__device__ unsigned char g_src8[Bb * TK];
__device__ unsigned char g_tgt8[Bb * TQ];

// ================= mask canonicalization =================
__global__ void mask_convert(const unsigned char* __restrict__ raw, int n, int which)
{
    __shared__ int has3F, oddNZ;
    if (threadIdx.x == 0) { has3F = 0; oddNZ = 0; }
    __syncthreads();
    int lf = 0, lo = 0;
    for (int i = threadIdx.x; i < n; i += blockDim.x) {
        unsigned char c = raw[i];
        if (c == 0x3F) lf = 1;
        if ((i & 3) && c) lo = 1;
    }
    if (lf) atomicOr(&has3F, 1);
    if (lo) atomicOr(&oddNZ, 1);
    __syncthreads();
    unsigned char* out = which ? g_tgt8 : g_src8;
    int mode = has3F ? 2 : (oddNZ ? 0 : 1);
    for (int i = threadIdx.x; i < n; i += blockDim.x) {
        unsigned char v;
        if (mode == 2)      v = (((const float*)raw)[i] != 0.0f) ? 1 : 0;
        else if (mode == 1) v = (((const int*)raw)[i]   != 0)    ? 1 : 0;
        else                v = (raw[i] != 0) ? 1 : 0;
        out[i] = v;
    }
}

// ================= fp32 -> bf16 conversions =================
__device__ __forceinline__ void split_store(const float4* __restrict__ x,
                                            __nv_bfloat16* __restrict__ hi,
                                            __nv_bfloat16* __restrict__ lo, size_t i)
{
    float4 f = x[i];
    __nv_bfloat16 h0 = __float2bfloat16_rn(f.x);
    __nv_bfloat16 h1 = __float2bfloat16_rn(f.y);
    __nv_bfloat16 h2 = __float2bfloat16_rn(f.z);
    __nv_bfloat16 h3 = __float2bfloat16_rn(f.w);
    __nv_bfloat16 l0 = __float2bfloat16_rn(f.x - __bfloat162float(h0));
    __nv_bfloat16 l1 = __float2bfloat16_rn(f.y - __bfloat162float(h1));
    __nv_bfloat16 l2 = __float2bfloat16_rn(f.z - __bfloat162float(h2));
    __nv_bfloat16 l3 = __float2bfloat16_rn(f.w - __bfloat162float(h3));
    __nv_bfloat162* Hp = (__nv_bfloat162*)(hi + 4 * i);
    __nv_bfloat162* Lp = (__nv_bfloat162*)(lo + 4 * i);
    Hp[0] = __halves2bfloat162(h0, h1);
    Hp[1] = __halves2bfloat162(h2, h3);
    Lp[0] = __halves2bfloat162(l0, l1);
    Lp[1] = __halves2bfloat162(l2, l3);
}
__device__ __forceinline__ void hi_store(const float4* __restrict__ x,
                                         __nv_bfloat16* __restrict__ hi, size_t i)
{
    float4 f = x[i];
    __nv_bfloat162* Hp = (__nv_bfloat162*)(hi + 4 * i);
    Hp[0] = __halves2bfloat162(__float2bfloat16_rn(f.x), __float2bfloat16_rn(f.y));
    Hp[1] = __halves2bfloat162(__float2bfloat16_rn(f.z), __float2bfloat16_rn(f.w));
}

__global__ __launch_bounds__(256)
void conv_split(const float4* __restrict__ x, __nv_bfloat16* __restrict__ hi,
                __nv_bfloat16* __restrict__ lo, int n4)
{
    int i = blockIdx.x * 256 + threadIdx.x;
    if (i >= n4) return;
    split_store(x, hi, lo, i);
}

// q,k hi-only; v hi+lo; Wq,Wk hi-only; Wv hi+lo
__global__ __launch_bounds__(256)
void conv_all(const float4* __restrict__ q, const float4* __restrict__ k,
              const float4* __restrict__ v, const float4* __restrict__ wq,
              const float4* __restrict__ wk, const float4* __restrict__ wv)
{
    const size_t ACT = (size_t)8 * 1024 * 1024;
    const size_t WSEG = (size_t)1024 * 1024;
    int bid = blockIdx.x;
    if (bid < 24576) {
        int seg = bid >> 13;
        size_t i = ((size_t)(bid & 8191)) * 256 + threadIdx.x;
        if (seg == 2) split_store(v, g_ah + 2 * ACT, g_al + 2 * ACT, i);
        else          hi_store(seg ? k : q, g_ah + seg * ACT, i);
    } else {
        bid -= 24576;
        int seg = bid >> 10;
        size_t i = ((size_t)(bid & 1023)) * 256 + threadIdx.x;
        if (seg == 2) split_store(wv, g_bh + 2 * WSEG, g_bl + 2 * WSEG, i);
        else          hi_store(seg ? wk : wq, g_bh + seg * WSEG, i);
    }
}

extern __shared__ char smem_raw[];

// ================= unified projection GEMM =================
// seg 0(Q)/1(K): 1-pass hi-only.  seg 2(V): 3-pass, hi/lo outputs.
// BK=32, SMEM rows interleave [32 hi | 32 lo] in 128B; 3 stages x 32KB; 2 CTAs/SM.
#define P_STG 32768
#define P_SMEM (3 * P_STG)

__global__ __launch_bounds__(256, 2)
void gemm_proj(const float* __restrict__ bias0, const float* __restrict__ bias1,
               const float* __restrict__ bias2)
{
    const uint32_t sb = smem_u32(smem_raw);
    const int tid  = threadIdx.x;
    const int lane = tid & 31;
    const int wid  = tid >> 5;
    const int wm = (wid >> 2) * 64;
    const int wn = (wid & 3) * 32;

    const int seg = blockIdx.x >> 3;
    const int bn  = (blockIdx.x & 7) * 128;
    const int bm  = blockIdx.y * 128;
    const bool full = (seg == 2);
    const __nv_bfloat16* Ahg = g_ah + (size_t)seg * 8 * 1024 * 1024;
    const __nv_bfloat16* Alg = g_al + (size_t)seg * 8 * 1024 * 1024;
    const __nv_bfloat16* Bhg = g_bh + (size_t)seg * 1024 * 1024;
    const __nv_bfloat16* Blg = g_bl + (size_t)seg * 1024 * 1024;
    const float* bias = (seg == 0) ? bias0 : (seg == 1) ? bias1 : bias2;
    __nv_bfloat16* Yh = (seg == 0) ? g_qph : (seg == 1) ? g_kph : g_vph;

    float C[4][4][4];
#pragma unroll
    for (int i = 0; i < 4; i++)
#pragma unroll
        for (int j = 0; j < 4; j++)
#pragma unroll
            for (int r = 0; r < 4; r++) C[i][j][r] = 0.0f;

    auto load_stage = [&](int s, int kc) {
        const uint32_t st = sb + s * P_STG;
        const int koff = kc * 32;
#pragma unroll
        for (int i = 0; i < 4; i++) {
            int idx = tid + i * 256;
            int row = idx >> 3, c = idx & 7;
            uint32_t off = row * 128 + c * 16;
            uint32_t sw = off ^ ((off >> 3) & 0x70);
            int gcol = koff + (c & 3) * 8;
            if (c < 4) {
                CP_ASYNC16(st + sw,         Ahg + (size_t)(bm + row) * 1024 + gcol);
                CP_ASYNC16(st + 16384 + sw, Bhg + (size_t)(bn + row) * 1024 + gcol);
            } else if (full) {
                CP_ASYNC16(st + sw,         Alg + (size_t)(bm + row) * 1024 + gcol);
                CP_ASYNC16(st + 16384 + sw, Blg + (size_t)(bn + row) * 1024 + gcol);
            }
        }
        CP_COMMIT();
    };

    const int q  = lane >> 3;
    const int lr = lane & 7;
    const int am_row = wm + (q & 1) * 8 + lr;
    const int a_kq   = (q >> 1) * 16;
    const int bn_row = wn + (q >> 1) * 8 + lr;
    const int b_kq   = (q & 1) * 16;

    load_stage(0, 0);
    load_stage(1, 1);

    for (int kc = 0; kc < 32; kc++) {
        if (kc < 31) CP_WAIT(1); else CP_WAIT(0);
        __syncthreads();
        if (kc + 2 < 32) load_stage((kc + 2) % 3, kc + 2);

        const uint32_t st = sb + (kc % 3) * P_STG;
#pragma unroll
        for (int ks = 0; ks < 2; ks++) {
            uint32_t aH[4][4], aL[4][4], bH[2][4], bL[2][4];
#pragma unroll
            for (int i = 0; i < 4; i++) {
                uint32_t off = (uint32_t)(am_row + i * 16) * 128 + ks * 32 + a_kq;
                uint32_t sw = off ^ ((off >> 3) & 0x70);
                LDSM4(aH[i], st + sw);
                if (full) {
                    uint32_t ofl = off + 64;
                    uint32_t swl = ofl ^ ((ofl >> 3) & 0x70);
                    LDSM4(aL[i], st + swl);
                }
            }
#pragma unroll
            for (int j2 = 0; j2 < 2; j2++) {
                uint32_t off = (uint32_t)(bn_row + j2 * 16) * 128 + ks * 32 + b_kq;
                uint32_t sw = off ^ ((off >> 3) & 0x70);
                LDSM4(bH[j2], st + 16384 + sw);
                if (full) {
                    uint32_t ofl = off + 64;
                    uint32_t swl = ofl ^ ((ofl >> 3) & 0x70);
                    LDSM4(bL[j2], st + 16384 + swl);
                }
            }
#pragma unroll
            for (int i = 0; i < 4; i++)
#pragma unroll
                for (int j = 0; j < 4; j++) {
                    const int jj = j >> 1, jo = (j & 1) * 2;
                    MMA16816(C[i][j], aH[i], bH[jj][jo], bH[jj][jo + 1]);
                    if (full) {
                        MMA16816(C[i][j], aH[i], bL[jj][jo], bL[jj][jo + 1]);
                        MMA16816(C[i][j], aL[i], bH[jj][jo], bH[jj][jo + 1]);
                    }
                }
        }
    }

    const int g  = lane >> 2;
    const int tg = lane & 3;
#pragma unroll
    for (int i = 0; i < 4; i++) {
#pragma unroll
        for (int j = 0; j < 4; j++) {
            const int col = bn + wn + j * 8 + tg * 2;
            const int r0 = bm + wm + i * 16 + g;
            const int r1 = r0 + 8;
            float b0v = bias[col], b1v = bias[col + 1];
            float y00 = C[i][j][0] + b0v, y01 = C[i][j][1] + b1v;
            float y10 = C[i][j][2] + b0v, y11 = C[i][j][3] + b1v;
            *(uint32_t*)(Yh + (size_t)r0 * 1024 + col) = pbf2(y00, y01);
            *(uint32_t*)(Yh + (size_t)r1 * 1024 + col) = pbf2(y10, y11);
            if (full) {
                float l00 = y00 - __bfloat162float(__float2bfloat16_rn(y00));
                float l01 = y01 - __bfloat162float(__float2bfloat16_rn(y01));
                float l10 = y10 - __bfloat162float(__float2bfloat16_rn(y10));
                float l11 = y11 - __bfloat162float(__float2bfloat16_rn(y11));
                *(uint32_t*)(g_vpl + (size_t)r0 * 1024 + col) = pbf2(l00, l01);
                *(uint32_t*)(g_vpl + (size_t)r1 * 1024 + col) = pbf2(l10, l11);
            }
        }
    }
}

// ================= beta @ V GEMM (3-pass, BK=32, 2 CTAs/SM) =================
// SMEM stage: A beta interleaved 16K @0; V hi 8K @16384 (2 halves x 4K); V lo 8K @24576.
#define B_STG 32768
#define B_SMEM (3 * B_STG)

__global__ __launch_bounds__(256, 2)
void gemm_beta(float* __restrict__ Yf)
{
    const uint32_t sb = smem_u32(smem_raw);
    const int tid  = threadIdx.x;
    const int lane = tid & 31;
    const int wid  = tid >> 5;
    const int wm = (wid >> 2) * 64;
    const int wn = (wid & 3) * 32;

    const int b0 = blockIdx.x * 2;
    const int bm = blockIdx.y * 128;
    const int h  = blockIdx.z;
    const size_t arow0 = (size_t)h * 1024 + bm;

    float C[4][4][4];
#pragma unroll
    for (int i = 0; i < 4; i++)
#pragma unroll
        for (int j = 0; j < 4; j++)
#pragma unroll
            for (int r = 0; r < 4; r++) C[i][j][r] = 0.0f;

    auto load_stage = [&](int s, int kc) {
        const uint32_t st = sb + s * B_STG;
        const int koff = kc * 32;
        // A (beta) interleaved hi/lo
#pragma unroll
        for (int i = 0; i < 4; i++) {
            int idx = tid + i * 256;
            int row = idx >> 3, c = idx & 7;
            uint32_t off = row * 128 + c * 16;
            uint32_t sw = off ^ ((off >> 3) & 0x70);
            const __nv_bfloat16* src = (c < 4) ? g_ah : g_al;
            CP_ASYNC16(st + sw, src + (arow0 + row) * 1024 + koff + (c & 3) * 8);
        }
        // V natural [k][d], hi and lo tiles
#pragma unroll
        for (int i = 0; i < 4; i++) {
            int idx = tid + i * 256;
            int half = idx >> 9;
            int r2 = idx & 511;
            int arr = r2 >> 8;
            int rr = r2 & 255;
            int row = rr >> 3, c = rr & 7;
            uint32_t off = row * 128 + c * 16;
            uint32_t sw = off ^ ((off >> 3) & 0x70);
            const __nv_bfloat16* src = arr ? g_vpl : g_vph;
            CP_ASYNC16(st + 16384 + arr * 8192 + half * 4096 + sw,
                       src + ((size_t)(b0 + half) * 1024 + koff + row) * 1024 + h * 64 + c * 8);
        }
        CP_COMMIT();
    };

    const int q  = lane >> 3;
    const int lr = lane & 7;
    const int am_row = wm + (q & 1) * 8 + lr;
    const int a_kq   = (q >> 1) * 16;

    load_stage(0, 0);
    load_stage(1, 1);

    for (int kc = 0; kc < 32; kc++) {
        if (kc < 31) CP_WAIT(1); else CP_WAIT(0);
        __syncthreads();
        if (kc + 2 < 32) load_stage((kc + 2) % 3, kc + 2);

        const uint32_t st = sb + (kc % 3) * B_STG;
#pragma unroll
        for (int ks = 0; ks < 2; ks++) {
            uint32_t aH[4][4], aL[4][4], bH[2][4], bL[2][4];
#pragma unroll
            for (int i = 0; i < 4; i++) {
                uint32_t off = (uint32_t)(am_row + i * 16) * 128 + ks * 32 + a_kq;
                uint32_t sw = off ^ ((off >> 3) & 0x70);
                LDSM4(aH[i], st + sw);
                uint32_t ofl = off + 64;
                uint32_t swl = ofl ^ ((ofl >> 3) & 0x70);
                LDSM4(aL[i], st + swl);
            }
#pragma unroll
            for (int j2 = 0; j2 < 2; j2++) {
                const int n16 = wn + j2 * 16;
                const int half = n16 >> 6, d0 = n16 & 63;
                uint32_t off = (uint32_t)(ks * 16 + (q & 1) * 8 + lr) * 128 +
                               (d0 + (q >> 1) * 8) * 2;
                uint32_t sw = off ^ ((off >> 3) & 0x70);
                LDSM4T(bH[j2], st + 16384 + half * 4096 + sw);
                LDSM4T(bL[j2], st + 16384 + 8192 + half * 4096 + sw);
            }
#pragma unroll
            for (int i = 0; i < 4; i++)
#pragma unroll
                for (int j = 0; j < 4; j++) {
                    const int jj = j >> 1, jo = (j & 1) * 2;
                    MMA16816(C[i][j], aH[i], bH[jj][jo], bH[jj][jo + 1]);
                    MMA16816(C[i][j], aH[i], bL[jj][jo], bL[jj][jo + 1]);
                    MMA16816(C[i][j], aL[i], bH[jj][jo], bH[jj][jo + 1]);
                }
        }
    }

    const int g  = lane >> 2;
    const int tg = lane & 3;
#pragma unroll
    for (int i = 0; i < 4; i++) {
#pragma unroll
        for (int j = 0; j < 4; j++) {
            const int ncol = wn + j * 8 + tg * 2;
            const int r0 = bm + wm + i * 16 + g;
            const int r1 = r0 + 8;
            const int n = blockIdx.x * 128 + ncol;
            const int bb = n >> 6, dd = n & 63;
            float* p0 = Yf + ((size_t)bb * 1024 + r0) * 1024 + h * 64 + dd;
            float* p1 = Yf + ((size_t)bb * 1024 + r1) * 1024 + h * 64 + dd;
            float2 o0 = *(float2*)p0, o1 = *(float2*)p1;
            o0.x += C[i][j][0]; o0.y += C[i][j][1];
            o1.x += C[i][j][2]; o1.y += C[i][j][3];
            *(float2*)p0 = o0;
            *(float2*)p1 = o1;
        }
    }
}

// ================= flash attention (S 1-pass, PV hi-only) =================
#define FQH 0
#define FST0 16384
#define FKH 0
#define FVH 8192
#define FSRC 16384
#define FSTG 16512
#define FSMEM (16384 + 3 * FSTG)

__global__ __launch_bounds__(256, 2)
void flash_tc(float* __restrict__ out)
{
    char* sm = smem_raw;
    const uint32_t sb = smem_u32(sm);
    const int tid  = threadIdx.x;
    const int lane = tid & 31;
    const int w    = tid >> 5;
    const int q0 = blockIdx.x * 128;
    const int h  = blockIdx.y;
    const int b  = blockIdx.z;
    const int g  = lane >> 2;
    const int tg = lane & 3;
    const int qq = lane >> 3;
    const int lr = lane & 7;

    {
#pragma unroll
        for (int i = 0; i < 4; i++) {
            int idx = tid + i * 256;
            int row = idx >> 3, c = idx & 7;
            uint32_t off = row * 128 + c * 16;
            uint32_t sw = off ^ ((off >> 3) & 0x70);
            size_t gq = ((size_t)b * 1024 + q0 + row) * 1024 + h * 64 + c * 8;
            CP_ASYNC16(sb + FQH + sw, g_qph + gq);
        }
        CP_COMMIT();
    }

    auto load_stage = [&](int s, int kt) {
        const uint32_t st = sb + FST0 + s * FSTG;
        const int k0 = kt * 64;
#pragma unroll
        for (int i = 0; i < 2; i++) {
            int idx = tid + i * 256;
            int row = idx >> 3, c = idx & 7;
            uint32_t off = row * 128 + c * 16;
            uint32_t sw = off ^ ((off >> 3) & 0x70);
            size_t gk = ((size_t)b * 1024 + k0 + row) * 1024 + h * 64 + c * 8;
            CP_ASYNC16(st + FKH + sw, g_kph + gk);
            CP_ASYNC16(st + FVH + sw, g_vph + gk);
        }
        if (tid < 4)
            CP_ASYNC16(st + FSRC + tid * 16, g_src8 + b * 1024 + k0 + tid * 16);
        CP_COMMIT();
    };

    load_stage(0, 0);
    load_stage(1, 1);

    const unsigned char t0m = g_tgt8[b * 1024 + q0 + w * 16 + g];
    const unsigned char t1m = g_tgt8[b * 1024 + q0 + w * 16 + 8 + g];

    float m0r = -3.0e38f, m1r = -3.0e38f, l0r = 0.0f, l1r = 0.0f;
    float O[8][4];
#pragma unroll
    for (int i = 0; i < 8; i++)
#pragma unroll
        for (int r = 0; r < 4; r++) O[i][r] = 0.0f;

    uint32_t aQh[4][4];

    for (int kt = 0; kt < 16; kt++) {
        if (kt < 15) CP_WAIT(1); else CP_WAIT(0);
        __syncthreads();
        if (kt + 2 < 16) load_stage((kt + 2) % 3, kt + 2);

        if (kt == 0) {
#pragma unroll
            for (int kc = 0; kc < 4; kc++) {
                uint32_t off = (uint32_t)(w * 16 + (qq & 1) * 8 + lr) * 128 + (qq >> 1) * 16 + kc * 32;
                uint32_t sw = off ^ ((off >> 3) & 0x70);
                LDSM4(aQh[kc], sb + FQH + sw);
            }
        }

        const uint32_t st = sb + FST0 + (kt % 3) * FSTG;
        char* stp = sm + FST0 + (kt % 3) * FSTG;

        // ---- S = Qh @ Kh^T ----
        float C[8][4];
#pragma unroll
        for (int i = 0; i < 8; i++)
#pragma unroll
            for (int r = 0; r < 4; r++) C[i][r] = 0.0f;
#pragma unroll
        for (int ks = 0; ks < 4; ks++) {
#pragma unroll
            for (int j2 = 0; j2 < 4; j2++) {
                uint32_t bh[4];
                uint32_t off = (uint32_t)(j2 * 16 + (qq >> 1) * 8 + lr) * 128 + (qq & 1) * 16 + ks * 32;
                uint32_t sw = off ^ ((off >> 3) & 0x70);
                LDSM4(bh, st + FKH + sw);
                MMA16816(C[j2 * 2],     aQh[ks], bh[0], bh[1]);
                MMA16816(C[j2 * 2 + 1], aQh[ks], bh[2], bh[3]);
            }
        }

        // ---- mask + online softmax (log2 domain) ----
        float mx0 = -3.0e38f, mx1 = -3.0e38f;
#pragma unroll
        for (int nt = 0; nt < 8; nt++) {
            unsigned char s0 = *(unsigned char*)(stp + FSRC + nt * 8 + tg * 2);
            unsigned char s1 = *(unsigned char*)(stp + FSRC + nt * 8 + tg * 2 + 1);
            C[nt][0] = (t0m && s0) ? C[nt][0] * SC2L : NEGV;
            C[nt][1] = (t0m && s1) ? C[nt][1] * SC2L : NEGV;
            C[nt][2] = (t1m && s0) ? C[nt][2] * SC2L : NEGV;
            C[nt][3] = (t1m && s1) ? C[nt][3] * SC2L : NEGV;
            mx0 = fmaxf(mx0, fmaxf(C[nt][0], C[nt][1]));
            mx1 = fmaxf(mx1, fmaxf(C[nt][2], C[nt][3]));
        }
        mx0 = fmaxf(mx0, __shfl_xor_sync(0xFFFFFFFF, mx0, 1));
        mx0 = fmaxf(mx0, __shfl_xor_sync(0xFFFFFFFF, mx0, 2));
        mx1 = fmaxf(mx1, __shfl_xor_sync(0xFFFFFFFF, mx1, 1));
        mx1 = fmaxf(mx1, __shfl_xor_sync(0xFFFFFFFF, mx1, 2));

        float mn0 = fmaxf(m0r, mx0), mn1 = fmaxf(m1r, mx1);
        float f0 = ex2f(m0r - mn0), f1 = ex2f(m1r - mn1);
        m0r = mn0; m1r = mn1;

        float s0 = 0.0f, s1 = 0.0f;
#pragma unroll
        for (int nt = 0; nt < 8; nt++) {
            C[nt][0] = ex2f(C[nt][0] - mn0);
            C[nt][1] = ex2f(C[nt][1] - mn0);
            C[nt][2] = ex2f(C[nt][2] - mn1);
            C[nt][3] = ex2f(C[nt][3] - mn1);
            s0 += C[nt][0] + C[nt][1];
            s1 += C[nt][2] + C[nt][3];
        }
        s0 += __shfl_xor_sync(0xFFFFFFFF, s0, 1);
        s0 += __shfl_xor_sync(0xFFFFFFFF, s0, 2);
        s1 += __shfl_xor_sync(0xFFFFFFFF, s1, 1);
        s1 += __shfl_xor_sync(0xFFFFFFFF, s1, 2);
        l0r = l0r * f0 + s0;
        l1r = l1r * f1 + s1;

#pragma unroll
        for (int nt = 0; nt < 8; nt++) {
            O[nt][0] *= f0; O[nt][1] *= f0;
            O[nt][2] *= f1; O[nt][3] *= f1;
        }

        // ---- pack P (hi only) ----
        uint32_t aPh[4][4];
#pragma unroll
        for (int kc = 0; kc < 4; kc++) {
            const int n0 = kc * 2, n1 = kc * 2 + 1;
            aPh[kc][0] = pbf2(C[n0][0], C[n0][1]);
            aPh[kc][1] = pbf2(C[n0][2], C[n0][3]);
            aPh[kc][2] = pbf2(C[n1][0], C[n1][1]);
            aPh[kc][3] = pbf2(C[n1][2], C[n1][3]);
        }

        // ---- O += Ph @ Vh ----
#pragma unroll
        for (int kc = 0; kc < 4; kc++) {
#pragma unroll
            for (int nd = 0; nd < 4; nd++) {
                uint32_t vh[4];
                uint32_t off = (uint32_t)(kc * 16 + (qq & 1) * 8 + lr) * 128 +
                               (nd * 16 + (qq >> 1) * 8) * 2;
                uint32_t sw = off ^ ((off >> 3) & 0x70);
                LDSM4T(vh, st + FVH + sw);
                MMA16816(O[nd * 2],     aPh[kc], vh[0], vh[1]);
                MMA16816(O[nd * 2 + 1], aPh[kc], vh[2], vh[3]);
            }
        }
    }

    const float il0 = 1.0f / l0r, il1 = 1.0f / l1r;
    const int r0 = q0 + w * 16 + g;
    const int r1 = r0 + 8;
#pragma unroll
    for (int nt = 0; nt < 8; nt++) {
        const int col = h * 64 + nt * 8 + tg * 2;
        float2 w0 = make_float2(O[nt][0] * il0, O[nt][1] * il0);
        float2 w1 = make_float2(O[nt][2] * il1, O[nt][3] * il1);
        *(float2*)(out + ((size_t)b * 1024 + r0) * 1024 + col) = w0;
        *(float2*)(out + ((size_t)b * 1024 + r1) * 1024 + col) = w1;
    }
}

// ================= kernel_launch =================
extern "C" void kernel_launch(void* const* d_in, const int* in_sizes, int n_in,
                              void* d_out, int out_size)
{
    const float* q    = (const float*)d_in[0];
    const float* k    = (const float*)d_in[1];
    const float* v    = (const float*)d_in[2];
    const float* beta = (const float*)d_in[3];
    const unsigned char* srcm = (const unsigned char*)d_in[4];
    const unsigned char* tgtm = (const unsigned char*)d_in[5];
    const float* Wq = (const float*)d_in[6];
    const float* bq = (const float*)d_in[7];
    const float* Wk = (const float*)d_in[8];
    const float* bk = (const float*)d_in[9];
    const float* Wv = (const float*)d_in[10];
    const float* bv = (const float*)d_in[11];
    float* out = (float*)d_out;

    void *ah, *al;
    cudaGetSymbolAddress(&ah, g_ah);
    cudaGetSymbolAddress(&al, g_al);
    __nv_bfloat16* AH = (__nv_bfloat16*)ah;
    __nv_bfloat16* AL = (__nv_bfloat16*)al;

    cudaFuncSetAttribute(gemm_proj, cudaFuncAttributeMaxDynamicSharedMemorySize, P_SMEM);
    cudaFuncSetAttribute(gemm_beta, cudaFuncAttributeMaxDynamicSharedMemorySize, B_SMEM);
    cudaFuncSetAttribute(flash_tc,  cudaFuncAttributeMaxDynamicSharedMemorySize, FSMEM);

    mask_convert<<<1, 1024>>>(srcm, Bb * TK, 0);
    mask_convert<<<1, 1024>>>(tgtm, Bb * TQ, 1);

    conv_all<<<27648, 256>>>((const float4*)q, (const float4*)k, (const float4*)v,
                             (const float4*)Wq, (const float4*)Wk, (const float4*)Wv);

    // unified Q/K/V projections
    gemm_proj<<<dim3(24, 64), 256, P_SMEM>>>(bq, bk, bv);

    // flash attention (writes out)
    flash_tc<<<dim3(TQ / 128, NH, Bb), 256, FSMEM>>>(out);

    // beta @ V accumulated into out
    const int n4_beta = (NH * TQ * TK) / 4;
    conv_split<<<(n4_beta + 255) / 256, 256>>>((const float4*)beta, AH, AL, n4_beta);
    gemm_beta<<<dim3(4, 8, 16), 256, B_SMEM>>>(out);
}

// round 11
// speedup vs baseline: 1.2455x; 1.2455x over previous
#include <cuda_runtime.h>
#include <cuda_bf16.h>
#include <math.h>
#include <stdint.h>

// Problem constants
#define Bb    8
#define TQ    1024
#define TK    1024
#define DIMX  1024
#define NH    16
#define HD    64
#define SCALE 0.03125f
#define NEGV  -1.0e9f
#define MROWS (Bb * TQ)
#define SC2L  (0.03125f * 1.44269504088896f)

// ================= PTX helpers =================
__device__ __forceinline__ uint32_t smem_u32(const void* p) {
    uint32_t a;
    asm("{ .reg .u64 t; cvta.to.shared.u64 t, %1; cvt.u32.u64 %0, t; }"
        : "=r"(a) : "l"(p));
    return a;
}
#define CP_ASYNC16(dst_u32, src_ptr) \
    asm volatile("cp.async.cg.shared.global [%0], [%1], 16;" \
        :: "r"(dst_u32), "l"(src_ptr))
#define CP_COMMIT() asm volatile("cp.async.commit_group;" ::: "memory")
#define CP_WAIT(n)  asm volatile("cp.async.wait_group %0;" :: "n"(n) : "memory")

#define LDSM4(r, addr) \
    asm volatile("ldmatrix.sync.aligned.m8n8.x4.shared.b16 {%0,%1,%2,%3}, [%4];" \
        : "=r"((r)[0]), "=r"((r)[1]), "=r"((r)[2]), "=r"((r)[3]) : "r"(addr))
#define LDSM4T(r, addr) \
    asm volatile("ldmatrix.sync.aligned.m8n8.x4.trans.shared.b16 {%0,%1,%2,%3}, [%4];" \
        : "=r"((r)[0]), "=r"((r)[1]), "=r"((r)[2]), "=r"((r)[3]) : "r"(addr))

#define MMA16816(c, a, b0, b1) \
    asm volatile("mma.sync.aligned.m16n8k16.row.col.f32.bf16.bf16.f32 " \
        "{%0,%1,%2,%3}, {%4,%5,%6,%7}, {%8,%9}, {%0,%1,%2,%3};" \
        : "+f"((c)[0]), "+f"((c)[1]), "+f"((c)[2]), "+f"((c)[3]) \
        : "r"((a)[0]), "r"((a)[1]), "r"((a)[2]), "r"((a)[3]), "r"(b0), "r"(b1))

__device__ __forceinline__ uint32_t pbf2(float lo, float hi) {
    uint32_t d;
    asm("cvt.rn.bf16x2.f32 %0, %1, %2;" : "=r"(d) : "f"(hi), "f"(lo));
    return d;
}
__device__ __forceinline__ float ex2f(float x) {
    float y;
    asm("ex2.approx.ftz.f32 %0, %1;" : "=f"(y) : "f"(x));
    return y;
}

// ================= scratch =================
__device__ __align__(16) __nv_bfloat16 g_qph[(size_t)MROWS * DIMX];
__device__ __align__(16) __nv_bfloat16 g_kph[(size_t)MROWS * DIMX];
__device__ __align__(16) __nv_bfloat16 g_vph[(size_t)MROWS * DIMX];
__device__ __align__(16) __nv_bfloat16 g_vpl[(size_t)MROWS * DIMX];
__device__ __align__(16) __nv_bfloat16 g_ah[(size_t)24 * 1024 * 1024];  // acts q|k|v, or beta
__device__ __align__(16) __nv_bfloat16 g_al[(size_t)24 * 1024 * 1024];
__device__ __align__(16) __nv_bfloat16 g_bh[(size_t)3 * 1024 * 1024];
__device__ __align__(16) __nv_bfloat16 g_bl[(size_t)3 * 1024 * 1024];
__device__ unsigned char g_src8[Bb * TK];
__device__ unsigned char g_tgt8[Bb * TQ];

// ================= mask canonicalization (both masks, 1 launch) =================
__global__ void mask_convert2(const unsigned char* __restrict__ raw0,
                              const unsigned char* __restrict__ raw1, int n)
{
    const unsigned char* raw = blockIdx.x ? raw1 : raw0;
    unsigned char* out = blockIdx.x ? g_tgt8 : g_src8;
    __shared__ int has3F, oddNZ;
    if (threadIdx.x == 0) { has3F = 0; oddNZ = 0; }
    __syncthreads();
    int lf = 0, lo = 0;
    for (int i = threadIdx.x; i < n; i += blockDim.x) {
        unsigned char c = raw[i];
        if (c == 0x3F) lf = 1;
        if ((i & 3) && c) lo = 1;
    }
    if (lf) atomicOr(&has3F, 1);
    if (lo) atomicOr(&oddNZ, 1);
    __syncthreads();
    int mode = has3F ? 2 : (oddNZ ? 0 : 1);
    for (int i = threadIdx.x; i < n; i += blockDim.x) {
        unsigned char v;
        if (mode == 2)      v = (((const float*)raw)[i] != 0.0f) ? 1 : 0;
        else if (mode == 1) v = (((const int*)raw)[i]   != 0)    ? 1 : 0;
        else                v = (raw[i] != 0) ? 1 : 0;
        out[i] = v;
    }
}

// ================= fp32 -> bf16 conversions =================
__device__ __forceinline__ void split_store(const float4* __restrict__ x,
                                            __nv_bfloat16* __restrict__ hi,
                                            __nv_bfloat16* __restrict__ lo, size_t i)
{
    float4 f = x[i];
    __nv_bfloat16 h0 = __float2bfloat16_rn(f.x);
    __nv_bfloat16 h1 = __float2bfloat16_rn(f.y);
    __nv_bfloat16 h2 = __float2bfloat16_rn(f.z);
    __nv_bfloat16 h3 = __float2bfloat16_rn(f.w);
    __nv_bfloat16 l0 = __float2bfloat16_rn(f.x - __bfloat162float(h0));
    __nv_bfloat16 l1 = __float2bfloat16_rn(f.y - __bfloat162float(h1));
    __nv_bfloat16 l2 = __float2bfloat16_rn(f.z - __bfloat162float(h2));
    __nv_bfloat16 l3 = __float2bfloat16_rn(f.w - __bfloat162float(h3));
    __nv_bfloat162* Hp = (__nv_bfloat162*)(hi + 4 * i);
    __nv_bfloat162* Lp = (__nv_bfloat162*)(lo + 4 * i);
    Hp[0] = __halves2bfloat162(h0, h1);
    Hp[1] = __halves2bfloat162(h2, h3);
    Lp[0] = __halves2bfloat162(l0, l1);
    Lp[1] = __halves2bfloat162(l2, l3);
}
__device__ __forceinline__ void hi_store(const float4* __restrict__ x,
                                         __nv_bfloat16* __restrict__ hi, size_t i)
{
    float4 f = x[i];
    __nv_bfloat162* Hp = (__nv_bfloat162*)(hi + 4 * i);
    Hp[0] = __halves2bfloat162(__float2bfloat16_rn(f.x), __float2bfloat16_rn(f.y));
    Hp[1] = __halves2bfloat162(__float2bfloat16_rn(f.z), __float2bfloat16_rn(f.w));
}

__global__ __launch_bounds__(256)
void conv_split(const float4* __restrict__ x, __nv_bfloat16* __restrict__ hi,
                __nv_bfloat16* __restrict__ lo, int n4)
{
    int i = blockIdx.x * 256 + threadIdx.x;
    if (i >= n4) return;
    split_store(x, hi, lo, i);
}

// q,k hi-only; v hi+lo; Wq,Wk hi-only; Wv hi+lo
__global__ __launch_bounds__(256)
void conv_all(const float4* __restrict__ q, const float4* __restrict__ k,
              const float4* __restrict__ v, const float4* __restrict__ wq,
              const float4* __restrict__ wk, const float4* __restrict__ wv)
{
    const size_t ACT = (size_t)8 * 1024 * 1024;
    const size_t WSEG = (size_t)1024 * 1024;
    int bid = blockIdx.x;
    if (bid < 24576) {
        int seg = bid >> 13;
        size_t i = ((size_t)(bid & 8191)) * 256 + threadIdx.x;
        if (seg == 2) split_store(v, g_ah + 2 * ACT, g_al + 2 * ACT, i);
        else          hi_store(seg ? k : q, g_ah + seg * ACT, i);
    } else {
        bid -= 24576;
        int seg = bid >> 10;
        size_t i = ((size_t)(bid & 1023)) * 256 + threadIdx.x;
        if (seg == 2) split_store(wv, g_bh + 2 * WSEG, g_bl + 2 * WSEG, i);
        else          hi_store(seg ? wk : wq, g_bh + seg * WSEG, i);
    }
}

extern __shared__ char smem_raw[];

// ================= gemm_qk: 1-pass bf16, BK=64, 2 CTAs/SM (R8 config) =================
#define QK_STG 32768
#define QK_SMEM (3 * QK_STG)

__global__ __launch_bounds__(256, 2)
void gemm_qk(const float* __restrict__ bias0, const float* __restrict__ bias1)
{
    const uint32_t sb = smem_u32(smem_raw);
    const int tid  = threadIdx.x;
    const int lane = tid & 31;
    const int wid  = tid >> 5;
    const int wm = (wid >> 2) * 64;
    const int wn = (wid & 3) * 32;

    const int seg = blockIdx.x >> 3;
    const int bn  = (blockIdx.x & 7) * 128;
    const int bm  = blockIdx.y * 128;
    const __nv_bfloat16* Ahg = g_ah + (size_t)seg * 8 * 1024 * 1024;
    const __nv_bfloat16* Bhg = g_bh + (size_t)seg * 1024 * 1024;
    const float* bias = seg ? bias1 : bias0;
    __nv_bfloat16* Yh = seg ? g_kph : g_qph;

    float C[4][4][4];
#pragma unroll
    for (int i = 0; i < 4; i++)
#pragma unroll
        for (int j = 0; j < 4; j++)
#pragma unroll
            for (int r = 0; r < 4; r++) C[i][j][r] = 0.0f;

    auto load_stage = [&](int s, int kc) {
        const uint32_t st = sb + s * QK_STG;
        const int koff = kc * 64;
#pragma unroll
        for (int i = 0; i < 4; i++) {
            int idx = tid + i * 256;
            int row = idx >> 3, c = idx & 7;
            uint32_t off = row * 128 + c * 16;
            uint32_t sw = off ^ ((off >> 3) & 0x70);
            CP_ASYNC16(st + sw,         Ahg + (size_t)(bm + row) * 1024 + koff + c * 8);
            CP_ASYNC16(st + 16384 + sw, Bhg + (size_t)(bn + row) * 1024 + koff + c * 8);
        }
        CP_COMMIT();
    };

    const int q  = lane >> 3;
    const int lr = lane & 7;
    const int am_row = wm + (q & 1) * 8 + lr;
    const int a_kq   = (q >> 1) * 16;
    const int bn_row = wn + (q >> 1) * 8 + lr;
    const int b_kq   = (q & 1) * 16;

    load_stage(0, 0);
    load_stage(1, 1);

    for (int kc = 0; kc < 16; kc++) {
        if (kc < 15) CP_WAIT(1); else CP_WAIT(0);
        __syncthreads();
        if (kc + 2 < 16) load_stage((kc + 2) % 3, kc + 2);

        const uint32_t st = sb + (kc % 3) * QK_STG;
#pragma unroll
        for (int ks = 0; ks < 4; ks++) {
            uint32_t aH[4][4], bH[2][4];
#pragma unroll
            for (int i = 0; i < 4; i++) {
                uint32_t off = (uint32_t)(am_row + i * 16) * 128 + a_kq + ks * 32;
                uint32_t sw = off ^ ((off >> 3) & 0x70);
                LDSM4(aH[i], st + sw);
            }
#pragma unroll
            for (int j2 = 0; j2 < 2; j2++) {
                uint32_t off = (uint32_t)(bn_row + j2 * 16) * 128 + b_kq + ks * 32;
                uint32_t sw = off ^ ((off >> 3) & 0x70);
                LDSM4(bH[j2], st + 16384 + sw);
            }
#pragma unroll
            for (int i = 0; i < 4; i++)
#pragma unroll
                for (int j = 0; j < 4; j++) {
                    const int jj = j >> 1, jo = (j & 1) * 2;
                    MMA16816(C[i][j], aH[i], bH[jj][jo], bH[jj][jo + 1]);
                }
        }
    }

    const int g  = lane >> 2;
    const int tg = lane & 3;
#pragma unroll
    for (int i = 0; i < 4; i++)
#pragma unroll
        for (int j = 0; j < 4; j++) {
            const int col = bn + wn + j * 8 + tg * 2;
            const int r0 = bm + wm + i * 16 + g;
            float b0v = bias[col], b1v = bias[col + 1];
            *(uint32_t*)(Yh + (size_t)r0 * 1024 + col) = pbf2(C[i][j][0] + b0v, C[i][j][1] + b1v);
            *(uint32_t*)(Yh + (size_t)(r0 + 8) * 1024 + col) = pbf2(C[i][j][2] + b0v, C[i][j][3] + b1v);
        }
}

// ================= gemm_v / gemm_beta (3-pass, BK=64, R8 config) =================
#define STG_B 65536
#define GSMEM_TOTAL (3 * STG_B)

template <int MODE>
__global__ __launch_bounds__(256)
void gemm_mma(const float* __restrict__ bias2, float* __restrict__ Yf)
{
    const uint32_t sb = smem_u32(smem_raw);
    const int tid  = threadIdx.x;
    const int lane = tid & 31;
    const int wid  = tid >> 5;
    const int wm = (wid >> 2) * 64;
    const int wn = (wid & 3) * 32;

    int bm, bn = 0, h = 0, b0 = 0;
    size_t arow0;
    const __nv_bfloat16 *Ahg, *Alg, *Bhg = nullptr, *Blg = nullptr;
    if (MODE == 0) {
        bn = blockIdx.x * 128; bm = blockIdx.y * 128;
        arow0 = (size_t)bm;
        Ahg = g_ah + (size_t)2 * 8 * 1024 * 1024;
        Alg = g_al + (size_t)2 * 8 * 1024 * 1024;
        Bhg = g_bh + (size_t)2 * 1024 * 1024;
        Blg = g_bl + (size_t)2 * 1024 * 1024;
    } else {
        b0 = blockIdx.x * 2; bm = blockIdx.y * 128; h = blockIdx.z;
        arow0 = (size_t)h * 1024 + bm;
        Ahg = g_ah; Alg = g_al;
    }

    float C[4][4][4];
#pragma unroll
    for (int i = 0; i < 4; i++)
#pragma unroll
        for (int j = 0; j < 4; j++)
#pragma unroll
            for (int r = 0; r < 4; r++) C[i][j][r] = 0.0f;

    auto load_stage = [&](int s, int kc) {
        const uint32_t st = sb + s * STG_B;
        const int koff = kc * 64;
#pragma unroll
        for (int i = 0; i < 4; i++) {
            int idx = tid + i * 256;
            int row = idx >> 3, c = idx & 7;
            uint32_t off = row * 128 + c * 16;
            uint32_t sw = off ^ ((off >> 3) & 0x70);
            size_t gA = (arow0 + row) * 1024 + koff + c * 8;
            CP_ASYNC16(st + sw,         Ahg + gA);
            CP_ASYNC16(st + 16384 + sw, Alg + gA);
        }
        if (MODE == 0) {
#pragma unroll
            for (int i = 0; i < 4; i++) {
                int idx = tid + i * 256;
                int row = idx >> 3, c = idx & 7;
                uint32_t off = row * 128 + c * 16;
                uint32_t sw = off ^ ((off >> 3) & 0x70);
                size_t gB = (size_t)(bn + row) * 1024 + koff + c * 8;
                CP_ASYNC16(st + 32768 + sw, Bhg + gB);
                CP_ASYNC16(st + 49152 + sw, Blg + gB);
            }
        } else {
#pragma unroll
            for (int i = 0; i < 4; i++) {
                int idx = tid + i * 256;
                int half = idx >> 9, row = (idx >> 3) & 63, c = idx & 7;
                uint32_t off = row * 128 + c * 16;
                uint32_t sw = off ^ ((off >> 3) & 0x70);
                size_t gV = ((size_t)(b0 + half) * 1024 + koff + row) * 1024 + h * 64 + c * 8;
                CP_ASYNC16(st + 32768 + half * 8192 + sw, g_vph + gV);
                CP_ASYNC16(st + 49152 + half * 8192 + sw, g_vpl + gV);
            }
        }
        CP_COMMIT();
    };

    const int q  = lane >> 3;
    const int lr = lane & 7;
    const int am_row = wm + (q & 1) * 8 + lr;
    const int a_kq   = (q >> 1) * 16;
    const int bn_row = wn + (q >> 1) * 8 + lr;
    const int b_kq   = (q & 1) * 16;

    load_stage(0, 0);
    load_stage(1, 1);

    for (int kc = 0; kc < 16; kc++) {
        if (kc < 15) CP_WAIT(1); else CP_WAIT(0);
        __syncthreads();
        if (kc + 2 < 16) load_stage((kc + 2) % 3, kc + 2);

        const uint32_t st = sb + (kc % 3) * STG_B;
#pragma unroll
        for (int ks = 0; ks < 4; ks++) {
            uint32_t aH[4][4], aL[4][4], bH[2][4], bL[2][4];
#pragma unroll
            for (int i = 0; i < 4; i++) {
                uint32_t off = (uint32_t)(am_row + i * 16) * 128 + a_kq + ks * 32;
                uint32_t sw = off ^ ((off >> 3) & 0x70);
                LDSM4(aH[i], st + sw);
                LDSM4(aL[i], st + 16384 + sw);
            }
#pragma unroll
            for (int j2 = 0; j2 < 2; j2++) {
                if (MODE == 0) {
                    uint32_t off = (uint32_t)(bn_row + j2 * 16) * 128 + b_kq + ks * 32;
                    uint32_t sw = off ^ ((off >> 3) & 0x70);
                    LDSM4(bH[j2], st + 32768 + sw);
                    LDSM4(bL[j2], st + 49152 + sw);
                } else {
                    const int n16 = wn + j2 * 16;
                    const int half = n16 >> 6, d0 = n16 & 63;
                    uint32_t off = (uint32_t)(ks * 16 + (q & 1) * 8 + lr) * 128 +
                                   (d0 + (q >> 1) * 8) * 2;
                    uint32_t sw = off ^ ((off >> 3) & 0x70);
                    LDSM4T(bH[j2], st + 32768 + half * 8192 + sw);
                    LDSM4T(bL[j2], st + 49152 + half * 8192 + sw);
                }
            }
#pragma unroll
            for (int i = 0; i < 4; i++)
#pragma unroll
                for (int j = 0; j < 4; j++) {
                    const int jj = j >> 1, jo = (j & 1) * 2;
                    MMA16816(C[i][j], aH[i], bH[jj][jo], bH[jj][jo + 1]);
                    MMA16816(C[i][j], aH[i], bL[jj][jo], bL[jj][jo + 1]);
                    MMA16816(C[i][j], aL[i], bH[jj][jo], bH[jj][jo + 1]);
                }
        }
    }

    const int g  = lane >> 2;
    const int tg = lane & 3;
#pragma unroll
    for (int i = 0; i < 4; i++) {
#pragma unroll
        for (int j = 0; j < 4; j++) {
            const int ncol = wn + j * 8 + tg * 2;
            const int r0 = bm + wm + i * 16 + g;
            const int r1 = r0 + 8;
            if (MODE == 0) {
                const int col = bn + ncol;
                float b0v = bias2[col], b1v = bias2[col + 1];
                float y00 = C[i][j][0] + b0v, y01 = C[i][j][1] + b1v;
                float y10 = C[i][j][2] + b0v, y11 = C[i][j][3] + b1v;
                float l00 = y00 - __bfloat162float(__float2bfloat16_rn(y00));
                float l01 = y01 - __bfloat162float(__float2bfloat16_rn(y01));
                float l10 = y10 - __bfloat162float(__float2bfloat16_rn(y10));
                float l11 = y11 - __bfloat162float(__float2bfloat16_rn(y11));
                *(uint32_t*)(g_vph + (size_t)r0 * 1024 + col) = pbf2(y00, y01);
                *(uint32_t*)(g_vph + (size_t)r1 * 1024 + col) = pbf2(y10, y11);
                *(uint32_t*)(g_vpl + (size_t)r0 * 1024 + col) = pbf2(l00, l01);
                *(uint32_t*)(g_vpl + (size_t)r1 * 1024 + col) = pbf2(l10, l11);
            } else {
                const int n = blockIdx.x * 128 + ncol;
                const int bb = n >> 6, dd = n & 63;
                float* p0 = Yf + ((size_t)bb * 1024 + r0) * 1024 + h * 64 + dd;
                float* p1 = Yf + ((size_t)bb * 1024 + r1) * 1024 + h * 64 + dd;
                float2 o0 = *(float2*)p0, o1 = *(float2*)p1;
                o0.x += C[i][j][0]; o0.y += C[i][j][1];
                o1.x += C[i][j][2]; o1.y += C[i][j][3];
                *(float2*)p0 = o0;
                *(float2*)p1 = o1;
            }
        }
    }
}

// ================= flash attention (S 1-pass, PV hi-only, 128-k stages) =================
// Safe single-sync double buffer: wait(0) -> sync -> load(next, other buf) -> compute.
#define FQH 0
#define FST0 16384
#define FKH 0
#define FVH 16384
#define FSRC 32768
#define FSTG 32896
#define FSMEM (16384 + 2 * FSTG)

__global__ __launch_bounds__(256, 2)
void flash_tc(float* __restrict__ out)
{
    char* sm = smem_raw;
    const uint32_t sb = smem_u32(sm);
    const int tid  = threadIdx.x;
    const int lane = tid & 31;
    const int w    = tid >> 5;
    const int q0 = blockIdx.x * 128;
    const int h  = blockIdx.y;
    const int b  = blockIdx.z;
    const int g  = lane >> 2;
    const int tg = lane & 3;
    const int qq = lane >> 3;
    const int lr = lane & 7;

    {
#pragma unroll
        for (int i = 0; i < 4; i++) {
            int idx = tid + i * 256;
            int row = idx >> 3, c = idx & 7;
            uint32_t off = row * 128 + c * 16;
            uint32_t sw = off ^ ((off >> 3) & 0x70);
            size_t gq = ((size_t)b * 1024 + q0 + row) * 1024 + h * 64 + c * 8;
            CP_ASYNC16(sb + FQH + sw, g_qph + gq);
        }
        CP_COMMIT();
    }

    // Load 128 k-rows of K hi and V hi per stage.
    auto load_stage = [&](int s, int kt) {
        const uint32_t st = sb + FST0 + s * FSTG;
        const int k0 = kt * 128;
#pragma unroll
        for (int i = 0; i < 4; i++) {
            int idx = tid + i * 256;
            int row = idx >> 3, c = idx & 7;
            uint32_t off = row * 128 + c * 16;
            uint32_t sw = off ^ ((off >> 3) & 0x70);
            size_t gk = ((size_t)b * 1024 + k0 + row) * 1024 + h * 64 + c * 8;
            CP_ASYNC16(st + FKH + sw, g_kph + gk);
            CP_ASYNC16(st + FVH + sw, g_vph + gk);
        }
        if (tid < 8)
            CP_ASYNC16(st + FSRC + tid * 16, g_src8 + b * 1024 + k0 + tid * 16);
        CP_COMMIT();
    };

    load_stage(0, 0);

    const unsigned char t0m = g_tgt8[b * 1024 + q0 + w * 16 + g];
    const unsigned char t1m = g_tgt8[b * 1024 + q0 + w * 16 + 8 + g];

    float m0r = -3.0e38f, m1r = -3.0e38f, l0r = 0.0f, l1r = 0.0f;
    float O[8][4];
#pragma unroll
    for (int i = 0; i < 8; i++)
#pragma unroll
        for (int r = 0; r < 4; r++) O[i][r] = 0.0f;

    uint32_t aQh[4][4];

    for (int kt = 0; kt < 8; kt++) {
        // Wait for ALL outstanding loads (stage kt is complete), barrier, then
        // prefetch stage kt+1 into the buffer whose compute finished at kt-1.
        CP_WAIT(0);
        __syncthreads();
        if (kt + 1 < 8) load_stage((kt + 1) & 1, kt + 1);

        if (kt == 0) {
#pragma unroll
            for (int kc = 0; kc < 4; kc++) {
                uint32_t off = (uint32_t)(w * 16 + (qq & 1) * 8 + lr) * 128 + (qq >> 1) * 16 + kc * 32;
                uint32_t sw = off ^ ((off >> 3) & 0x70);
                LDSM4(aQh[kc], sb + FQH + sw);
            }
        }

        const uint32_t st = sb + FST0 + (kt & 1) * FSTG;
        char* stp = sm + FST0 + (kt & 1) * FSTG;

        // Two 64-k sub-tiles within the stage
#pragma unroll
        for (int sub = 0; sub < 2; sub++) {
            const uint32_t kofs = sub * 64 * 128;

            // ---- S = Qh @ Kh^T ----
            float C[8][4];
#pragma unroll
            for (int i = 0; i < 8; i++)
#pragma unroll
                for (int r = 0; r < 4; r++) C[i][r] = 0.0f;
#pragma unroll
            for (int ks = 0; ks < 4; ks++) {
#pragma unroll
                for (int j2 = 0; j2 < 4; j2++) {
                    uint32_t bh[4];
                    uint32_t off = kofs + (uint32_t)(j2 * 16 + (qq >> 1) * 8 + lr) * 128 +
                                   (qq & 1) * 16 + ks * 32;
                    uint32_t sw = off ^ ((off >> 3) & 0x70);
                    LDSM4(bh, st + FKH + sw);
                    MMA16816(C[j2 * 2],     aQh[ks], bh[0], bh[1]);
                    MMA16816(C[j2 * 2 + 1], aQh[ks], bh[2], bh[3]);
                }
            }

            // ---- mask + online softmax (log2 domain) ----
            float mx0 = -3.0e38f, mx1 = -3.0e38f;
#pragma unroll
            for (int nt = 0; nt < 8; nt++) {
                unsigned char s0 = *(unsigned char*)(stp + FSRC + sub * 64 + nt * 8 + tg * 2);
                unsigned char s1 = *(unsigned char*)(stp + FSRC + sub * 64 + nt * 8 + tg * 2 + 1);
                C[nt][0] = (t0m && s0) ? C[nt][0] * SC2L : NEGV;
                C[nt][1] = (t0m && s1) ? C[nt][1] * SC2L : NEGV;
                C[nt][2] = (t1m && s0) ? C[nt][2] * SC2L : NEGV;
                C[nt][3] = (t1m && s1) ? C[nt][3] * SC2L : NEGV;
                mx0 = fmaxf(mx0, fmaxf(C[nt][0], C[nt][1]));
                mx1 = fmaxf(mx1, fmaxf(C[nt][2], C[nt][3]));
            }
            mx0 = fmaxf(mx0, __shfl_xor_sync(0xFFFFFFFF, mx0, 1));
            mx0 = fmaxf(mx0, __shfl_xor_sync(0xFFFFFFFF, mx0, 2));
            mx1 = fmaxf(mx1, __shfl_xor_sync(0xFFFFFFFF, mx1, 1));
            mx1 = fmaxf(mx1, __shfl_xor_sync(0xFFFFFFFF, mx1, 2));

            float mn0 = fmaxf(m0r, mx0), mn1 = fmaxf(m1r, mx1);
            float f0 = ex2f(m0r - mn0), f1 = ex2f(m1r - mn1);
            m0r = mn0; m1r = mn1;

            float s0 = 0.0f, s1 = 0.0f;
#pragma unroll
            for (int nt = 0; nt < 8; nt++) {
                C[nt][0] = ex2f(C[nt][0] - mn0);
                C[nt][1] = ex2f(C[nt][1] - mn0);
                C[nt][2] = ex2f(C[nt][2] - mn1);
                C[nt][3] = ex2f(C[nt][3] - mn1);
                s0 += C[nt][0] + C[nt][1];
                s1 += C[nt][2] + C[nt][3];
            }
            s0 += __shfl_xor_sync(0xFFFFFFFF, s0, 1);
            s0 += __shfl_xor_sync(0xFFFFFFFF, s0, 2);
            s1 += __shfl_xor_sync(0xFFFFFFFF, s1, 1);
            s1 += __shfl_xor_sync(0xFFFFFFFF, s1, 2);
            l0r = l0r * f0 + s0;
            l1r = l1r * f1 + s1;

#pragma unroll
            for (int nt = 0; nt < 8; nt++) {
                O[nt][0] *= f0; O[nt][1] *= f0;
                O[nt][2] *= f1; O[nt][3] *= f1;
            }

            // ---- pack P (hi only) ----
            uint32_t aPh[4][4];
#pragma unroll
            for (int kc = 0; kc < 4; kc++) {
                const int n0 = kc * 2, n1 = kc * 2 + 1;
                aPh[kc][0] = pbf2(C[n0][0], C[n0][1]);
                aPh[kc][1] = pbf2(C[n0][2], C[n0][3]);
                aPh[kc][2] = pbf2(C[n1][0], C[n1][1]);
                aPh[kc][3] = pbf2(C[n1][2], C[n1][3]);
            }

            // ---- O += Ph @ Vh ----
#pragma unroll
            for (int kc = 0; kc < 4; kc++) {
#pragma unroll
                for (int nd = 0; nd < 4; nd++) {
                    uint32_t vh[4];
                    uint32_t off = kofs + (uint32_t)(kc * 16 + (qq & 1) * 8 + lr) * 128 +
                                   (nd * 16 + (qq >> 1) * 8) * 2;
                    uint32_t sw = off ^ ((off >> 3) & 0x70);
                    LDSM4T(vh, st + FVH + sw);
                    MMA16816(O[nd * 2],     aPh[kc], vh[0], vh[1]);
                    MMA16816(O[nd * 2 + 1], aPh[kc], vh[2], vh[3]);
                }
            }
        }
    }

    const float il0 = 1.0f / l0r, il1 = 1.0f / l1r;
    const int r0 = q0 + w * 16 + g;
    const int r1 = r0 + 8;
#pragma unroll
    for (int nt = 0; nt < 8; nt++) {
        const int col = h * 64 + nt * 8 + tg * 2;
        float2 w0 = make_float2(O[nt][0] * il0, O[nt][1] * il0);
        float2 w1 = make_float2(O[nt][2] * il1, O[nt][3] * il1);
        *(float2*)(out + ((size_t)b * 1024 + r0) * 1024 + col) = w0;
        *(float2*)(out + ((size_t)b * 1024 + r1) * 1024 + col) = w1;
    }
}

// ================= kernel_launch =================
extern "C" void kernel_launch(void* const* d_in, const int* in_sizes, int n_in,
                              void* d_out, int out_size)
{
    const float* q    = (const float*)d_in[0];
    const float* k    = (const float*)d_in[1];
    const float* v    = (const float*)d_in[2];
    const float* beta = (const float*)d_in[3];
    const unsigned char* srcm = (const unsigned char*)d_in[4];
    const unsigned char* tgtm = (const unsigned char*)d_in[5];
    const float* Wq = (const float*)d_in[6];
    const float* bq = (const float*)d_in[7];
    const float* Wk = (const float*)d_in[8];
    const float* bk = (const float*)d_in[9];
    const float* Wv = (const float*)d_in[10];
    const float* bv = (const float*)d_in[11];
    float* out = (float*)d_out;

    void *ah, *al;
    cudaGetSymbolAddress(&ah, g_ah);
    cudaGetSymbolAddress(&al, g_al);
    __nv_bfloat16* AH = (__nv_bfloat16*)ah;
    __nv_bfloat16* AL = (__nv_bfloat16*)al;

    cudaFuncSetAttribute(gemm_qk,     cudaFuncAttributeMaxDynamicSharedMemorySize, QK_SMEM);
    cudaFuncSetAttribute(gemm_mma<0>, cudaFuncAttributeMaxDynamicSharedMemorySize, GSMEM_TOTAL);
    cudaFuncSetAttribute(gemm_mma<1>, cudaFuncAttributeMaxDynamicSharedMemorySize, GSMEM_TOTAL);
    cudaFuncSetAttribute(flash_tc,    cudaFuncAttributeMaxDynamicSharedMemorySize, FSMEM);

    mask_convert2<<<2, 1024>>>(srcm, tgtm, Bb * TK);

    conv_all<<<27648, 256>>>((const float4*)q, (const float4*)k, (const float4*)v,
                             (const float4*)Wq, (const float4*)Wk, (const float4*)Wv);

    // Q,K projections (1-pass bf16, 2 CTAs/SM)
    gemm_qk<<<dim3(16, 64), 256, QK_SMEM>>>(bq, bk);
    // V projection (3-pass split)
    gemm_mma<0><<<dim3(8, 64), 256, GSMEM_TOTAL>>>(bv, nullptr);

    // flash attention (writes out)
    flash_tc<<<dim3(TQ / 128, NH, Bb), 256, FSMEM>>>(out);

    // beta @ V accumulated into out
    const int n4_beta = (NH * TQ * TK) / 4;
    conv_split<<<(n4_beta + 255) / 256, 256>>>((const float4*)beta, AH, AL, n4_beta);
    gemm_mma<1><<<dim3(4, 8, 16), 256, GSMEM_TOTAL>>>(nullptr, out);
}

// round 12
// speedup vs baseline: 1.2602x; 1.0118x over previous
#include <cuda_runtime.h>
#include <cuda_bf16.h>
#include <math.h>
#include <stdint.h>

// Problem constants
#define Bb    8
#define TQ    1024
#define TK    1024
#define DIMX  1024
#define NH    16
#define HD    64
#define SCALE 0.03125f
#define NEGV  -1.0e9f
#define MROWS (Bb * TQ)
#define SC2L  (0.03125f * 1.44269504088896f)

// ================= PTX helpers =================
__device__ __forceinline__ uint32_t smem_u32(const void* p) {
    uint32_t a;
    asm("{ .reg .u64 t; cvta.to.shared.u64 t, %1; cvt.u32.u64 %0, t; }"
        : "=r"(a) : "l"(p));
    return a;
}
#define CP_ASYNC16(dst_u32, src_ptr) \
    asm volatile("cp.async.cg.shared.global [%0], [%1], 16;" \
        :: "r"(dst_u32), "l"(src_ptr))
#define CP_COMMIT() asm volatile("cp.async.commit_group;" ::: "memory")
#define CP_WAIT(n)  asm volatile("cp.async.wait_group %0;" :: "n"(n) : "memory")

#define LDSM4(r, addr) \
    asm volatile("ldmatrix.sync.aligned.m8n8.x4.shared.b16 {%0,%1,%2,%3}, [%4];" \
        : "=r"((r)[0]), "=r"((r)[1]), "=r"((r)[2]), "=r"((r)[3]) : "r"(addr))
#define LDSM4T(r, addr) \
    asm volatile("ldmatrix.sync.aligned.m8n8.x4.trans.shared.b16 {%0,%1,%2,%3}, [%4];" \
        : "=r"((r)[0]), "=r"((r)[1]), "=r"((r)[2]), "=r"((r)[3]) : "r"(addr))

#define MMA16816(c, a, b0, b1) \
    asm volatile("mma.sync.aligned.m16n8k16.row.col.f32.bf16.bf16.f32 " \
        "{%0,%1,%2,%3}, {%4,%5,%6,%7}, {%8,%9}, {%0,%1,%2,%3};" \
        : "+f"((c)[0]), "+f"((c)[1]), "+f"((c)[2]), "+f"((c)[3]) \
        : "r"((a)[0]), "r"((a)[1]), "r"((a)[2]), "r"((a)[3]), "r"(b0), "r"(b1))

__device__ __forceinline__ uint32_t pbf2(float lo, float hi) {
    uint32_t d;
    asm("cvt.rn.bf16x2.f32 %0, %1, %2;" : "=r"(d) : "f"(hi), "f"(lo));
    return d;
}
__device__ __forceinline__ float ex2f(float x) {
    float y;
    asm("ex2.approx.ftz.f32 %0, %1;" : "=f"(y) : "f"(x));
    return y;
}

// ================= scratch =================
__device__ __align__(16) __nv_bfloat16 g_qph[(size_t)MROWS * DIMX];
__device__ __align__(16) __nv_bfloat16 g_kph[(size_t)MROWS * DIMX];
__device__ __align__(16) __nv_bfloat16 g_vph[(size_t)MROWS * DIMX];
__device__ __align__(16) __nv_bfloat16 g_vpl[(size_t)MROWS * DIMX];
__device__ __align__(16) __nv_bfloat16 g_ah[(size_t)24 * 1024 * 1024];   // acts q|k|v
__device__ __align__(16) __nv_bfloat16 g_al[(size_t)24 * 1024 * 1024];
__device__ __align__(16) __nv_bfloat16 g_bth[(size_t)16 * 1024 * 1024];  // beta hi
__device__ __align__(16) __nv_bfloat16 g_btl[(size_t)16 * 1024 * 1024];  // beta lo
__device__ __align__(16) __nv_bfloat16 g_bh[(size_t)3 * 1024 * 1024];
__device__ __align__(16) __nv_bfloat16 g_bl[(size_t)3 * 1024 * 1024];
__device__ unsigned char g_src8[Bb * TK];
__device__ unsigned char g_tgt8[Bb * TQ];

// ================= mask canonicalization (both masks, 1 launch) =================
__global__ void mask_convert2(const unsigned char* __restrict__ raw0,
                              const unsigned char* __restrict__ raw1, int n)
{
    const unsigned char* raw = blockIdx.x ? raw1 : raw0;
    unsigned char* out = blockIdx.x ? g_tgt8 : g_src8;
    __shared__ int has3F, oddNZ;
    if (threadIdx.x == 0) { has3F = 0; oddNZ = 0; }
    __syncthreads();
    int lf = 0, lo = 0;
    for (int i = threadIdx.x; i < n; i += blockDim.x) {
        unsigned char c = raw[i];
        if (c == 0x3F) lf = 1;
        if ((i & 3) && c) lo = 1;
    }
    if (lf) atomicOr(&has3F, 1);
    if (lo) atomicOr(&oddNZ, 1);
    __syncthreads();
    int mode = has3F ? 2 : (oddNZ ? 0 : 1);
    for (int i = threadIdx.x; i < n; i += blockDim.x) {
        unsigned char v;
        if (mode == 2)      v = (((const float*)raw)[i] != 0.0f) ? 1 : 0;
        else if (mode == 1) v = (((const int*)raw)[i]   != 0)    ? 1 : 0;
        else                v = (raw[i] != 0) ? 1 : 0;
        out[i] = v;
    }
}

// ================= fp32 -> bf16 conversions (MLP=4 per thread) =================
__device__ __forceinline__ void split_store(const float4* __restrict__ x,
                                            __nv_bfloat16* __restrict__ hi,
                                            __nv_bfloat16* __restrict__ lo, size_t i)
{
    float4 f = x[i];
    __nv_bfloat16 h0 = __float2bfloat16_rn(f.x);
    __nv_bfloat16 h1 = __float2bfloat16_rn(f.y);
    __nv_bfloat16 h2 = __float2bfloat16_rn(f.z);
    __nv_bfloat16 h3 = __float2bfloat16_rn(f.w);
    __nv_bfloat16 l0 = __float2bfloat16_rn(f.x - __bfloat162float(h0));
    __nv_bfloat16 l1 = __float2bfloat16_rn(f.y - __bfloat162float(h1));
    __nv_bfloat16 l2 = __float2bfloat16_rn(f.z - __bfloat162float(h2));
    __nv_bfloat16 l3 = __float2bfloat16_rn(f.w - __bfloat162float(h3));
    __nv_bfloat162* Hp = (__nv_bfloat162*)(hi + 4 * i);
    __nv_bfloat162* Lp = (__nv_bfloat162*)(lo + 4 * i);
    Hp[0] = __halves2bfloat162(h0, h1);
    Hp[1] = __halves2bfloat162(h2, h3);
    Lp[0] = __halves2bfloat162(l0, l1);
    Lp[1] = __halves2bfloat162(l2, l3);
}

// Unified conversion: q,k (hi), v (hi+lo), Wq,Wk (hi), Wv (hi+lo), beta (hi+lo).
// Each block handles 1024 float4; each thread 4 float4 (front-batched loads, MLP=4).
__global__ __launch_bounds__(256)
void conv_allx(const float4* __restrict__ q, const float4* __restrict__ k,
               const float4* __restrict__ v, const float4* __restrict__ wq,
               const float4* __restrict__ wk, const float4* __restrict__ wv,
               const float4* __restrict__ beta)
{
    const size_t ACT = (size_t)8 * 1024 * 1024;
    const size_t WSEG = (size_t)1024 * 1024;
    int bid = blockIdx.x;
    const float4* src;
    __nv_bfloat16 *hi, *lo = nullptr;
    bool full;
    size_t base;
    if (bid < 6144) {                       // activations: 2048 blocks each
        int seg = bid / 2048;
        src = (seg == 0) ? q : (seg == 1) ? k : v;
        full = (seg == 2);
        hi = g_ah + seg * ACT; lo = g_al + seg * ACT;
        base = (size_t)(bid % 2048) * 1024;
    } else if (bid < 6912) {                // weights: 256 blocks each
        int seg = (bid - 6144) / 256;
        src = (seg == 0) ? wq : (seg == 1) ? wk : wv;
        full = (seg == 2);
        hi = g_bh + seg * WSEG; lo = g_bl + seg * WSEG;
        base = (size_t)((bid - 6144) % 256) * 1024;
    } else {                                // beta: 4096 blocks
        src = beta; full = true;
        hi = g_bth; lo = g_btl;
        base = (size_t)(bid - 6912) * 1024;
    }
    const int tid = threadIdx.x;

    // front-batch 4 independent loads
    float4 f[4];
#pragma unroll
    for (int u = 0; u < 4; u++) f[u] = src[base + tid + u * 256];

    if (full) {
#pragma unroll
        for (int u = 0; u < 4; u++) {
            size_t i = base + tid + u * 256;
            __nv_bfloat16 h0 = __float2bfloat16_rn(f[u].x);
            __nv_bfloat16 h1 = __float2bfloat16_rn(f[u].y);
            __nv_bfloat16 h2 = __float2bfloat16_rn(f[u].z);
            __nv_bfloat16 h3 = __float2bfloat16_rn(f[u].w);
            __nv_bfloat16 l0 = __float2bfloat16_rn(f[u].x - __bfloat162float(h0));
            __nv_bfloat16 l1 = __float2bfloat16_rn(f[u].y - __bfloat162float(h1));
            __nv_bfloat16 l2 = __float2bfloat16_rn(f[u].z - __bfloat162float(h2));
            __nv_bfloat16 l3 = __float2bfloat16_rn(f[u].w - __bfloat162float(h3));
            __nv_bfloat162* Hp = (__nv_bfloat162*)(hi + 4 * i);
            __nv_bfloat162* Lp = (__nv_bfloat162*)(lo + 4 * i);
            Hp[0] = __halves2bfloat162(h0, h1);
            Hp[1] = __halves2bfloat162(h2, h3);
            Lp[0] = __halves2bfloat162(l0, l1);
            Lp[1] = __halves2bfloat162(l2, l3);
        }
    } else {
#pragma unroll
        for (int u = 0; u < 4; u++) {
            size_t i = base + tid + u * 256;
            __nv_bfloat162* Hp = (__nv_bfloat162*)(hi + 4 * i);
            Hp[0] = __halves2bfloat162(__float2bfloat16_rn(f[u].x), __float2bfloat16_rn(f[u].y));
            Hp[1] = __halves2bfloat162(__float2bfloat16_rn(f[u].z), __float2bfloat16_rn(f[u].w));
        }
    }
}

extern __shared__ char smem_raw[];

// ================= gemm_qk: 1-pass bf16, BK=64, 2 CTAs/SM =================
#define QK_STG 32768
#define QK_SMEM (3 * QK_STG)

__global__ __launch_bounds__(256, 2)
void gemm_qk(const float* __restrict__ bias0, const float* __restrict__ bias1)
{
    const uint32_t sb = smem_u32(smem_raw);
    const int tid  = threadIdx.x;
    const int lane = tid & 31;
    const int wid  = tid >> 5;
    const int wm = (wid >> 2) * 64;
    const int wn = (wid & 3) * 32;

    const int seg = blockIdx.x >> 3;
    const int bn  = (blockIdx.x & 7) * 128;
    const int bm  = blockIdx.y * 128;
    const __nv_bfloat16* Ahg = g_ah + (size_t)seg * 8 * 1024 * 1024;
    const __nv_bfloat16* Bhg = g_bh + (size_t)seg * 1024 * 1024;
    const float* bias = seg ? bias1 : bias0;
    __nv_bfloat16* Yh = seg ? g_kph : g_qph;

    float C[4][4][4];
#pragma unroll
    for (int i = 0; i < 4; i++)
#pragma unroll
        for (int j = 0; j < 4; j++)
#pragma unroll
            for (int r = 0; r < 4; r++) C[i][j][r] = 0.0f;

    auto load_stage = [&](int s, int kc) {
        const uint32_t st = sb + s * QK_STG;
        const int koff = kc * 64;
#pragma unroll
        for (int i = 0; i < 4; i++) {
            int idx = tid + i * 256;
            int row = idx >> 3, c = idx & 7;
            uint32_t off = row * 128 + c * 16;
            uint32_t sw = off ^ ((off >> 3) & 0x70);
            CP_ASYNC16(st + sw,         Ahg + (size_t)(bm + row) * 1024 + koff + c * 8);
            CP_ASYNC16(st + 16384 + sw, Bhg + (size_t)(bn + row) * 1024 + koff + c * 8);
        }
        CP_COMMIT();
    };

    const int q  = lane >> 3;
    const int lr = lane & 7;
    const int am_row = wm + (q & 1) * 8 + lr;
    const int a_kq   = (q >> 1) * 16;
    const int bn_row = wn + (q >> 1) * 8 + lr;
    const int b_kq   = (q & 1) * 16;

    load_stage(0, 0);
    load_stage(1, 1);

    for (int kc = 0; kc < 16; kc++) {
        if (kc < 15) CP_WAIT(1); else CP_WAIT(0);
        __syncthreads();
        if (kc + 2 < 16) load_stage((kc + 2) % 3, kc + 2);

        const uint32_t st = sb + (kc % 3) * QK_STG;
#pragma unroll
        for (int ks = 0; ks < 4; ks++) {
            uint32_t aH[4][4], bH[2][4];
#pragma unroll
            for (int i = 0; i < 4; i++) {
                uint32_t off = (uint32_t)(am_row + i * 16) * 128 + a_kq + ks * 32;
                uint32_t sw = off ^ ((off >> 3) & 0x70);
                LDSM4(aH[i], st + sw);
            }
#pragma unroll
            for (int j2 = 0; j2 < 2; j2++) {
                uint32_t off = (uint32_t)(bn_row + j2 * 16) * 128 + b_kq + ks * 32;
                uint32_t sw = off ^ ((off >> 3) & 0x70);
                LDSM4(bH[j2], st + 16384 + sw);
            }
#pragma unroll
            for (int i = 0; i < 4; i++)
#pragma unroll
                for (int j = 0; j < 4; j++) {
                    const int jj = j >> 1, jo = (j & 1) * 2;
                    MMA16816(C[i][j], aH[i], bH[jj][jo], bH[jj][jo + 1]);
                }
        }
    }

    const int g  = lane >> 2;
    const int tg = lane & 3;
#pragma unroll
    for (int i = 0; i < 4; i++)
#pragma unroll
        for (int j = 0; j < 4; j++) {
            const int col = bn + wn + j * 8 + tg * 2;
            const int r0 = bm + wm + i * 16 + g;
            float b0v = bias[col], b1v = bias[col + 1];
            *(uint32_t*)(Yh + (size_t)r0 * 1024 + col) = pbf2(C[i][j][0] + b0v, C[i][j][1] + b1v);
            *(uint32_t*)(Yh + (size_t)(r0 + 8) * 1024 + col) = pbf2(C[i][j][2] + b0v, C[i][j][3] + b1v);
        }
}

// ================= gemm_v / gemm_beta (3-pass, BK=64) =================
#define STG_B 65536
#define GSMEM_TOTAL (3 * STG_B)

template <int MODE>
__global__ __launch_bounds__(256)
void gemm_mma(const float* __restrict__ bias2, float* __restrict__ Yf)
{
    const uint32_t sb = smem_u32(smem_raw);
    const int tid  = threadIdx.x;
    const int lane = tid & 31;
    const int wid  = tid >> 5;
    const int wm = (wid >> 2) * 64;
    const int wn = (wid & 3) * 32;

    int bm, bn = 0, h = 0, b0 = 0;
    size_t arow0;
    const __nv_bfloat16 *Ahg, *Alg, *Bhg = nullptr, *Blg = nullptr;
    if (MODE == 0) {
        bn = blockIdx.x * 128; bm = blockIdx.y * 128;
        arow0 = (size_t)bm;
        Ahg = g_ah + (size_t)2 * 8 * 1024 * 1024;
        Alg = g_al + (size_t)2 * 8 * 1024 * 1024;
        Bhg = g_bh + (size_t)2 * 1024 * 1024;
        Blg = g_bl + (size_t)2 * 1024 * 1024;
    } else {
        b0 = blockIdx.x * 2; bm = blockIdx.y * 128; h = blockIdx.z;
        arow0 = (size_t)h * 1024 + bm;
        Ahg = g_bth; Alg = g_btl;
    }

    float C[4][4][4];
#pragma unroll
    for (int i = 0; i < 4; i++)
#pragma unroll
        for (int j = 0; j < 4; j++)
#pragma unroll
            for (int r = 0; r < 4; r++) C[i][j][r] = 0.0f;

    auto load_stage = [&](int s, int kc) {
        const uint32_t st = sb + s * STG_B;
        const int koff = kc * 64;
#pragma unroll
        for (int i = 0; i < 4; i++) {
            int idx = tid + i * 256;
            int row = idx >> 3, c = idx & 7;
            uint32_t off = row * 128 + c * 16;
            uint32_t sw = off ^ ((off >> 3) & 0x70);
            size_t gA = (arow0 + row) * 1024 + koff + c * 8;
            CP_ASYNC16(st + sw,         Ahg + gA);
            CP_ASYNC16(st + 16384 + sw, Alg + gA);
        }
        if (MODE == 0) {
#pragma unroll
            for (int i = 0; i < 4; i++) {
                int idx = tid + i * 256;
                int row = idx >> 3, c = idx & 7;
                uint32_t off = row * 128 + c * 16;
                uint32_t sw = off ^ ((off >> 3) & 0x70);
                size_t gB = (size_t)(bn + row) * 1024 + koff + c * 8;
                CP_ASYNC16(st + 32768 + sw, Bhg + gB);
                CP_ASYNC16(st + 49152 + sw, Blg + gB);
            }
        } else {
#pragma unroll
            for (int i = 0; i < 4; i++) {
                int idx = tid + i * 256;
                int half = idx >> 9, row = (idx >> 3) & 63, c = idx & 7;
                uint32_t off = row * 128 + c * 16;
                uint32_t sw = off ^ ((off >> 3) & 0x70);
                size_t gV = ((size_t)(b0 + half) * 1024 + koff + row) * 1024 + h * 64 + c * 8;
                CP_ASYNC16(st + 32768 + half * 8192 + sw, g_vph + gV);
                CP_ASYNC16(st + 49152 + half * 8192 + sw, g_vpl + gV);
            }
        }
        CP_COMMIT();
    };

    const int q  = lane >> 3;
    const int lr = lane & 7;
    const int am_row = wm + (q & 1) * 8 + lr;
    const int a_kq   = (q >> 1) * 16;
    const int bn_row = wn + (q >> 1) * 8 + lr;
    const int b_kq   = (q & 1) * 16;

    load_stage(0, 0);
    load_stage(1, 1);

    for (int kc = 0; kc < 16; kc++) {
        if (kc < 15) CP_WAIT(1); else CP_WAIT(0);
        __syncthreads();
        if (kc + 2 < 16) load_stage((kc + 2) % 3, kc + 2);

        const uint32_t st = sb + (kc % 3) * STG_B;
#pragma unroll
        for (int ks = 0; ks < 4; ks++) {
            uint32_t aH[4][4], aL[4][4], bH[2][4], bL[2][4];
#pragma unroll
            for (int i = 0; i < 4; i++) {
                uint32_t off = (uint32_t)(am_row + i * 16) * 128 + a_kq + ks * 32;
                uint32_t sw = off ^ ((off >> 3) & 0x70);
                LDSM4(aH[i], st + sw);
                LDSM4(aL[i], st + 16384 + sw);
            }
#pragma unroll
            for (int j2 = 0; j2 < 2; j2++) {
                if (MODE == 0) {
                    uint32_t off = (uint32_t)(bn_row + j2 * 16) * 128 + b_kq + ks * 32;
                    uint32_t sw = off ^ ((off >> 3) & 0x70);
                    LDSM4(bH[j2], st + 32768 + sw);
                    LDSM4(bL[j2], st + 49152 + sw);
                } else {
                    const int n16 = wn + j2 * 16;
                    const int half = n16 >> 6, d0 = n16 & 63;
                    uint32_t off = (uint32_t)(ks * 16 + (q & 1) * 8 + lr) * 128 +
                                   (d0 + (q >> 1) * 8) * 2;
                    uint32_t sw = off ^ ((off >> 3) & 0x70);
                    LDSM4T(bH[j2], st + 32768 + half * 8192 + sw);
                    LDSM4T(bL[j2], st + 49152 + half * 8192 + sw);
                }
            }
#pragma unroll
            for (int i = 0; i < 4; i++)
#pragma unroll
                for (int j = 0; j < 4; j++) {
                    const int jj = j >> 1, jo = (j & 1) * 2;
                    MMA16816(C[i][j], aH[i], bH[jj][jo], bH[jj][jo + 1]);
                    MMA16816(C[i][j], aH[i], bL[jj][jo], bL[jj][jo + 1]);
                    MMA16816(C[i][j], aL[i], bH[jj][jo], bH[jj][jo + 1]);
                }
        }
    }

    const int g  = lane >> 2;
    const int tg = lane & 3;
#pragma unroll
    for (int i = 0; i < 4; i++) {
#pragma unroll
        for (int j = 0; j < 4; j++) {
            const int ncol = wn + j * 8 + tg * 2;
            const int r0 = bm + wm + i * 16 + g;
            const int r1 = r0 + 8;
            if (MODE == 0) {
                const int col = bn + ncol;
                float b0v = bias2[col], b1v = bias2[col + 1];
                float y00 = C[i][j][0] + b0v, y01 = C[i][j][1] + b1v;
                float y10 = C[i][j][2] + b0v, y11 = C[i][j][3] + b1v;
                float l00 = y00 - __bfloat162float(__float2bfloat16_rn(y00));
                float l01 = y01 - __bfloat162float(__float2bfloat16_rn(y01));
                float l10 = y10 - __bfloat162float(__float2bfloat16_rn(y10));
                float l11 = y11 - __bfloat162float(__float2bfloat16_rn(y11));
                *(uint32_t*)(g_vph + (size_t)r0 * 1024 + col) = pbf2(y00, y01);
                *(uint32_t*)(g_vph + (size_t)r1 * 1024 + col) = pbf2(y10, y11);
                *(uint32_t*)(g_vpl + (size_t)r0 * 1024 + col) = pbf2(l00, l01);
                *(uint32_t*)(g_vpl + (size_t)r1 * 1024 + col) = pbf2(l10, l11);
            } else {
                const int n = blockIdx.x * 128 + ncol;
                const int bb = n >> 6, dd = n & 63;
                float* p0 = Yf + ((size_t)bb * 1024 + r0) * 1024 + h * 64 + dd;
                float* p1 = Yf + ((size_t)bb * 1024 + r1) * 1024 + h * 64 + dd;
                float2 o0 = *(float2*)p0, o1 = *(float2*)p1;
                o0.x += C[i][j][0]; o0.y += C[i][j][1];
                o1.x += C[i][j][2]; o1.y += C[i][j][3];
                *(float2*)p0 = o0;
                *(float2*)p1 = o1;
            }
        }
    }
}

// ================= flash attention (S 1-pass, PV hi-only, 128-k stages) =================
#define FQH 0
#define FST0 16384
#define FKH 0
#define FVH 16384
#define FSRC 32768
#define FSTG 32896
#define FSMEM (16384 + 2 * FSTG)

__global__ __launch_bounds__(256, 2)
void flash_tc(float* __restrict__ out)
{
    char* sm = smem_raw;
    const uint32_t sb = smem_u32(sm);
    const int tid  = threadIdx.x;
    const int lane = tid & 31;
    const int w    = tid >> 5;
    const int q0 = blockIdx.x * 128;
    const int h  = blockIdx.y;
    const int b  = blockIdx.z;
    const int g  = lane >> 2;
    const int tg = lane & 3;
    const int qq = lane >> 3;
    const int lr = lane & 7;

    {
#pragma unroll
        for (int i = 0; i < 4; i++) {
            int idx = tid + i * 256;
            int row = idx >> 3, c = idx & 7;
            uint32_t off = row * 128 + c * 16;
            uint32_t sw = off ^ ((off >> 3) & 0x70);
            size_t gq = ((size_t)b * 1024 + q0 + row) * 1024 + h * 64 + c * 8;
            CP_ASYNC16(sb + FQH + sw, g_qph + gq);
        }
        CP_COMMIT();
    }

    auto load_stage = [&](int s, int kt) {
        const uint32_t st = sb + FST0 + s * FSTG;
        const int k0 = kt * 128;
#pragma unroll
        for (int i = 0; i < 4; i++) {
            int idx = tid + i * 256;
            int row = idx >> 3, c = idx & 7;
            uint32_t off = row * 128 + c * 16;
            uint32_t sw = off ^ ((off >> 3) & 0x70);
            size_t gk = ((size_t)b * 1024 + k0 + row) * 1024 + h * 64 + c * 8;
            CP_ASYNC16(st + FKH + sw, g_kph + gk);
            CP_ASYNC16(st + FVH + sw, g_vph + gk);
        }
        if (tid < 8)
            CP_ASYNC16(st + FSRC + tid * 16, g_src8 + b * 1024 + k0 + tid * 16);
        CP_COMMIT();
    };

    load_stage(0, 0);

    const unsigned char t0m = g_tgt8[b * 1024 + q0 + w * 16 + g];
    const unsigned char t1m = g_tgt8[b * 1024 + q0 + w * 16 + 8 + g];

    float m0r = -3.0e38f, m1r = -3.0e38f, l0r = 0.0f, l1r = 0.0f;
    float O[8][4];
#pragma unroll
    for (int i = 0; i < 8; i++)
#pragma unroll
        for (int r = 0; r < 4; r++) O[i][r] = 0.0f;

    uint32_t aQh[4][4];

    for (int kt = 0; kt < 8; kt++) {
        CP_WAIT(0);
        __syncthreads();
        if (kt + 1 < 8) load_stage((kt + 1) & 1, kt + 1);

        if (kt == 0) {
#pragma unroll
            for (int kc = 0; kc < 4; kc++) {
                uint32_t off = (uint32_t)(w * 16 + (qq & 1) * 8 + lr) * 128 + (qq >> 1) * 16 + kc * 32;
                uint32_t sw = off ^ ((off >> 3) & 0x70);
                LDSM4(aQh[kc], sb + FQH + sw);
            }
        }

        const uint32_t st = sb + FST0 + (kt & 1) * FSTG;
        char* stp = sm + FST0 + (kt & 1) * FSTG;

#pragma unroll
        for (int sub = 0; sub < 2; sub++) {
            const uint32_t kofs = sub * 64 * 128;

            float C[8][4];
#pragma unroll
            for (int i = 0; i < 8; i++)
#pragma unroll
                for (int r = 0; r < 4; r++) C[i][r] = 0.0f;
#pragma unroll
            for (int ks = 0; ks < 4; ks++) {
#pragma unroll
                for (int j2 = 0; j2 < 4; j2++) {
                    uint32_t bh[4];
                    uint32_t off = kofs + (uint32_t)(j2 * 16 + (qq >> 1) * 8 + lr) * 128 +
                                   (qq & 1) * 16 + ks * 32;
                    uint32_t sw = off ^ ((off >> 3) & 0x70);
                    LDSM4(bh, st + FKH + sw);
                    MMA16816(C[j2 * 2],     aQh[ks], bh[0], bh[1]);
                    MMA16816(C[j2 * 2 + 1], aQh[ks], bh[2], bh[3]);
                }
            }

            float mx0 = -3.0e38f, mx1 = -3.0e38f;
#pragma unroll
            for (int nt = 0; nt < 8; nt++) {
                unsigned char s0 = *(unsigned char*)(stp + FSRC + sub * 64 + nt * 8 + tg * 2);
                unsigned char s1 = *(unsigned char*)(stp + FSRC + sub * 64 + nt * 8 + tg * 2 + 1);
                C[nt][0] = (t0m && s0) ? C[nt][0] * SC2L : NEGV;
                C[nt][1] = (t0m && s1) ? C[nt][1] * SC2L : NEGV;
                C[nt][2] = (t1m && s0) ? C[nt][2] * SC2L : NEGV;
                C[nt][3] = (t1m && s1) ? C[nt][3] * SC2L : NEGV;
                mx0 = fmaxf(mx0, fmaxf(C[nt][0], C[nt][1]));
                mx1 = fmaxf(mx1, fmaxf(C[nt][2], C[nt][3]));
            }
            mx0 = fmaxf(mx0, __shfl_xor_sync(0xFFFFFFFF, mx0, 1));
            mx0 = fmaxf(mx0, __shfl_xor_sync(0xFFFFFFFF, mx0, 2));
            mx1 = fmaxf(mx1, __shfl_xor_sync(0xFFFFFFFF, mx1, 1));
            mx1 = fmaxf(mx1, __shfl_xor_sync(0xFFFFFFFF, mx1, 2));

            float mn0 = fmaxf(m0r, mx0), mn1 = fmaxf(m1r, mx1);
            float f0 = ex2f(m0r - mn0), f1 = ex2f(m1r - mn1);
            m0r = mn0; m1r = mn1;

            float s0 = 0.0f, s1 = 0.0f;
#pragma unroll
            for (int nt = 0; nt < 8; nt++) {
                C[nt][0] = ex2f(C[nt][0] - mn0);
                C[nt][1] = ex2f(C[nt][1] - mn0);
                C[nt][2] = ex2f(C[nt][2] - mn1);
                C[nt][3] = ex2f(C[nt][3] - mn1);
                s0 += C[nt][0] + C[nt][1];
                s1 += C[nt][2] + C[nt][3];
            }
            s0 += __shfl_xor_sync(0xFFFFFFFF, s0, 1);
            s0 += __shfl_xor_sync(0xFFFFFFFF, s0, 2);
            s1 += __shfl_xor_sync(0xFFFFFFFF, s1, 1);
            s1 += __shfl_xor_sync(0xFFFFFFFF, s1, 2);
            l0r = l0r * f0 + s0;
            l1r = l1r * f1 + s1;

#pragma unroll
            for (int nt = 0; nt < 8; nt++) {
                O[nt][0] *= f0; O[nt][1] *= f0;
                O[nt][2] *= f1; O[nt][3] *= f1;
            }

            uint32_t aPh[4][4];
#pragma unroll
            for (int kc = 0; kc < 4; kc++) {
                const int n0 = kc * 2, n1 = kc * 2 + 1;
                aPh[kc][0] = pbf2(C[n0][0], C[n0][1]);
                aPh[kc][1] = pbf2(C[n0][2], C[n0][3]);
                aPh[kc][2] = pbf2(C[n1][0], C[n1][1]);
                aPh[kc][3] = pbf2(C[n1][2], C[n1][3]);
            }

#pragma unroll
            for (int kc = 0; kc < 4; kc++) {
#pragma unroll
                for (int nd = 0; nd < 4; nd++) {
                    uint32_t vh[4];
                    uint32_t off = kofs + (uint32_t)(kc * 16 + (qq & 1) * 8 + lr) * 128 +
                                   (nd * 16 + (qq >> 1) * 8) * 2;
                    uint32_t sw = off ^ ((off >> 3) & 0x70);
                    LDSM4T(vh, st + FVH + sw);
                    MMA16816(O[nd * 2],     aPh[kc], vh[0], vh[1]);
                    MMA16816(O[nd * 2 + 1], aPh[kc], vh[2], vh[3]);
                }
            }
        }
    }

    const float il0 = 1.0f / l0r, il1 = 1.0f / l1r;
    const int r0 = q0 + w * 16 + g;
    const int r1 = r0 + 8;
#pragma unroll
    for (int nt = 0; nt < 8; nt++) {
        const int col = h * 64 + nt * 8 + tg * 2;
        float2 w0 = make_float2(O[nt][0] * il0, O[nt][1] * il0);
        float2 w1 = make_float2(O[nt][2] * il1, O[nt][3] * il1);
        *(float2*)(out + ((size_t)b * 1024 + r0) * 1024 + col) = w0;
        *(float2*)(out + ((size_t)b * 1024 + r1) * 1024 + col) = w1;
    }
}

// ================= kernel_launch =================
extern "C" void kernel_launch(void* const* d_in, const int* in_sizes, int n_in,
                              void* d_out, int out_size)
{
    const float* q    = (const float*)d_in[0];
    const float* k    = (const float*)d_in[1];
    const float* v    = (const float*)d_in[2];
    const float* beta = (const float*)d_in[3];
    const unsigned char* srcm = (const unsigned char*)d_in[4];
    const unsigned char* tgtm = (const unsigned char*)d_in[5];
    const float* Wq = (const float*)d_in[6];
    const float* bq = (const float*)d_in[7];
    const float* Wk = (const float*)d_in[8];
    const float* bk = (const float*)d_in[9];
    const float* Wv = (const float*)d_in[10];
    const float* bv = (const float*)d_in[11];
    float* out = (float*)d_out;

    cudaFuncSetAttribute(gemm_qk,     cudaFuncAttributeMaxDynamicSharedMemorySize, QK_SMEM);
    cudaFuncSetAttribute(gemm_mma<0>, cudaFuncAttributeMaxDynamicSharedMemorySize, GSMEM_TOTAL);
    cudaFuncSetAttribute(gemm_mma<1>, cudaFuncAttributeMaxDynamicSharedMemorySize, GSMEM_TOTAL);
    cudaFuncSetAttribute(flash_tc,    cudaFuncAttributeMaxDynamicSharedMemorySize, FSMEM);

    mask_convert2<<<2, 1024>>>(srcm, tgtm, Bb * TK);

    // one conversion kernel for everything (acts, weights, beta), MLP=4
    conv_allx<<<11008, 256>>>((const float4*)q, (const float4*)k, (const float4*)v,
                              (const float4*)Wq, (const float4*)Wk, (const float4*)Wv,
                              (const float4*)beta);

    // Q,K projections (1-pass bf16, 2 CTAs/SM)
    gemm_qk<<<dim3(16, 64), 256, QK_SMEM>>>(bq, bk);
    // V projection (3-pass split)
    gemm_mma<0><<<dim3(8, 64), 256, GSMEM_TOTAL>>>(bv, nullptr);

    // flash attention (writes out)
    flash_tc<<<dim3(TQ / 128, NH, Bb), 256, FSMEM>>>(out);

    // beta @ V accumulated into out
    gemm_mma<1><<<dim3(4, 8, 16), 256, GSMEM_TOTAL>>>(nullptr, out);
}

// round 13
// speedup vs baseline: 1.2816x; 1.0170x over previous
#include <cuda_runtime.h>
#include <cuda_bf16.h>
#include <math.h>
#include <stdint.h>

// Problem constants
#define Bb    8
#define TQ    1024
#define TK    1024
#define DIMX  1024
#define NH    16
#define HD    64
#define SCALE 0.03125f
#define NEGV  -1.0e9f
#define MROWS (Bb * TQ)
#define SC2L  (0.03125f * 1.44269504088896f)

// ================= PTX helpers =================
__device__ __forceinline__ uint32_t smem_u32(const void* p) {
    uint32_t a;
    asm("{ .reg .u64 t; cvta.to.shared.u64 t, %1; cvt.u32.u64 %0, t; }"
        : "=r"(a) : "l"(p));
    return a;
}
#define CP_ASYNC16(dst_u32, src_ptr) \
    asm volatile("cp.async.cg.shared.global [%0], [%1], 16;" \
        :: "r"(dst_u32), "l"(src_ptr))
#define CP_COMMIT() asm volatile("cp.async.commit_group;" ::: "memory")
#define CP_WAIT(n)  asm volatile("cp.async.wait_group %0;" :: "n"(n) : "memory")

#define LDSM4(r, addr) \
    asm volatile("ldmatrix.sync.aligned.m8n8.x4.shared.b16 {%0,%1,%2,%3}, [%4];" \
        : "=r"((r)[0]), "=r"((r)[1]), "=r"((r)[2]), "=r"((r)[3]) : "r"(addr))
#define LDSM4T(r, addr) \
    asm volatile("ldmatrix.sync.aligned.m8n8.x4.trans.shared.b16 {%0,%1,%2,%3}, [%4];" \
        : "=r"((r)[0]), "=r"((r)[1]), "=r"((r)[2]), "=r"((r)[3]) : "r"(addr))

#define MMA16816(c, a, b0, b1) \
    asm volatile("mma.sync.aligned.m16n8k16.row.col.f32.bf16.bf16.f32 " \
        "{%0,%1,%2,%3}, {%4,%5,%6,%7}, {%8,%9}, {%0,%1,%2,%3};" \
        : "+f"((c)[0]), "+f"((c)[1]), "+f"((c)[2]), "+f"((c)[3]) \
        : "r"((a)[0]), "r"((a)[1]), "r"((a)[2]), "r"((a)[3]), "r"(b0), "r"(b1))

__device__ __forceinline__ uint32_t pbf2(float lo, float hi) {
    uint32_t d;
    asm("cvt.rn.bf16x2.f32 %0, %1, %2;" : "=r"(d) : "f"(hi), "f"(lo));
    return d;
}
__device__ __forceinline__ float ex2f(float x) {
    float y;
    asm("ex2.approx.ftz.f32 %0, %1;" : "=f"(y) : "f"(x));
    return y;
}

// ================= scratch =================
__device__ __align__(16) __nv_bfloat16 g_qph[(size_t)MROWS * DIMX];
__device__ __align__(16) __nv_bfloat16 g_kph[(size_t)MROWS * DIMX];
__device__ __align__(16) __nv_bfloat16 g_vph[(size_t)MROWS * DIMX];
__device__ __align__(16) __nv_bfloat16 g_vpl[(size_t)MROWS * DIMX];
__device__ __align__(16) __nv_bfloat16 g_ah[(size_t)24 * 1024 * 1024];   // acts q|k|v
__device__ __align__(16) __nv_bfloat16 g_al[(size_t)24 * 1024 * 1024];
__device__ __align__(16) __nv_bfloat16 g_bth[(size_t)16 * 1024 * 1024];  // beta hi
__device__ __align__(16) __nv_bfloat16 g_btl[(size_t)16 * 1024 * 1024];  // beta lo
__device__ __align__(16) __nv_bfloat16 g_bh[(size_t)3 * 1024 * 1024];
__device__ __align__(16) __nv_bfloat16 g_bl[(size_t)3 * 1024 * 1024];
__device__ unsigned char g_src8[Bb * TK];
__device__ unsigned char g_tgt8[Bb * TQ];

// ================= mask canonicalization =================
__global__ void mask_convert2(const unsigned char* __restrict__ raw0,
                              const unsigned char* __restrict__ raw1, int n)
{
    const unsigned char* raw = blockIdx.x ? raw1 : raw0;
    unsigned char* out = blockIdx.x ? g_tgt8 : g_src8;
    __shared__ int has3F, oddNZ;
    if (threadIdx.x == 0) { has3F = 0; oddNZ = 0; }
    __syncthreads();
    int lf = 0, lo = 0;
    for (int i = threadIdx.x; i < n; i += blockDim.x) {
        unsigned char c = raw[i];
        if (c == 0x3F) lf = 1;
        if ((i & 3) && c) lo = 1;
    }
    if (lf) atomicOr(&has3F, 1);
    if (lo) atomicOr(&oddNZ, 1);
    __syncthreads();
    int mode = has3F ? 2 : (oddNZ ? 0 : 1);
    for (int i = threadIdx.x; i < n; i += blockDim.x) {
        unsigned char v;
        if (mode == 2)      v = (((const float*)raw)[i] != 0.0f) ? 1 : 0;
        else if (mode == 1) v = (((const int*)raw)[i]   != 0)    ? 1 : 0;
        else                v = (raw[i] != 0) ? 1 : 0;
        out[i] = v;
    }
}

// ================= fp32 -> bf16 conversion (MLP=4) =================
__global__ __launch_bounds__(256)
void conv_allx(const float4* __restrict__ q, const float4* __restrict__ k,
               const float4* __restrict__ v, const float4* __restrict__ wq,
               const float4* __restrict__ wk, const float4* __restrict__ wv,
               const float4* __restrict__ beta)
{
    const size_t ACT = (size_t)8 * 1024 * 1024;
    const size_t WSEG = (size_t)1024 * 1024;
    int bid = blockIdx.x;
    const float4* src;
    __nv_bfloat16 *hi, *lo = nullptr;
    bool full;
    size_t base;
    if (bid < 6144) {
        int seg = bid / 2048;
        src = (seg == 0) ? q : (seg == 1) ? k : v;
        full = (seg == 2);
        hi = g_ah + seg * ACT; lo = g_al + seg * ACT;
        base = (size_t)(bid % 2048) * 1024;
    } else if (bid < 6912) {
        int seg = (bid - 6144) / 256;
        src = (seg == 0) ? wq : (seg == 1) ? wk : wv;
        full = (seg == 2);
        hi = g_bh + seg * WSEG; lo = g_bl + seg * WSEG;
        base = (size_t)((bid - 6144) % 256) * 1024;
    } else {
        src = beta; full = true;
        hi = g_bth; lo = g_btl;
        base = (size_t)(bid - 6912) * 1024;
    }
    const int tid = threadIdx.x;

    float4 f[4];
#pragma unroll
    for (int u = 0; u < 4; u++) f[u] = src[base + tid + u * 256];

    if (full) {
#pragma unroll
        for (int u = 0; u < 4; u++) {
            size_t i = base + tid + u * 256;
            __nv_bfloat16 h0 = __float2bfloat16_rn(f[u].x);
            __nv_bfloat16 h1 = __float2bfloat16_rn(f[u].y);
            __nv_bfloat16 h2 = __float2bfloat16_rn(f[u].z);
            __nv_bfloat16 h3 = __float2bfloat16_rn(f[u].w);
            __nv_bfloat16 l0 = __float2bfloat16_rn(f[u].x - __bfloat162float(h0));
            __nv_bfloat16 l1 = __float2bfloat16_rn(f[u].y - __bfloat162float(h1));
            __nv_bfloat16 l2 = __float2bfloat16_rn(f[u].z - __bfloat162float(h2));
            __nv_bfloat16 l3 = __float2bfloat16_rn(f[u].w - __bfloat162float(h3));
            __nv_bfloat162* Hp = (__nv_bfloat162*)(hi + 4 * i);
            __nv_bfloat162* Lp = (__nv_bfloat162*)(lo + 4 * i);
            Hp[0] = __halves2bfloat162(h0, h1);
            Hp[1] = __halves2bfloat162(h2, h3);
            Lp[0] = __halves2bfloat162(l0, l1);
            Lp[1] = __halves2bfloat162(l2, l3);
        }
    } else {
#pragma unroll
        for (int u = 0; u < 4; u++) {
            size_t i = base + tid + u * 256;
            __nv_bfloat162* Hp = (__nv_bfloat162*)(hi + 4 * i);
            Hp[0] = __halves2bfloat162(__float2bfloat16_rn(f[u].x), __float2bfloat16_rn(f[u].y));
            Hp[1] = __halves2bfloat162(__float2bfloat16_rn(f[u].z), __float2bfloat16_rn(f[u].w));
        }
    }
}

extern __shared__ char smem_raw[];

// ================= gemm_qk: 1-pass bf16, BK=64, 2 CTAs/SM (unchanged) =================
#define QK_STG 32768
#define QK_SMEM (3 * QK_STG)

__global__ __launch_bounds__(256, 2)
void gemm_qk(const float* __restrict__ bias0, const float* __restrict__ bias1)
{
    const uint32_t sb = smem_u32(smem_raw);
    const int tid  = threadIdx.x;
    const int lane = tid & 31;
    const int wid  = tid >> 5;
    const int wm = (wid >> 2) * 64;
    const int wn = (wid & 3) * 32;

    const int seg = blockIdx.x >> 3;
    const int bn  = (blockIdx.x & 7) * 128;
    const int bm  = blockIdx.y * 128;
    const __nv_bfloat16* Ahg = g_ah + (size_t)seg * 8 * 1024 * 1024;
    const __nv_bfloat16* Bhg = g_bh + (size_t)seg * 1024 * 1024;
    const float* bias = seg ? bias1 : bias0;
    __nv_bfloat16* Yh = seg ? g_kph : g_qph;

    float C[4][4][4];
#pragma unroll
    for (int i = 0; i < 4; i++)
#pragma unroll
        for (int j = 0; j < 4; j++)
#pragma unroll
            for (int r = 0; r < 4; r++) C[i][j][r] = 0.0f;

    auto load_stage = [&](int s, int kc) {
        const uint32_t st = sb + s * QK_STG;
        const int koff = kc * 64;
#pragma unroll
        for (int i = 0; i < 4; i++) {
            int idx = tid + i * 256;
            int row = idx >> 3, c = idx & 7;
            uint32_t off = row * 128 + c * 16;
            uint32_t sw = off ^ ((off >> 3) & 0x70);
            CP_ASYNC16(st + sw,         Ahg + (size_t)(bm + row) * 1024 + koff + c * 8);
            CP_ASYNC16(st + 16384 + sw, Bhg + (size_t)(bn + row) * 1024 + koff + c * 8);
        }
        CP_COMMIT();
    };

    const int q  = lane >> 3;
    const int lr = lane & 7;
    const int am_row = wm + (q & 1) * 8 + lr;
    const int a_kq   = (q >> 1) * 16;
    const int bn_row = wn + (q >> 1) * 8 + lr;
    const int b_kq   = (q & 1) * 16;

    load_stage(0, 0);
    load_stage(1, 1);

    for (int kc = 0; kc < 16; kc++) {
        if (kc < 15) CP_WAIT(1); else CP_WAIT(0);
        __syncthreads();
        if (kc + 2 < 16) load_stage((kc + 2) % 3, kc + 2);

        const uint32_t st = sb + (kc % 3) * QK_STG;
#pragma unroll
        for (int ks = 0; ks < 4; ks++) {
            uint32_t aH[4][4], bH[2][4];
#pragma unroll
            for (int i = 0; i < 4; i++) {
                uint32_t off = (uint32_t)(am_row + i * 16) * 128 + a_kq + ks * 32;
                uint32_t sw = off ^ ((off >> 3) & 0x70);
                LDSM4(aH[i], st + sw);
            }
#pragma unroll
            for (int j2 = 0; j2 < 2; j2++) {
                uint32_t off = (uint32_t)(bn_row + j2 * 16) * 128 + b_kq + ks * 32;
                uint32_t sw = off ^ ((off >> 3) & 0x70);
                LDSM4(bH[j2], st + 16384 + sw);
            }
#pragma unroll
            for (int i = 0; i < 4; i++)
#pragma unroll
                for (int j = 0; j < 4; j++) {
                    const int jj = j >> 1, jo = (j & 1) * 2;
                    MMA16816(C[i][j], aH[i], bH[jj][jo], bH[jj][jo + 1]);
                }
        }
    }

    const int g  = lane >> 2;
    const int tg = lane & 3;
#pragma unroll
    for (int i = 0; i < 4; i++)
#pragma unroll
        for (int j = 0; j < 4; j++) {
            const int col = bn + wn + j * 8 + tg * 2;
            const int r0 = bm + wm + i * 16 + g;
            float b0v = bias[col], b1v = bias[col + 1];
            *(uint32_t*)(Yh + (size_t)r0 * 1024 + col) = pbf2(C[i][j][0] + b0v, C[i][j][1] + b1v);
            *(uint32_t*)(Yh + (size_t)(r0 + 8) * 1024 + col) = pbf2(C[i][j][2] + b0v, C[i][j][3] + b1v);
        }
}

// ================= wide 3-pass GEMM: 512 threads, 128x256 tile, 2-stage =================
// MODE 0: V projection (hi/lo out).  MODE 1: beta@V accumulate into out.
// Stage: A hi @0 (16K), A lo @16384, B hi @32768 (32K), B lo @65536. 96KB/stage.
#define W_STG 98304
#define W_SMEM (2 * W_STG)

template <int MODE>
__global__ __launch_bounds__(512, 1)
void gemm_wide(const float* __restrict__ bias2, float* __restrict__ Yf)
{
    const uint32_t sb = smem_u32(smem_raw);
    const int tid  = threadIdx.x;
    const int lane = tid & 31;
    const int wid  = tid >> 5;            // 0..15
    const int wm = (wid >> 3) * 64;       // 0 / 64
    const int wn = (wid & 7) * 32;        // 0..224

    int bm, bn = 0, h = 0, b0 = 0;
    size_t arow0;
    const __nv_bfloat16 *Ahg, *Alg, *Bhg = nullptr, *Blg = nullptr;
    if (MODE == 0) {
        bn = blockIdx.x * 256; bm = blockIdx.y * 128;
        arow0 = (size_t)bm;
        Ahg = g_ah + (size_t)2 * 8 * 1024 * 1024;
        Alg = g_al + (size_t)2 * 8 * 1024 * 1024;
        Bhg = g_bh + (size_t)2 * 1024 * 1024;
        Blg = g_bl + (size_t)2 * 1024 * 1024;
    } else {
        b0 = blockIdx.x * 4; bm = blockIdx.y * 128; h = blockIdx.z;
        arow0 = (size_t)h * 1024 + bm;
        Ahg = g_bth; Alg = g_btl;
    }

    float C[4][4][4];
#pragma unroll
    for (int i = 0; i < 4; i++)
#pragma unroll
        for (int j = 0; j < 4; j++)
#pragma unroll
            for (int r = 0; r < 4; r++) C[i][j][r] = 0.0f;

    auto load_stage = [&](int s, int kc) {
        const uint32_t st = sb + s * W_STG;
        const int koff = kc * 64;
        // A hi+lo: 2048 cp.asyncs
#pragma unroll
        for (int i = 0; i < 4; i++) {
            int idx = tid + i * 512;
            int arr = idx >> 10, r2 = idx & 1023;
            int row = r2 >> 3, c = r2 & 7;
            uint32_t off = row * 128 + c * 16;
            uint32_t sw = off ^ ((off >> 3) & 0x70);
            const __nv_bfloat16* src = arr ? Alg : Ahg;
            CP_ASYNC16(st + arr * 16384 + sw, src + (arow0 + row) * 1024 + koff + c * 8);
        }
        // B hi+lo: 4096 cp.asyncs
#pragma unroll
        for (int i = 0; i < 8; i++) {
            int idx = tid + i * 512;
            if (MODE == 0) {
                int arr = idx >> 11, r2 = idx & 2047;
                int row = r2 >> 3, c = r2 & 7;
                uint32_t off = row * 128 + c * 16;
                uint32_t sw = off ^ ((off >> 3) & 0x70);
                const __nv_bfloat16* src = arr ? Blg : Bhg;
                CP_ASYNC16(st + 32768 + arr * 32768 + sw,
                           src + (size_t)(bn + row) * 1024 + koff + c * 8);
            } else {
                int batch = idx >> 10, rem = idx & 1023;
                int arr = rem >> 9, r2 = rem & 511;
                int row = r2 >> 3, c = r2 & 7;
                uint32_t off = row * 128 + c * 16;
                uint32_t sw = off ^ ((off >> 3) & 0x70);
                const __nv_bfloat16* src = arr ? g_vpl : g_vph;
                CP_ASYNC16(st + 32768 + arr * 32768 + batch * 8192 + sw,
                           src + ((size_t)(b0 + batch) * 1024 + koff + row) * 1024 + h * 64 + c * 8);
            }
        }
        CP_COMMIT();
    };

    const int q  = lane >> 3;
    const int lr = lane & 7;
    const int am_row = wm + (q & 1) * 8 + lr;
    const int a_kq   = (q >> 1) * 16;
    const int bn_row = wn + (q >> 1) * 8 + lr;
    const int b_kq   = (q & 1) * 16;

    load_stage(0, 0);

    for (int kc = 0; kc < 16; kc++) {
        CP_WAIT(0);
        __syncthreads();
        if (kc + 1 < 16) load_stage((kc + 1) & 1, kc + 1);

        const uint32_t st = sb + (kc & 1) * W_STG;
#pragma unroll
        for (int ks = 0; ks < 4; ks++) {
            uint32_t aH[4][4], aL[4][4];
#pragma unroll
            for (int i = 0; i < 4; i++) {
                uint32_t off = (uint32_t)(am_row + i * 16) * 128 + a_kq + ks * 32;
                uint32_t sw = off ^ ((off >> 3) & 0x70);
                LDSM4(aH[i], st + sw);
                LDSM4(aL[i], st + 16384 + sw);
            }
#pragma unroll
            for (int j2 = 0; j2 < 2; j2++) {
                uint32_t bH[4], bL[4];
                if (MODE == 0) {
                    uint32_t off = (uint32_t)(bn_row + j2 * 16) * 128 + b_kq + ks * 32;
                    uint32_t sw = off ^ ((off >> 3) & 0x70);
                    LDSM4(bH, st + 32768 + sw);
                    LDSM4(bL, st + 65536 + sw);
                } else {
                    const int n16 = wn + j2 * 16;
                    const int batch = n16 >> 6, d0 = n16 & 63;
                    uint32_t off = (uint32_t)(ks * 16 + (q & 1) * 8 + lr) * 128 +
                                   (d0 + (q >> 1) * 8) * 2;
                    uint32_t sw = off ^ ((off >> 3) & 0x70);
                    LDSM4T(bH, st + 32768 + batch * 8192 + sw);
                    LDSM4T(bL, st + 65536 + batch * 8192 + sw);
                }
#pragma unroll
                for (int i = 0; i < 4; i++)
#pragma unroll
                    for (int jo = 0; jo < 2; jo++) {
                        float* Cp = C[i][j2 * 2 + jo];
                        MMA16816(Cp, aH[i], bH[jo * 2], bH[jo * 2 + 1]);
                        MMA16816(Cp, aH[i], bL[jo * 2], bL[jo * 2 + 1]);
                        MMA16816(Cp, aL[i], bH[jo * 2], bH[jo * 2 + 1]);
                    }
            }
        }
    }

    const int g  = lane >> 2;
    const int tg = lane & 3;
#pragma unroll
    for (int i = 0; i < 4; i++) {
#pragma unroll
        for (int j = 0; j < 4; j++) {
            const int ncol = wn + j * 8 + tg * 2;
            const int r0 = bm + wm + i * 16 + g;
            const int r1 = r0 + 8;
            if (MODE == 0) {
                const int col = bn + ncol;
                float b0v = bias2[col], b1v = bias2[col + 1];
                float y00 = C[i][j][0] + b0v, y01 = C[i][j][1] + b1v;
                float y10 = C[i][j][2] + b0v, y11 = C[i][j][3] + b1v;
                float l00 = y00 - __bfloat162float(__float2bfloat16_rn(y00));
                float l01 = y01 - __bfloat162float(__float2bfloat16_rn(y01));
                float l10 = y10 - __bfloat162float(__float2bfloat16_rn(y10));
                float l11 = y11 - __bfloat162float(__float2bfloat16_rn(y11));
                *(uint32_t*)(g_vph + (size_t)r0 * 1024 + col) = pbf2(y00, y01);
                *(uint32_t*)(g_vph + (size_t)r1 * 1024 + col) = pbf2(y10, y11);
                *(uint32_t*)(g_vpl + (size_t)r0 * 1024 + col) = pbf2(l00, l01);
                *(uint32_t*)(g_vpl + (size_t)r1 * 1024 + col) = pbf2(l10, l11);
            } else {
                const int bb = b0 + (ncol >> 6);
                const int dd = ncol & 63;
                float* p0 = Yf + ((size_t)bb * 1024 + r0) * 1024 + h * 64 + dd;
                float* p1 = Yf + ((size_t)bb * 1024 + r1) * 1024 + h * 64 + dd;
                float2 o0 = *(float2*)p0, o1 = *(float2*)p1;
                o0.x += C[i][j][0]; o0.y += C[i][j][1];
                o1.x += C[i][j][2]; o1.y += C[i][j][3];
                *(float2*)p0 = o0;
                *(float2*)p1 = o1;
            }
        }
    }
}

// ================= flash attention (unchanged from R12) =================
#define FQH 0
#define FST0 16384
#define FKH 0
#define FVH 16384
#define FSRC 32768
#define FSTG 32896
#define FSMEM (16384 + 2 * FSTG)

__global__ __launch_bounds__(256, 2)
void flash_tc(float* __restrict__ out)
{
    char* sm = smem_raw;
    const uint32_t sb = smem_u32(sm);
    const int tid  = threadIdx.x;
    const int lane = tid & 31;
    const int w    = tid >> 5;
    const int q0 = blockIdx.x * 128;
    const int h  = blockIdx.y;
    const int b  = blockIdx.z;
    const int g  = lane >> 2;
    const int tg = lane & 3;
    const int qq = lane >> 3;
    const int lr = lane & 7;

    {
#pragma unroll
        for (int i = 0; i < 4; i++) {
            int idx = tid + i * 256;
            int row = idx >> 3, c = idx & 7;
            uint32_t off = row * 128 + c * 16;
            uint32_t sw = off ^ ((off >> 3) & 0x70);
            size_t gq = ((size_t)b * 1024 + q0 + row) * 1024 + h * 64 + c * 8;
            CP_ASYNC16(sb + FQH + sw, g_qph + gq);
        }
        CP_COMMIT();
    }

    auto load_stage = [&](int s, int kt) {
        const uint32_t st = sb + FST0 + s * FSTG;
        const int k0 = kt * 128;
#pragma unroll
        for (int i = 0; i < 4; i++) {
            int idx = tid + i * 256;
            int row = idx >> 3, c = idx & 7;
            uint32_t off = row * 128 + c * 16;
            uint32_t sw = off ^ ((off >> 3) & 0x70);
            size_t gk = ((size_t)b * 1024 + k0 + row) * 1024 + h * 64 + c * 8;
            CP_ASYNC16(st + FKH + sw, g_kph + gk);
            CP_ASYNC16(st + FVH + sw, g_vph + gk);
        }
        if (tid < 8)
            CP_ASYNC16(st + FSRC + tid * 16, g_src8 + b * 1024 + k0 + tid * 16);
        CP_COMMIT();
    };

    load_stage(0, 0);

    const unsigned char t0m = g_tgt8[b * 1024 + q0 + w * 16 + g];
    const unsigned char t1m = g_tgt8[b * 1024 + q0 + w * 16 + 8 + g];

    float m0r = -3.0e38f, m1r = -3.0e38f, l0r = 0.0f, l1r = 0.0f;
    float O[8][4];
#pragma unroll
    for (int i = 0; i < 8; i++)
#pragma unroll
        for (int r = 0; r < 4; r++) O[i][r] = 0.0f;

    uint32_t aQh[4][4];

    for (int kt = 0; kt < 8; kt++) {
        CP_WAIT(0);
        __syncthreads();
        if (kt + 1 < 8) load_stage((kt + 1) & 1, kt + 1);

        if (kt == 0) {
#pragma unroll
            for (int kc = 0; kc < 4; kc++) {
                uint32_t off = (uint32_t)(w * 16 + (qq & 1) * 8 + lr) * 128 + (qq >> 1) * 16 + kc * 32;
                uint32_t sw = off ^ ((off >> 3) & 0x70);
                LDSM4(aQh[kc], sb + FQH + sw);
            }
        }

        const uint32_t st = sb + FST0 + (kt & 1) * FSTG;
        char* stp = sm + FST0 + (kt & 1) * FSTG;

#pragma unroll
        for (int sub = 0; sub < 2; sub++) {
            const uint32_t kofs = sub * 64 * 128;

            float C[8][4];
#pragma unroll
            for (int i = 0; i < 8; i++)
#pragma unroll
                for (int r = 0; r < 4; r++) C[i][r] = 0.0f;
#pragma unroll
            for (int ks = 0; ks < 4; ks++) {
#pragma unroll
                for (int j2 = 0; j2 < 4; j2++) {
                    uint32_t bh[4];
                    uint32_t off = kofs + (uint32_t)(j2 * 16 + (qq >> 1) * 8 + lr) * 128 +
                                   (qq & 1) * 16 + ks * 32;
                    uint32_t sw = off ^ ((off >> 3) & 0x70);
                    LDSM4(bh, st + FKH + sw);
                    MMA16816(C[j2 * 2],     aQh[ks], bh[0], bh[1]);
                    MMA16816(C[j2 * 2 + 1], aQh[ks], bh[2], bh[3]);
                }
            }

            float mx0 = -3.0e38f, mx1 = -3.0e38f;
#pragma unroll
            for (int nt = 0; nt < 8; nt++) {
                unsigned char s0 = *(unsigned char*)(stp + FSRC + sub * 64 + nt * 8 + tg * 2);
                unsigned char s1 = *(unsigned char*)(stp + FSRC + sub * 64 + nt * 8 + tg * 2 + 1);
                C[nt][0] = (t0m && s0) ? C[nt][0] * SC2L : NEGV;
                C[nt][1] = (t0m && s1) ? C[nt][1] * SC2L : NEGV;
                C[nt][2] = (t1m && s0) ? C[nt][2] * SC2L : NEGV;
                C[nt][3] = (t1m && s1) ? C[nt][3] * SC2L : NEGV;
                mx0 = fmaxf(mx0, fmaxf(C[nt][0], C[nt][1]));
                mx1 = fmaxf(mx1, fmaxf(C[nt][2], C[nt][3]));
            }
            mx0 = fmaxf(mx0, __shfl_xor_sync(0xFFFFFFFF, mx0, 1));
            mx0 = fmaxf(mx0, __shfl_xor_sync(0xFFFFFFFF, mx0, 2));
            mx1 = fmaxf(mx1, __shfl_xor_sync(0xFFFFFFFF, mx1, 1));
            mx1 = fmaxf(mx1, __shfl_xor_sync(0xFFFFFFFF, mx1, 2));

            float mn0 = fmaxf(m0r, mx0), mn1 = fmaxf(m1r, mx1);
            float f0 = ex2f(m0r - mn0), f1 = ex2f(m1r - mn1);
            m0r = mn0; m1r = mn1;

            float s0 = 0.0f, s1 = 0.0f;
#pragma unroll
            for (int nt = 0; nt < 8; nt++) {
                C[nt][0] = ex2f(C[nt][0] - mn0);
                C[nt][1] = ex2f(C[nt][1] - mn0);
                C[nt][2] = ex2f(C[nt][2] - mn1);
                C[nt][3] = ex2f(C[nt][3] - mn1);
                s0 += C[nt][0] + C[nt][1];
                s1 += C[nt][2] + C[nt][3];
            }
            s0 += __shfl_xor_sync(0xFFFFFFFF, s0, 1);
            s0 += __shfl_xor_sync(0xFFFFFFFF, s0, 2);
            s1 += __shfl_xor_sync(0xFFFFFFFF, s1, 1);
            s1 += __shfl_xor_sync(0xFFFFFFFF, s1, 2);
            l0r = l0r * f0 + s0;
            l1r = l1r * f1 + s1;

#pragma unroll
            for (int nt = 0; nt < 8; nt++) {
                O[nt][0] *= f0; O[nt][1] *= f0;
                O[nt][2] *= f1; O[nt][3] *= f1;
            }

            uint32_t aPh[4][4];
#pragma unroll
            for (int kc = 0; kc < 4; kc++) {
                const int n0 = kc * 2, n1 = kc * 2 + 1;
                aPh[kc][0] = pbf2(C[n0][0], C[n0][1]);
                aPh[kc][1] = pbf2(C[n0][2], C[n0][3]);
                aPh[kc][2] = pbf2(C[n1][0], C[n1][1]);
                aPh[kc][3] = pbf2(C[n1][2], C[n1][3]);
            }

#pragma unroll
            for (int kc = 0; kc < 4; kc++) {
#pragma unroll
                for (int nd = 0; nd < 4; nd++) {
                    uint32_t vh[4];
                    uint32_t off = kofs + (uint32_t)(kc * 16 + (qq & 1) * 8 + lr) * 128 +
                                   (nd * 16 + (qq >> 1) * 8) * 2;
                    uint32_t sw = off ^ ((off >> 3) & 0x70);
                    LDSM4T(vh, st + FVH + sw);
                    MMA16816(O[nd * 2],     aPh[kc], vh[0], vh[1]);
                    MMA16816(O[nd * 2 + 1], aPh[kc], vh[2], vh[3]);
                }
            }
        }
    }

    const float il0 = 1.0f / l0r, il1 = 1.0f / l1r;
    const int r0 = q0 + w * 16 + g;
    const int r1 = r0 + 8;
#pragma unroll
    for (int nt = 0; nt < 8; nt++) {
        const int col = h * 64 + nt * 8 + tg * 2;
        float2 w0 = make_float2(O[nt][0] * il0, O[nt][1] * il0);
        float2 w1 = make_float2(O[nt][2] * il1, O[nt][3] * il1);
        *(float2*)(out + ((size_t)b * 1024 + r0) * 1024 + col) = w0;
        *(float2*)(out + ((size_t)b * 1024 + r1) * 1024 + col) = w1;
    }
}

// ================= kernel_launch =================
extern "C" void kernel_launch(void* const* d_in, const int* in_sizes, int n_in,
                              void* d_out, int out_size)
{
    const float* q    = (const float*)d_in[0];
    const float* k    = (const float*)d_in[1];
    const float* v    = (const float*)d_in[2];
    const float* beta = (const float*)d_in[3];
    const unsigned char* srcm = (const unsigned char*)d_in[4];
    const unsigned char* tgtm = (const unsigned char*)d_in[5];
    const float* Wq = (const float*)d_in[6];
    const float* bq = (const float*)d_in[7];
    const float* Wk = (const float*)d_in[8];
    const float* bk = (const float*)d_in[9];
    const float* Wv = (const float*)d_in[10];
    const float* bv = (const float*)d_in[11];
    float* out = (float*)d_out;

    cudaFuncSetAttribute(gemm_qk,      cudaFuncAttributeMaxDynamicSharedMemorySize, QK_SMEM);
    cudaFuncSetAttribute(gemm_wide<0>, cudaFuncAttributeMaxDynamicSharedMemorySize, W_SMEM);
    cudaFuncSetAttribute(gemm_wide<1>, cudaFuncAttributeMaxDynamicSharedMemorySize, W_SMEM);
    cudaFuncSetAttribute(flash_tc,     cudaFuncAttributeMaxDynamicSharedMemorySize, FSMEM);

    mask_convert2<<<2, 1024>>>(srcm, tgtm, Bb * TK);

    conv_allx<<<11008, 256>>>((const float4*)q, (const float4*)k, (const float4*)v,
                              (const float4*)Wq, (const float4*)Wk, (const float4*)Wv,
                              (const float4*)beta);

    // Q,K projections (1-pass bf16, 2 CTAs/SM)
    gemm_qk<<<dim3(16, 64), 256, QK_SMEM>>>(bq, bk);
    // V projection (3-pass, wide CTA)
    gemm_wide<0><<<dim3(4, 64), 512, W_SMEM>>>(bv, nullptr);

    // flash attention (writes out)
    flash_tc<<<dim3(TQ / 128, NH, Bb), 256, FSMEM>>>(out);

    // beta @ V accumulated into out (wide CTA)
    gemm_wide<1><<<dim3(2, 8, 16), 512, W_SMEM>>>(nullptr, out);
}

// round 14
// speedup vs baseline: 1.4174x; 1.1059x over previous
#include <cuda_runtime.h>
#include <cuda_bf16.h>
#include <math.h>
#include <stdint.h>

// Problem constants
#define Bb    8
#define TQ    1024
#define TK    1024
#define DIMX  1024
#define NH    16
#define HD    64
#define SCALE 0.03125f
#define NEGV  -1.0e9f
#define MROWS (Bb * TQ)
#define SC2L  (0.03125f * 1.44269504088896f)

// ================= PTX helpers =================
__device__ __forceinline__ uint32_t smem_u32(const void* p) {
    uint32_t a;
    asm("{ .reg .u64 t; cvta.to.shared.u64 t, %1; cvt.u32.u64 %0, t; }"
        : "=r"(a) : "l"(p));
    return a;
}
#define CP_ASYNC16(dst_u32, src_ptr) \
    asm volatile("cp.async.cg.shared.global [%0], [%1], 16;" \
        :: "r"(dst_u32), "l"(src_ptr))
#define CP_COMMIT() asm volatile("cp.async.commit_group;" ::: "memory")
#define CP_WAIT(n)  asm volatile("cp.async.wait_group %0;" :: "n"(n) : "memory")

#define LDSM4(r, addr) \
    asm volatile("ldmatrix.sync.aligned.m8n8.x4.shared.b16 {%0,%1,%2,%3}, [%4];" \
        : "=r"((r)[0]), "=r"((r)[1]), "=r"((r)[2]), "=r"((r)[3]) : "r"(addr))
#define LDSM4T(r, addr) \
    asm volatile("ldmatrix.sync.aligned.m8n8.x4.trans.shared.b16 {%0,%1,%2,%3}, [%4];" \
        : "=r"((r)[0]), "=r"((r)[1]), "=r"((r)[2]), "=r"((r)[3]) : "r"(addr))

#define MMA16816(c, a, b0, b1) \
    asm volatile("mma.sync.aligned.m16n8k16.row.col.f32.bf16.bf16.f32 " \
        "{%0,%1,%2,%3}, {%4,%5,%6,%7}, {%8,%9}, {%0,%1,%2,%3};" \
        : "+f"((c)[0]), "+f"((c)[1]), "+f"((c)[2]), "+f"((c)[3]) \
        : "r"((a)[0]), "r"((a)[1]), "r"((a)[2]), "r"((a)[3]), "r"(b0), "r"(b1))

__device__ __forceinline__ uint32_t pbf2(float lo, float hi) {
    uint32_t d;
    asm("cvt.rn.bf16x2.f32 %0, %1, %2;" : "=r"(d) : "f"(hi), "f"(lo));
    return d;
}
__device__ __forceinline__ float ex2f(float x) {
    float y;
    asm("ex2.approx.ftz.f32 %0, %1;" : "=f"(y) : "f"(x));
    return y;
}

// ================= scratch =================
__device__ __align__(16) __nv_bfloat16 g_qph[(size_t)MROWS * DIMX];
__device__ __align__(16) __nv_bfloat16 g_kph[(size_t)MROWS * DIMX];
__device__ __align__(16) __nv_bfloat16 g_vph[(size_t)MROWS * DIMX];
__device__ __align__(16) __nv_bfloat16 g_vpl[(size_t)MROWS * DIMX];
__device__ __align__(16) __nv_bfloat16 g_ah[(size_t)24 * 1024 * 1024];   // acts q|k|v
__device__ __align__(16) __nv_bfloat16 g_al[(size_t)24 * 1024 * 1024];
__device__ __align__(16) __nv_bfloat16 g_bth[(size_t)16 * 1024 * 1024];  // beta hi
__device__ __align__(16) __nv_bfloat16 g_btl[(size_t)16 * 1024 * 1024];  // beta lo
__device__ __align__(16) __nv_bfloat16 g_bh[(size_t)3 * 1024 * 1024];
__device__ __align__(16) __nv_bfloat16 g_bl[(size_t)3 * 1024 * 1024];
__device__ __align__(16) float g_bout[(size_t)MROWS * DIMX];             // beta@V result
__device__ unsigned char g_src8[Bb * TK];
__device__ unsigned char g_tgt8[Bb * TQ];

// ================= mask canonicalization =================
__global__ void mask_convert2(const unsigned char* __restrict__ raw0,
                              const unsigned char* __restrict__ raw1, int n)
{
    const unsigned char* raw = blockIdx.x ? raw1 : raw0;
    unsigned char* out = blockIdx.x ? g_tgt8 : g_src8;
    __shared__ int has3F, oddNZ;
    if (threadIdx.x == 0) { has3F = 0; oddNZ = 0; }
    __syncthreads();
    int lf = 0, lo = 0;
    for (int i = threadIdx.x; i < n; i += blockDim.x) {
        unsigned char c = raw[i];
        if (c == 0x3F) lf = 1;
        if ((i & 3) && c) lo = 1;
    }
    if (lf) atomicOr(&has3F, 1);
    if (lo) atomicOr(&oddNZ, 1);
    __syncthreads();
    int mode = has3F ? 2 : (oddNZ ? 0 : 1);
    for (int i = threadIdx.x; i < n; i += blockDim.x) {
        unsigned char v;
        if (mode == 2)      v = (((const float*)raw)[i] != 0.0f) ? 1 : 0;
        else if (mode == 1) v = (((const int*)raw)[i]   != 0)    ? 1 : 0;
        else                v = (raw[i] != 0) ? 1 : 0;
        out[i] = v;
    }
}

// ================= fp32 -> bf16 conversion (MLP=4) =================
__global__ __launch_bounds__(256)
void conv_allx(const float4* __restrict__ q, const float4* __restrict__ k,
               const float4* __restrict__ v, const float4* __restrict__ wq,
               const float4* __restrict__ wk, const float4* __restrict__ wv,
               const float4* __restrict__ beta)
{
    const size_t ACT = (size_t)8 * 1024 * 1024;
    const size_t WSEG = (size_t)1024 * 1024;
    int bid = blockIdx.x;
    const float4* src;
    __nv_bfloat16 *hi, *lo = nullptr;
    bool full;
    size_t base;
    if (bid < 6144) {
        int seg = bid / 2048;
        src = (seg == 0) ? q : (seg == 1) ? k : v;
        full = (seg == 2);
        hi = g_ah + seg * ACT; lo = g_al + seg * ACT;
        base = (size_t)(bid % 2048) * 1024;
    } else if (bid < 6912) {
        int seg = (bid - 6144) / 256;
        src = (seg == 0) ? wq : (seg == 1) ? wk : wv;
        full = (seg == 2);
        hi = g_bh + seg * WSEG; lo = g_bl + seg * WSEG;
        base = (size_t)((bid - 6144) % 256) * 1024;
    } else {
        src = beta; full = true;
        hi = g_bth; lo = g_btl;
        base = (size_t)(bid - 6912) * 1024;
    }
    const int tid = threadIdx.x;

    float4 f[4];
#pragma unroll
    for (int u = 0; u < 4; u++) f[u] = src[base + tid + u * 256];

    if (full) {
#pragma unroll
        for (int u = 0; u < 4; u++) {
            size_t i = base + tid + u * 256;
            __nv_bfloat16 h0 = __float2bfloat16_rn(f[u].x);
            __nv_bfloat16 h1 = __float2bfloat16_rn(f[u].y);
            __nv_bfloat16 h2 = __float2bfloat16_rn(f[u].z);
            __nv_bfloat16 h3 = __float2bfloat16_rn(f[u].w);
            __nv_bfloat16 l0 = __float2bfloat16_rn(f[u].x - __bfloat162float(h0));
            __nv_bfloat16 l1 = __float2bfloat16_rn(f[u].y - __bfloat162float(h1));
            __nv_bfloat16 l2 = __float2bfloat16_rn(f[u].z - __bfloat162float(h2));
            __nv_bfloat16 l3 = __float2bfloat16_rn(f[u].w - __bfloat162float(h3));
            __nv_bfloat162* Hp = (__nv_bfloat162*)(hi + 4 * i);
            __nv_bfloat162* Lp = (__nv_bfloat162*)(lo + 4 * i);
            Hp[0] = __halves2bfloat162(h0, h1);
            Hp[1] = __halves2bfloat162(h2, h3);
            Lp[0] = __halves2bfloat162(l0, l1);
            Lp[1] = __halves2bfloat162(l2, l3);
        }
    } else {
#pragma unroll
        for (int u = 0; u < 4; u++) {
            size_t i = base + tid + u * 256;
            __nv_bfloat162* Hp = (__nv_bfloat162*)(hi + 4 * i);
            Hp[0] = __halves2bfloat162(__float2bfloat16_rn(f[u].x), __float2bfloat16_rn(f[u].y));
            Hp[1] = __halves2bfloat162(__float2bfloat16_rn(f[u].z), __float2bfloat16_rn(f[u].w));
        }
    }
}

// ================= out += g_bout =================
__global__ __launch_bounds__(256)
void add_out(float4* __restrict__ out)
{
    size_t i = (size_t)blockIdx.x * 1024 + threadIdx.x;
    const float4* bo = (const float4*)g_bout;
    float4 a[4], b[4];
#pragma unroll
    for (int u = 0; u < 4; u++) { a[u] = out[i + u * 256]; b[u] = bo[i + u * 256]; }
#pragma unroll
    for (int u = 0; u < 4; u++) {
        a[u].x += b[u].x; a[u].y += b[u].y; a[u].z += b[u].z; a[u].w += b[u].w;
        out[i + u * 256] = a[u];
    }
}

extern __shared__ char smem_raw[];

// ================= gemm_qk: 1-pass bf16, BK=64, 2 CTAs/SM =================
#define QK_STG 32768
#define QK_SMEM (3 * QK_STG)

__global__ __launch_bounds__(256, 2)
void gemm_qk(const float* __restrict__ bias0, const float* __restrict__ bias1)
{
    const uint32_t sb = smem_u32(smem_raw);
    const int tid  = threadIdx.x;
    const int lane = tid & 31;
    const int wid  = tid >> 5;
    const int wm = (wid >> 2) * 64;
    const int wn = (wid & 3) * 32;

    const int seg = blockIdx.x >> 3;
    const int bn  = (blockIdx.x & 7) * 128;
    const int bm  = blockIdx.y * 128;
    const __nv_bfloat16* Ahg = g_ah + (size_t)seg * 8 * 1024 * 1024;
    const __nv_bfloat16* Bhg = g_bh + (size_t)seg * 1024 * 1024;
    const float* bias = seg ? bias1 : bias0;
    __nv_bfloat16* Yh = seg ? g_kph : g_qph;

    float C[4][4][4];
#pragma unroll
    for (int i = 0; i < 4; i++)
#pragma unroll
        for (int j = 0; j < 4; j++)
#pragma unroll
            for (int r = 0; r < 4; r++) C[i][j][r] = 0.0f;

    auto load_stage = [&](int s, int kc) {
        const uint32_t st = sb + s * QK_STG;
        const int koff = kc * 64;
#pragma unroll
        for (int i = 0; i < 4; i++) {
            int idx = tid + i * 256;
            int row = idx >> 3, c = idx & 7;
            uint32_t off = row * 128 + c * 16;
            uint32_t sw = off ^ ((off >> 3) & 0x70);
            CP_ASYNC16(st + sw,         Ahg + (size_t)(bm + row) * 1024 + koff + c * 8);
            CP_ASYNC16(st + 16384 + sw, Bhg + (size_t)(bn + row) * 1024 + koff + c * 8);
        }
        CP_COMMIT();
    };

    const int q  = lane >> 3;
    const int lr = lane & 7;
    const int am_row = wm + (q & 1) * 8 + lr;
    const int a_kq   = (q >> 1) * 16;
    const int bn_row = wn + (q >> 1) * 8 + lr;
    const int b_kq   = (q & 1) * 16;

    load_stage(0, 0);
    load_stage(1, 1);

    for (int kc = 0; kc < 16; kc++) {
        if (kc < 15) CP_WAIT(1); else CP_WAIT(0);
        __syncthreads();
        if (kc + 2 < 16) load_stage((kc + 2) % 3, kc + 2);

        const uint32_t st = sb + (kc % 3) * QK_STG;
#pragma unroll
        for (int ks = 0; ks < 4; ks++) {
            uint32_t aH[4][4], bH[2][4];
#pragma unroll
            for (int i = 0; i < 4; i++) {
                uint32_t off = (uint32_t)(am_row + i * 16) * 128 + a_kq + ks * 32;
                uint32_t sw = off ^ ((off >> 3) & 0x70);
                LDSM4(aH[i], st + sw);
            }
#pragma unroll
            for (int j2 = 0; j2 < 2; j2++) {
                uint32_t off = (uint32_t)(bn_row + j2 * 16) * 128 + b_kq + ks * 32;
                uint32_t sw = off ^ ((off >> 3) & 0x70);
                LDSM4(bH[j2], st + 16384 + sw);
            }
#pragma unroll
            for (int i = 0; i < 4; i++)
#pragma unroll
                for (int j = 0; j < 4; j++) {
                    const int jj = j >> 1, jo = (j & 1) * 2;
                    MMA16816(C[i][j], aH[i], bH[jj][jo], bH[jj][jo + 1]);
                }
        }
    }

    const int g  = lane >> 2;
    const int tg = lane & 3;
#pragma unroll
    for (int i = 0; i < 4; i++)
#pragma unroll
        for (int j = 0; j < 4; j++) {
            const int col = bn + wn + j * 8 + tg * 2;
            const int r0 = bm + wm + i * 16 + g;
            float b0v = bias[col], b1v = bias[col + 1];
            *(uint32_t*)(Yh + (size_t)r0 * 1024 + col) = pbf2(C[i][j][0] + b0v, C[i][j][1] + b1v);
            *(uint32_t*)(Yh + (size_t)(r0 + 8) * 1024 + col) = pbf2(C[i][j][2] + b0v, C[i][j][3] + b1v);
        }
}

// ================= wide 3-pass GEMM: 512 threads, 128x256 tile, 2-stage =================
// MODE 0: V projection (hi/lo out).  MODE 1: beta@V -> g_bout (plain store).
#define W_STG 98304
#define W_SMEM (2 * W_STG)

template <int MODE>
__global__ __launch_bounds__(512, 1)
void gemm_wide(const float* __restrict__ bias2, float* __restrict__ Yf)
{
    const uint32_t sb = smem_u32(smem_raw);
    const int tid  = threadIdx.x;
    const int lane = tid & 31;
    const int wid  = tid >> 5;
    const int wm = (wid >> 3) * 64;
    const int wn = (wid & 7) * 32;

    int bm, bn = 0, h = 0, b0 = 0;
    size_t arow0;
    const __nv_bfloat16 *Ahg, *Alg, *Bhg = nullptr, *Blg = nullptr;
    if (MODE == 0) {
        bn = blockIdx.x * 256; bm = blockIdx.y * 128;
        arow0 = (size_t)bm;
        Ahg = g_ah + (size_t)2 * 8 * 1024 * 1024;
        Alg = g_al + (size_t)2 * 8 * 1024 * 1024;
        Bhg = g_bh + (size_t)2 * 1024 * 1024;
        Blg = g_bl + (size_t)2 * 1024 * 1024;
    } else {
        b0 = blockIdx.x * 4; bm = blockIdx.y * 128; h = blockIdx.z;
        arow0 = (size_t)h * 1024 + bm;
        Ahg = g_bth; Alg = g_btl;
    }

    float C[4][4][4];
#pragma unroll
    for (int i = 0; i < 4; i++)
#pragma unroll
        for (int j = 0; j < 4; j++)
#pragma unroll
            for (int r = 0; r < 4; r++) C[i][j][r] = 0.0f;

    auto load_stage = [&](int s, int kc) {
        const uint32_t st = sb + s * W_STG;
        const int koff = kc * 64;
#pragma unroll
        for (int i = 0; i < 4; i++) {
            int idx = tid + i * 512;
            int arr = idx >> 10, r2 = idx & 1023;
            int row = r2 >> 3, c = r2 & 7;
            uint32_t off = row * 128 + c * 16;
            uint32_t sw = off ^ ((off >> 3) & 0x70);
            const __nv_bfloat16* src = arr ? Alg : Ahg;
            CP_ASYNC16(st + arr * 16384 + sw, src + (arow0 + row) * 1024 + koff + c * 8);
        }
#pragma unroll
        for (int i = 0; i < 8; i++) {
            int idx = tid + i * 512;
            if (MODE == 0) {
                int arr = idx >> 11, r2 = idx & 2047;
                int row = r2 >> 3, c = r2 & 7;
                uint32_t off = row * 128 + c * 16;
                uint32_t sw = off ^ ((off >> 3) & 0x70);
                const __nv_bfloat16* src = arr ? Blg : Bhg;
                CP_ASYNC16(st + 32768 + arr * 32768 + sw,
                           src + (size_t)(bn + row) * 1024 + koff + c * 8);
            } else {
                int batch = idx >> 10, rem = idx & 1023;
                int arr = rem >> 9, r2 = rem & 511;
                int row = r2 >> 3, c = r2 & 7;
                uint32_t off = row * 128 + c * 16;
                uint32_t sw = off ^ ((off >> 3) & 0x70);
                const __nv_bfloat16* src = arr ? g_vpl : g_vph;
                CP_ASYNC16(st + 32768 + arr * 32768 + batch * 8192 + sw,
                           src + ((size_t)(b0 + batch) * 1024 + koff + row) * 1024 + h * 64 + c * 8);
            }
        }
        CP_COMMIT();
    };

    const int q  = lane >> 3;
    const int lr = lane & 7;
    const int am_row = wm + (q & 1) * 8 + lr;
    const int a_kq   = (q >> 1) * 16;
    const int bn_row = wn + (q >> 1) * 8 + lr;
    const int b_kq   = (q & 1) * 16;

    load_stage(0, 0);

    for (int kc = 0; kc < 16; kc++) {
        CP_WAIT(0);
        __syncthreads();
        if (kc + 1 < 16) load_stage((kc + 1) & 1, kc + 1);

        const uint32_t st = sb + (kc & 1) * W_STG;
#pragma unroll
        for (int ks = 0; ks < 4; ks++) {
            uint32_t aH[4][4], aL[4][4];
#pragma unroll
            for (int i = 0; i < 4; i++) {
                uint32_t off = (uint32_t)(am_row + i * 16) * 128 + a_kq + ks * 32;
                uint32_t sw = off ^ ((off >> 3) & 0x70);
                LDSM4(aH[i], st + sw);
                LDSM4(aL[i], st + 16384 + sw);
            }
#pragma unroll
            for (int j2 = 0; j2 < 2; j2++) {
                uint32_t bH[4], bL[4];
                if (MODE == 0) {
                    uint32_t off = (uint32_t)(bn_row + j2 * 16) * 128 + b_kq + ks * 32;
                    uint32_t sw = off ^ ((off >> 3) & 0x70);
                    LDSM4(bH, st + 32768 + sw);
                    LDSM4(bL, st + 65536 + sw);
                } else {
                    const int n16 = wn + j2 * 16;
                    const int batch = n16 >> 6, d0 = n16 & 63;
                    uint32_t off = (uint32_t)(ks * 16 + (q & 1) * 8 + lr) * 128 +
                                   (d0 + (q >> 1) * 8) * 2;
                    uint32_t sw = off ^ ((off >> 3) & 0x70);
                    LDSM4T(bH, st + 32768 + batch * 8192 + sw);
                    LDSM4T(bL, st + 65536 + batch * 8192 + sw);
                }
#pragma unroll
                for (int i = 0; i < 4; i++)
#pragma unroll
                    for (int jo = 0; jo < 2; jo++) {
                        float* Cp = C[i][j2 * 2 + jo];
                        MMA16816(Cp, aH[i], bH[jo * 2], bH[jo * 2 + 1]);
                        MMA16816(Cp, aH[i], bL[jo * 2], bL[jo * 2 + 1]);
                        MMA16816(Cp, aL[i], bH[jo * 2], bH[jo * 2 + 1]);
                    }
            }
        }
    }

    const int g  = lane >> 2;
    const int tg = lane & 3;
#pragma unroll
    for (int i = 0; i < 4; i++) {
#pragma unroll
        for (int j = 0; j < 4; j++) {
            const int ncol = wn + j * 8 + tg * 2;
            const int r0 = bm + wm + i * 16 + g;
            const int r1 = r0 + 8;
            if (MODE == 0) {
                const int col = bn + ncol;
                float b0v = bias2[col], b1v = bias2[col + 1];
                float y00 = C[i][j][0] + b0v, y01 = C[i][j][1] + b1v;
                float y10 = C[i][j][2] + b0v, y11 = C[i][j][3] + b1v;
                float l00 = y00 - __bfloat162float(__float2bfloat16_rn(y00));
                float l01 = y01 - __bfloat162float(__float2bfloat16_rn(y01));
                float l10 = y10 - __bfloat162float(__float2bfloat16_rn(y10));
                float l11 = y11 - __bfloat162float(__float2bfloat16_rn(y11));
                *(uint32_t*)(g_vph + (size_t)r0 * 1024 + col) = pbf2(y00, y01);
                *(uint32_t*)(g_vph + (size_t)r1 * 1024 + col) = pbf2(y10, y11);
                *(uint32_t*)(g_vpl + (size_t)r0 * 1024 + col) = pbf2(l00, l01);
                *(uint32_t*)(g_vpl + (size_t)r1 * 1024 + col) = pbf2(l10, l11);
            } else {
                const int bb = b0 + (ncol >> 6);
                const int dd = ncol & 63;
                float* p0 = g_bout + ((size_t)bb * 1024 + r0) * 1024 + h * 64 + dd;
                float* p1 = g_bout + ((size_t)bb * 1024 + r1) * 1024 + h * 64 + dd;
                *(float2*)p0 = make_float2(C[i][j][0], C[i][j][1]);
                *(float2*)p1 = make_float2(C[i][j][2], C[i][j][3]);
            }
        }
    }
}

// ================= flash attention (unchanged) =================
#define FQH 0
#define FST0 16384
#define FKH 0
#define FVH 16384
#define FSRC 32768
#define FSTG 32896
#define FSMEM (16384 + 2 * FSTG)

__global__ __launch_bounds__(256, 2)
void flash_tc(float* __restrict__ out)
{
    char* sm = smem_raw;
    const uint32_t sb = smem_u32(sm);
    const int tid  = threadIdx.x;
    const int lane = tid & 31;
    const int w    = tid >> 5;
    const int q0 = blockIdx.x * 128;
    const int h  = blockIdx.y;
    const int b  = blockIdx.z;
    const int g  = lane >> 2;
    const int tg = lane & 3;
    const int qq = lane >> 3;
    const int lr = lane & 7;

    {
#pragma unroll
        for (int i = 0; i < 4; i++) {
            int idx = tid + i * 256;
            int row = idx >> 3, c = idx & 7;
            uint32_t off = row * 128 + c * 16;
            uint32_t sw = off ^ ((off >> 3) & 0x70);
            size_t gq = ((size_t)b * 1024 + q0 + row) * 1024 + h * 64 + c * 8;
            CP_ASYNC16(sb + FQH + sw, g_qph + gq);
        }
        CP_COMMIT();
    }

    auto load_stage = [&](int s, int kt) {
        const uint32_t st = sb + FST0 + s * FSTG;
        const int k0 = kt * 128;
#pragma unroll
        for (int i = 0; i < 4; i++) {
            int idx = tid + i * 256;
            int row = idx >> 3, c = idx & 7;
            uint32_t off = row * 128 + c * 16;
            uint32_t sw = off ^ ((off >> 3) & 0x70);
            size_t gk = ((size_t)b * 1024 + k0 + row) * 1024 + h * 64 + c * 8;
            CP_ASYNC16(st + FKH + sw, g_kph + gk);
            CP_ASYNC16(st + FVH + sw, g_vph + gk);
        }
        if (tid < 8)
            CP_ASYNC16(st + FSRC + tid * 16, g_src8 + b * 1024 + k0 + tid * 16);
        CP_COMMIT();
    };

    load_stage(0, 0);

    const unsigned char t0m = g_tgt8[b * 1024 + q0 + w * 16 + g];
    const unsigned char t1m = g_tgt8[b * 1024 + q0 + w * 16 + 8 + g];

    float m0r = -3.0e38f, m1r = -3.0e38f, l0r = 0.0f, l1r = 0.0f;
    float O[8][4];
#pragma unroll
    for (int i = 0; i < 8; i++)
#pragma unroll
        for (int r = 0; r < 4; r++) O[i][r] = 0.0f;

    uint32_t aQh[4][4];

    for (int kt = 0; kt < 8; kt++) {
        CP_WAIT(0);
        __syncthreads();
        if (kt + 1 < 8) load_stage((kt + 1) & 1, kt + 1);

        if (kt == 0) {
#pragma unroll
            for (int kc = 0; kc < 4; kc++) {
                uint32_t off = (uint32_t)(w * 16 + (qq & 1) * 8 + lr) * 128 + (qq >> 1) * 16 + kc * 32;
                uint32_t sw = off ^ ((off >> 3) & 0x70);
                LDSM4(aQh[kc], sb + FQH + sw);
            }
        }

        const uint32_t st = sb + FST0 + (kt & 1) * FSTG;
        char* stp = sm + FST0 + (kt & 1) * FSTG;

#pragma unroll
        for (int sub = 0; sub < 2; sub++) {
            const uint32_t kofs = sub * 64 * 128;

            float C[8][4];
#pragma unroll
            for (int i = 0; i < 8; i++)
#pragma unroll
                for (int r = 0; r < 4; r++) C[i][r] = 0.0f;
#pragma unroll
            for (int ks = 0; ks < 4; ks++) {
#pragma unroll
                for (int j2 = 0; j2 < 4; j2++) {
                    uint32_t bh[4];
                    uint32_t off = kofs + (uint32_t)(j2 * 16 + (qq >> 1) * 8 + lr) * 128 +
                                   (qq & 1) * 16 + ks * 32;
                    uint32_t sw = off ^ ((off >> 3) & 0x70);
                    LDSM4(bh, st + FKH + sw);
                    MMA16816(C[j2 * 2],     aQh[ks], bh[0], bh[1]);
                    MMA16816(C[j2 * 2 + 1], aQh[ks], bh[2], bh[3]);
                }
            }

            float mx0 = -3.0e38f, mx1 = -3.0e38f;
#pragma unroll
            for (int nt = 0; nt < 8; nt++) {
                unsigned char s0 = *(unsigned char*)(stp + FSRC + sub * 64 + nt * 8 + tg * 2);
                unsigned char s1 = *(unsigned char*)(stp + FSRC + sub * 64 + nt * 8 + tg * 2 + 1);
                C[nt][0] = (t0m && s0) ? C[nt][0] * SC2L : NEGV;
                C[nt][1] = (t0m && s1) ? C[nt][1] * SC2L : NEGV;
                C[nt][2] = (t1m && s0) ? C[nt][2] * SC2L : NEGV;
                C[nt][3] = (t1m && s1) ? C[nt][3] * SC2L : NEGV;
                mx0 = fmaxf(mx0, fmaxf(C[nt][0], C[nt][1]));
                mx1 = fmaxf(mx1, fmaxf(C[nt][2], C[nt][3]));
            }
            mx0 = fmaxf(mx0, __shfl_xor_sync(0xFFFFFFFF, mx0, 1));
            mx0 = fmaxf(mx0, __shfl_xor_sync(0xFFFFFFFF, mx0, 2));
            mx1 = fmaxf(mx1, __shfl_xor_sync(0xFFFFFFFF, mx1, 1));
            mx1 = fmaxf(mx1, __shfl_xor_sync(0xFFFFFFFF, mx1, 2));

            float mn0 = fmaxf(m0r, mx0), mn1 = fmaxf(m1r, mx1);
            float f0 = ex2f(m0r - mn0), f1 = ex2f(m1r - mn1);
            m0r = mn0; m1r = mn1;

            float s0 = 0.0f, s1 = 0.0f;
#pragma unroll
            for (int nt = 0; nt < 8; nt++) {
                C[nt][0] = ex2f(C[nt][0] - mn0);
                C[nt][1] = ex2f(C[nt][1] - mn0);
                C[nt][2] = ex2f(C[nt][2] - mn1);
                C[nt][3] = ex2f(C[nt][3] - mn1);
                s0 += C[nt][0] + C[nt][1];
                s1 += C[nt][2] + C[nt][3];
            }
            s0 += __shfl_xor_sync(0xFFFFFFFF, s0, 1);
            s0 += __shfl_xor_sync(0xFFFFFFFF, s0, 2);
            s1 += __shfl_xor_sync(0xFFFFFFFF, s1, 1);
            s1 += __shfl_xor_sync(0xFFFFFFFF, s1, 2);
            l0r = l0r * f0 + s0;
            l1r = l1r * f1 + s1;

#pragma unroll
            for (int nt = 0; nt < 8; nt++) {
                O[nt][0] *= f0; O[nt][1] *= f0;
                O[nt][2] *= f1; O[nt][3] *= f1;
            }

            uint32_t aPh[4][4];
#pragma unroll
            for (int kc = 0; kc < 4; kc++) {
                const int n0 = kc * 2, n1 = kc * 2 + 1;
                aPh[kc][0] = pbf2(C[n0][0], C[n0][1]);
                aPh[kc][1] = pbf2(C[n0][2], C[n0][3]);
                aPh[kc][2] = pbf2(C[n1][0], C[n1][1]);
                aPh[kc][3] = pbf2(C[n1][2], C[n1][3]);
            }

#pragma unroll
            for (int kc = 0; kc < 4; kc++) {
#pragma unroll
                for (int nd = 0; nd < 4; nd++) {
                    uint32_t vh[4];
                    uint32_t off = kofs + (uint32_t)(kc * 16 + (qq & 1) * 8 + lr) * 128 +
                                   (nd * 16 + (qq >> 1) * 8) * 2;
                    uint32_t sw = off ^ ((off >> 3) & 0x70);
                    LDSM4T(vh, st + FVH + sw);
                    MMA16816(O[nd * 2],     aPh[kc], vh[0], vh[1]);
                    MMA16816(O[nd * 2 + 1], aPh[kc], vh[2], vh[3]);
                }
            }
        }
    }

    const float il0 = 1.0f / l0r, il1 = 1.0f / l1r;
    const int r0 = q0 + w * 16 + g;
    const int r1 = r0 + 8;
#pragma unroll
    for (int nt = 0; nt < 8; nt++) {
        const int col = h * 64 + nt * 8 + tg * 2;
        float2 w0 = make_float2(O[nt][0] * il0, O[nt][1] * il0);
        float2 w1 = make_float2(O[nt][2] * il1, O[nt][3] * il1);
        *(float2*)(out + ((size_t)b * 1024 + r0) * 1024 + col) = w0;
        *(float2*)(out + ((size_t)b * 1024 + r1) * 1024 + col) = w1;
    }
}

// ================= kernel_launch =================
extern "C" void kernel_launch(void* const* d_in, const int* in_sizes, int n_in,
                              void* d_out, int out_size)
{
    const float* q    = (const float*)d_in[0];
    const float* k    = (const float*)d_in[1];
    const float* v    = (const float*)d_in[2];
    const float* beta = (const float*)d_in[3];
    const unsigned char* srcm = (const unsigned char*)d_in[4];
    const unsigned char* tgtm = (const unsigned char*)d_in[5];
    const float* Wq = (const float*)d_in[6];
    const float* bq = (const float*)d_in[7];
    const float* Wk = (const float*)d_in[8];
    const float* bk = (const float*)d_in[9];
    const float* Wv = (const float*)d_in[10];
    const float* bv = (const float*)d_in[11];
    float* out = (float*)d_out;

    cudaFuncSetAttribute(gemm_qk,      cudaFuncAttributeMaxDynamicSharedMemorySize, QK_SMEM);
    cudaFuncSetAttribute(gemm_wide<0>, cudaFuncAttributeMaxDynamicSharedMemorySize, W_SMEM);
    cudaFuncSetAttribute(gemm_wide<1>, cudaFuncAttributeMaxDynamicSharedMemorySize, W_SMEM);
    cudaFuncSetAttribute(flash_tc,     cudaFuncAttributeMaxDynamicSharedMemorySize, FSMEM);

    // Fork-join: side stream runs V-proj then beta-GEMM while the main stream
    // runs QK-proj then flash. Streams/events are created per call and not
    // destroyed (destroying capture-participating objects mid-capture is
    // illegal; kernel_launch is invoked only a handful of times).
    cudaStream_t s1;
    cudaStreamCreateWithFlags(&s1, cudaStreamNonBlocking);
    cudaEvent_t evC, evV, evB;
    cudaEventCreateWithFlags(&evC, cudaEventDisableTiming);
    cudaEventCreateWithFlags(&evV, cudaEventDisableTiming);
    cudaEventCreateWithFlags(&evB, cudaEventDisableTiming);

    // main stream: masks + conversions
    mask_convert2<<<2, 1024>>>(srcm, tgtm, Bb * TK);
    conv_allx<<<11008, 256>>>((const float4*)q, (const float4*)k, (const float4*)v,
                              (const float4*)Wq, (const float4*)Wk, (const float4*)Wv,
                              (const float4*)beta);
    cudaEventRecord(evC, 0);
    cudaStreamWaitEvent(s1, evC, 0);

    // side stream: V projection -> beta GEMM (into g_bout)
    gemm_wide<0><<<dim3(4, 64), 512, W_SMEM, s1>>>(bv, nullptr);
    cudaEventRecord(evV, s1);
    gemm_wide<1><<<dim3(2, 8, 16), 512, W_SMEM, s1>>>(nullptr, nullptr);
    cudaEventRecord(evB, s1);

    // main stream: QK projection, then flash (needs V), then add (needs beta)
    gemm_qk<<<dim3(16, 64), 256, QK_SMEM>>>(bq, bk);
    cudaStreamWaitEvent(0, evV, 0);
    flash_tc<<<dim3(TQ / 128, NH, Bb), 256, FSMEM>>>(out);
    cudaStreamWaitEvent(0, evB, 0);
    add_out<<<2048, 256>>>((float4*)out);
}

// round 15
// speedup vs baseline: 1.4809x; 1.0447x over previous
#include <cuda_runtime.h>
#include <cuda_bf16.h>
#include <math.h>
#include <stdint.h>

// Problem constants
#define Bb    8
#define TQ    1024
#define TK    1024
#define DIMX  1024
#define NH    16
#define HD    64
#define SCALE 0.03125f
#define NEGV  -1.0e9f
#define MROWS (Bb * TQ)
#define SC2L  (0.03125f * 1.44269504088896f)

// ================= PTX helpers =================
__device__ __forceinline__ uint32_t smem_u32(const void* p) {
    uint32_t a;
    asm("{ .reg .u64 t; cvta.to.shared.u64 t, %1; cvt.u32.u64 %0, t; }"
        : "=r"(a) : "l"(p));
    return a;
}
#define CP_ASYNC16(dst_u32, src_ptr) \
    asm volatile("cp.async.cg.shared.global [%0], [%1], 16;" \
        :: "r"(dst_u32), "l"(src_ptr))
#define CP_COMMIT() asm volatile("cp.async.commit_group;" ::: "memory")
#define CP_WAIT(n)  asm volatile("cp.async.wait_group %0;" :: "n"(n) : "memory")

#define LDSM4(r, addr) \
    asm volatile("ldmatrix.sync.aligned.m8n8.x4.shared.b16 {%0,%1,%2,%3}, [%4];" \
        : "=r"((r)[0]), "=r"((r)[1]), "=r"((r)[2]), "=r"((r)[3]) : "r"(addr))
#define LDSM4T(r, addr) \
    asm volatile("ldmatrix.sync.aligned.m8n8.x4.trans.shared.b16 {%0,%1,%2,%3}, [%4];" \
        : "=r"((r)[0]), "=r"((r)[1]), "=r"((r)[2]), "=r"((r)[3]) : "r"(addr))

#define MMA16816(c, a, b0, b1) \
    asm volatile("mma.sync.aligned.m16n8k16.row.col.f32.bf16.bf16.f32 " \
        "{%0,%1,%2,%3}, {%4,%5,%6,%7}, {%8,%9}, {%0,%1,%2,%3};" \
        : "+f"((c)[0]), "+f"((c)[1]), "+f"((c)[2]), "+f"((c)[3]) \
        : "r"((a)[0]), "r"((a)[1]), "r"((a)[2]), "r"((a)[3]), "r"(b0), "r"(b1))

__device__ __forceinline__ uint32_t pbf2(float lo, float hi) {
    uint32_t d;
    asm("cvt.rn.bf16x2.f32 %0, %1, %2;" : "=r"(d) : "f"(hi), "f"(lo));
    return d;
}
__device__ __forceinline__ float ex2f(float x) {
    float y;
    asm("ex2.approx.ftz.f32 %0, %1;" : "=f"(y) : "f"(x));
    return y;
}

// ================= scratch =================
__device__ __align__(16) __nv_bfloat16 g_qph[(size_t)MROWS * DIMX];
__device__ __align__(16) __nv_bfloat16 g_kph[(size_t)MROWS * DIMX];
__device__ __align__(16) __nv_bfloat16 g_vph[(size_t)MROWS * DIMX];
__device__ __align__(16) __nv_bfloat16 g_vpl[(size_t)MROWS * DIMX];
__device__ __align__(16) __nv_bfloat16 g_ah[(size_t)24 * 1024 * 1024];   // acts q|k|v
__device__ __align__(16) __nv_bfloat16 g_al[(size_t)24 * 1024 * 1024];
__device__ __align__(16) __nv_bfloat16 g_bth[(size_t)16 * 1024 * 1024];  // beta hi
__device__ __align__(16) __nv_bfloat16 g_btl[(size_t)16 * 1024 * 1024];  // beta lo
__device__ __align__(16) __nv_bfloat16 g_bh[(size_t)3 * 1024 * 1024];
__device__ __align__(16) __nv_bfloat16 g_bl[(size_t)3 * 1024 * 1024];
__device__ __align__(16) float g_bout[(size_t)MROWS * DIMX];             // beta@V result
__device__ unsigned char g_src8[Bb * TK];
__device__ unsigned char g_tgt8[Bb * TQ];

// ================= mask canonicalization =================
__global__ void mask_convert2(const unsigned char* __restrict__ raw0,
                              const unsigned char* __restrict__ raw1, int n)
{
    const unsigned char* raw = blockIdx.x ? raw1 : raw0;
    unsigned char* out = blockIdx.x ? g_tgt8 : g_src8;
    __shared__ int has3F, oddNZ;
    if (threadIdx.x == 0) { has3F = 0; oddNZ = 0; }
    __syncthreads();
    int lf = 0, lo = 0;
    for (int i = threadIdx.x; i < n; i += blockDim.x) {
        unsigned char c = raw[i];
        if (c == 0x3F) lf = 1;
        if ((i & 3) && c) lo = 1;
    }
    if (lf) atomicOr(&has3F, 1);
    if (lo) atomicOr(&oddNZ, 1);
    __syncthreads();
    int mode = has3F ? 2 : (oddNZ ? 0 : 1);
    for (int i = threadIdx.x; i < n; i += blockDim.x) {
        unsigned char v;
        if (mode == 2)      v = (((const float*)raw)[i] != 0.0f) ? 1 : 0;
        else if (mode == 1) v = (((const int*)raw)[i]   != 0)    ? 1 : 0;
        else                v = (raw[i] != 0) ? 1 : 0;
        out[i] = v;
    }
}

// ================= fp32 -> bf16 conversion slices (MLP=4) =================
__device__ __forceinline__ void conv_block(const float4* __restrict__ src,
                                           __nv_bfloat16* __restrict__ hi,
                                           __nv_bfloat16* __restrict__ lo,
                                           bool full, size_t base)
{
    const int tid = threadIdx.x;
    float4 f[4];
#pragma unroll
    for (int u = 0; u < 4; u++) f[u] = src[base + tid + u * 256];
    if (full) {
#pragma unroll
        for (int u = 0; u < 4; u++) {
            size_t i = base + tid + u * 256;
            __nv_bfloat16 h0 = __float2bfloat16_rn(f[u].x);
            __nv_bfloat16 h1 = __float2bfloat16_rn(f[u].y);
            __nv_bfloat16 h2 = __float2bfloat16_rn(f[u].z);
            __nv_bfloat16 h3 = __float2bfloat16_rn(f[u].w);
            __nv_bfloat16 l0 = __float2bfloat16_rn(f[u].x - __bfloat162float(h0));
            __nv_bfloat16 l1 = __float2bfloat16_rn(f[u].y - __bfloat162float(h1));
            __nv_bfloat16 l2 = __float2bfloat16_rn(f[u].z - __bfloat162float(h2));
            __nv_bfloat16 l3 = __float2bfloat16_rn(f[u].w - __bfloat162float(h3));
            __nv_bfloat162* Hp = (__nv_bfloat162*)(hi + 4 * i);
            __nv_bfloat162* Lp = (__nv_bfloat162*)(lo + 4 * i);
            Hp[0] = __halves2bfloat162(h0, h1);
            Hp[1] = __halves2bfloat162(h2, h3);
            Lp[0] = __halves2bfloat162(l0, l1);
            Lp[1] = __halves2bfloat162(l2, l3);
        }
    } else {
#pragma unroll
        for (int u = 0; u < 4; u++) {
            size_t i = base + tid + u * 256;
            __nv_bfloat162* Hp = (__nv_bfloat162*)(hi + 4 * i);
            Hp[0] = __halves2bfloat162(__float2bfloat16_rn(f[u].x), __float2bfloat16_rn(f[u].y));
            Hp[1] = __halves2bfloat162(__float2bfloat16_rn(f[u].z), __float2bfloat16_rn(f[u].w));
        }
    }
}

// MODE 0: v + Wv (2304 blocks).  MODE 1: q,k + Wq,Wk (4608 blocks).  MODE 2: beta (4096).
template <int MODE>
__global__ __launch_bounds__(256)
void conv_part(const float4* __restrict__ p0, const float4* __restrict__ p1,
               const float4* __restrict__ p2, const float4* __restrict__ p3)
{
    const size_t ACT = (size_t)8 * 1024 * 1024;
    const size_t WSEG = (size_t)1024 * 1024;
    int bid = blockIdx.x;
    if (MODE == 0) {
        if (bid < 2048)
            conv_block(p0, g_ah + 2 * ACT, g_al + 2 * ACT, true, (size_t)bid * 1024);
        else
            conv_block(p1, g_bh + 2 * WSEG, g_bl + 2 * WSEG, true, (size_t)(bid - 2048) * 1024);
    } else if (MODE == 1) {
        if (bid < 2048)
            conv_block(p0, g_ah, nullptr, false, (size_t)bid * 1024);
        else if (bid < 4096)
            conv_block(p1, g_ah + ACT, nullptr, false, (size_t)(bid - 2048) * 1024);
        else if (bid < 4352)
            conv_block(p2, g_bh, nullptr, false, (size_t)(bid - 4096) * 1024);
        else
            conv_block(p3, g_bh + WSEG, nullptr, false, (size_t)(bid - 4352) * 1024);
    } else {
        conv_block(p0, g_bth, g_btl, true, (size_t)bid * 1024);
    }
}

// ================= out += g_bout =================
__global__ __launch_bounds__(256)
void add_out(float4* __restrict__ out)
{
    size_t i = (size_t)blockIdx.x * 1024 + threadIdx.x;
    const float4* bo = (const float4*)g_bout;
    float4 a[4], b[4];
#pragma unroll
    for (int u = 0; u < 4; u++) { a[u] = out[i + u * 256]; b[u] = bo[i + u * 256]; }
#pragma unroll
    for (int u = 0; u < 4; u++) {
        a[u].x += b[u].x; a[u].y += b[u].y; a[u].z += b[u].z; a[u].w += b[u].w;
        out[i + u * 256] = a[u];
    }
}

extern __shared__ char smem_raw[];

// ================= gemm_qk: 1-pass bf16, BK=64, 2 CTAs/SM =================
#define QK_STG 32768
#define QK_SMEM (3 * QK_STG)

__global__ __launch_bounds__(256, 2)
void gemm_qk(const float* __restrict__ bias0, const float* __restrict__ bias1)
{
    const uint32_t sb = smem_u32(smem_raw);
    const int tid  = threadIdx.x;
    const int lane = tid & 31;
    const int wid  = tid >> 5;
    const int wm = (wid >> 2) * 64;
    const int wn = (wid & 3) * 32;

    const int seg = blockIdx.x >> 3;
    const int bn  = (blockIdx.x & 7) * 128;
    const int bm  = blockIdx.y * 128;
    const __nv_bfloat16* Ahg = g_ah + (size_t)seg * 8 * 1024 * 1024;
    const __nv_bfloat16* Bhg = g_bh + (size_t)seg * 1024 * 1024;
    const float* bias = seg ? bias1 : bias0;
    __nv_bfloat16* Yh = seg ? g_kph : g_qph;

    float C[4][4][4];
#pragma unroll
    for (int i = 0; i < 4; i++)
#pragma unroll
        for (int j = 0; j < 4; j++)
#pragma unroll
            for (int r = 0; r < 4; r++) C[i][j][r] = 0.0f;

    auto load_stage = [&](int s, int kc) {
        const uint32_t st = sb + s * QK_STG;
        const int koff = kc * 64;
#pragma unroll
        for (int i = 0; i < 4; i++) {
            int idx = tid + i * 256;
            int row = idx >> 3, c = idx & 7;
            uint32_t off = row * 128 + c * 16;
            uint32_t sw = off ^ ((off >> 3) & 0x70);
            CP_ASYNC16(st + sw,         Ahg + (size_t)(bm + row) * 1024 + koff + c * 8);
            CP_ASYNC16(st + 16384 + sw, Bhg + (size_t)(bn + row) * 1024 + koff + c * 8);
        }
        CP_COMMIT();
    };

    const int q  = lane >> 3;
    const int lr = lane & 7;
    const int am_row = wm + (q & 1) * 8 + lr;
    const int a_kq   = (q >> 1) * 16;
    const int bn_row = wn + (q >> 1) * 8 + lr;
    const int b_kq   = (q & 1) * 16;

    load_stage(0, 0);
    load_stage(1, 1);

    for (int kc = 0; kc < 16; kc++) {
        if (kc < 15) CP_WAIT(1); else CP_WAIT(0);
        __syncthreads();
        if (kc + 2 < 16) load_stage((kc + 2) % 3, kc + 2);

        const uint32_t st = sb + (kc % 3) * QK_STG;
#pragma unroll
        for (int ks = 0; ks < 4; ks++) {
            uint32_t aH[4][4], bH[2][4];
#pragma unroll
            for (int i = 0; i < 4; i++) {
                uint32_t off = (uint32_t)(am_row + i * 16) * 128 + a_kq + ks * 32;
                uint32_t sw = off ^ ((off >> 3) & 0x70);
                LDSM4(aH[i], st + sw);
            }
#pragma unroll
            for (int j2 = 0; j2 < 2; j2++) {
                uint32_t off = (uint32_t)(bn_row + j2 * 16) * 128 + b_kq + ks * 32;
                uint32_t sw = off ^ ((off >> 3) & 0x70);
                LDSM4(bH[j2], st + 16384 + sw);
            }
#pragma unroll
            for (int i = 0; i < 4; i++)
#pragma unroll
                for (int j = 0; j < 4; j++) {
                    const int jj = j >> 1, jo = (j & 1) * 2;
                    MMA16816(C[i][j], aH[i], bH[jj][jo], bH[jj][jo + 1]);
                }
        }
    }

    const int g  = lane >> 2;
    const int tg = lane & 3;
#pragma unroll
    for (int i = 0; i < 4; i++)
#pragma unroll
        for (int j = 0; j < 4; j++) {
            const int col = bn + wn + j * 8 + tg * 2;
            const int r0 = bm + wm + i * 16 + g;
            float b0v = bias[col], b1v = bias[col + 1];
            *(uint32_t*)(Yh + (size_t)r0 * 1024 + col) = pbf2(C[i][j][0] + b0v, C[i][j][1] + b1v);
            *(uint32_t*)(Yh + (size_t)(r0 + 8) * 1024 + col) = pbf2(C[i][j][2] + b0v, C[i][j][3] + b1v);
        }
}

// ================= wide 3-pass GEMM: 512 threads, 128x256 tile, 2-stage =================
#define W_STG 98304
#define W_SMEM (2 * W_STG)

template <int MODE>
__global__ __launch_bounds__(512, 1)
void gemm_wide(const float* __restrict__ bias2, float* __restrict__ Yf)
{
    const uint32_t sb = smem_u32(smem_raw);
    const int tid  = threadIdx.x;
    const int lane = tid & 31;
    const int wid  = tid >> 5;
    const int wm = (wid >> 3) * 64;
    const int wn = (wid & 7) * 32;

    int bm, bn = 0, h = 0, b0 = 0;
    size_t arow0;
    const __nv_bfloat16 *Ahg, *Alg, *Bhg = nullptr, *Blg = nullptr;
    if (MODE == 0) {
        bn = blockIdx.x * 256; bm = blockIdx.y * 128;
        arow0 = (size_t)bm;
        Ahg = g_ah + (size_t)2 * 8 * 1024 * 1024;
        Alg = g_al + (size_t)2 * 8 * 1024 * 1024;
        Bhg = g_bh + (size_t)2 * 1024 * 1024;
        Blg = g_bl + (size_t)2 * 1024 * 1024;
    } else {
        b0 = blockIdx.x * 4; bm = blockIdx.y * 128; h = blockIdx.z;
        arow0 = (size_t)h * 1024 + bm;
        Ahg = g_bth; Alg = g_btl;
    }

    float C[4][4][4];
#pragma unroll
    for (int i = 0; i < 4; i++)
#pragma unroll
        for (int j = 0; j < 4; j++)
#pragma unroll
            for (int r = 0; r < 4; r++) C[i][j][r] = 0.0f;

    auto load_stage = [&](int s, int kc) {
        const uint32_t st = sb + s * W_STG;
        const int koff = kc * 64;
#pragma unroll
        for (int i = 0; i < 4; i++) {
            int idx = tid + i * 512;
            int arr = idx >> 10, r2 = idx & 1023;
            int row = r2 >> 3, c = r2 & 7;
            uint32_t off = row * 128 + c * 16;
            uint32_t sw = off ^ ((off >> 3) & 0x70);
            const __nv_bfloat16* src = arr ? Alg : Ahg;
            CP_ASYNC16(st + arr * 16384 + sw, src + (arow0 + row) * 1024 + koff + c * 8);
        }
#pragma unroll
        for (int i = 0; i < 8; i++) {
            int idx = tid + i * 512;
            if (MODE == 0) {
                int arr = idx >> 11, r2 = idx & 2047;
                int row = r2 >> 3, c = r2 & 7;
                uint32_t off = row * 128 + c * 16;
                uint32_t sw = off ^ ((off >> 3) & 0x70);
                const __nv_bfloat16* src = arr ? Blg : Bhg;
                CP_ASYNC16(st + 32768 + arr * 32768 + sw,
                           src + (size_t)(bn + row) * 1024 + koff + c * 8);
            } else {
                int batch = idx >> 10, rem = idx & 1023;
                int arr = rem >> 9, r2 = rem & 511;
                int row = r2 >> 3, c = r2 & 7;
                uint32_t off = row * 128 + c * 16;
                uint32_t sw = off ^ ((off >> 3) & 0x70);
                const __nv_bfloat16* src = arr ? g_vpl : g_vph;
                CP_ASYNC16(st + 32768 + arr * 32768 + batch * 8192 + sw,
                           src + ((size_t)(b0 + batch) * 1024 + koff + row) * 1024 + h * 64 + c * 8);
            }
        }
        CP_COMMIT();
    };

    const int q  = lane >> 3;
    const int lr = lane & 7;
    const int am_row = wm + (q & 1) * 8 + lr;
    const int a_kq   = (q >> 1) * 16;
    const int bn_row = wn + (q >> 1) * 8 + lr;
    const int b_kq   = (q & 1) * 16;

    load_stage(0, 0);

    for (int kc = 0; kc < 16; kc++) {
        CP_WAIT(0);
        __syncthreads();
        if (kc + 1 < 16) load_stage((kc + 1) & 1, kc + 1);

        const uint32_t st = sb + (kc & 1) * W_STG;
#pragma unroll
        for (int ks = 0; ks < 4; ks++) {
            uint32_t aH[4][4], aL[4][4];
#pragma unroll
            for (int i = 0; i < 4; i++) {
                uint32_t off = (uint32_t)(am_row + i * 16) * 128 + a_kq + ks * 32;
                uint32_t sw = off ^ ((off >> 3) & 0x70);
                LDSM4(aH[i], st + sw);
                LDSM4(aL[i], st + 16384 + sw);
            }
#pragma unroll
            for (int j2 = 0; j2 < 2; j2++) {
                uint32_t bH[4], bL[4];
                if (MODE == 0) {
                    uint32_t off = (uint32_t)(bn_row + j2 * 16) * 128 + b_kq + ks * 32;
                    uint32_t sw = off ^ ((off >> 3) & 0x70);
                    LDSM4(bH, st + 32768 + sw);
                    LDSM4(bL, st + 65536 + sw);
                } else {
                    const int n16 = wn + j2 * 16;
                    const int batch = n16 >> 6, d0 = n16 & 63;
                    uint32_t off = (uint32_t)(ks * 16 + (q & 1) * 8 + lr) * 128 +
                                   (d0 + (q >> 1) * 8) * 2;
                    uint32_t sw = off ^ ((off >> 3) & 0x70);
                    LDSM4T(bH, st + 32768 + batch * 8192 + sw);
                    LDSM4T(bL, st + 65536 + batch * 8192 + sw);
                }
#pragma unroll
                for (int i = 0; i < 4; i++)
#pragma unroll
                    for (int jo = 0; jo < 2; jo++) {
                        float* Cp = C[i][j2 * 2 + jo];
                        MMA16816(Cp, aH[i], bH[jo * 2], bH[jo * 2 + 1]);
                        MMA16816(Cp, aH[i], bL[jo * 2], bL[jo * 2 + 1]);
                        MMA16816(Cp, aL[i], bH[jo * 2], bH[jo * 2 + 1]);
                    }
            }
        }
    }

    const int g  = lane >> 2;
    const int tg = lane & 3;
#pragma unroll
    for (int i = 0; i < 4; i++) {
#pragma unroll
        for (int j = 0; j < 4; j++) {
            const int ncol = wn + j * 8 + tg * 2;
            const int r0 = bm + wm + i * 16 + g;
            const int r1 = r0 + 8;
            if (MODE == 0) {
                const int col = bn + ncol;
                float b0v = bias2[col], b1v = bias2[col + 1];
                float y00 = C[i][j][0] + b0v, y01 = C[i][j][1] + b1v;
                float y10 = C[i][j][2] + b0v, y11 = C[i][j][3] + b1v;
                float l00 = y00 - __bfloat162float(__float2bfloat16_rn(y00));
                float l01 = y01 - __bfloat162float(__float2bfloat16_rn(y01));
                float l10 = y10 - __bfloat162float(__float2bfloat16_rn(y10));
                float l11 = y11 - __bfloat162float(__float2bfloat16_rn(y11));
                *(uint32_t*)(g_vph + (size_t)r0 * 1024 + col) = pbf2(y00, y01);
                *(uint32_t*)(g_vph + (size_t)r1 * 1024 + col) = pbf2(y10, y11);
                *(uint32_t*)(g_vpl + (size_t)r0 * 1024 + col) = pbf2(l00, l01);
                *(uint32_t*)(g_vpl + (size_t)r1 * 1024 + col) = pbf2(l10, l11);
            } else {
                const int bb = b0 + (ncol >> 6);
                const int dd = ncol & 63;
                float* p0 = g_bout + ((size_t)bb * 1024 + r0) * 1024 + h * 64 + dd;
                float* p1 = g_bout + ((size_t)bb * 1024 + r1) * 1024 + h * 64 + dd;
                *(float2*)p0 = make_float2(C[i][j][0], C[i][j][1]);
                *(float2*)p1 = make_float2(C[i][j][2], C[i][j][3]);
            }
        }
    }
}

// ================= flash attention (unchanged) =================
#define FQH 0
#define FST0 16384
#define FKH 0
#define FVH 16384
#define FSRC 32768
#define FSTG 32896
#define FSMEM (16384 + 2 * FSTG)

__global__ __launch_bounds__(256, 2)
void flash_tc(float* __restrict__ out)
{
    char* sm = smem_raw;
    const uint32_t sb = smem_u32(sm);
    const int tid  = threadIdx.x;
    const int lane = tid & 31;
    const int w    = tid >> 5;
    const int q0 = blockIdx.x * 128;
    const int h  = blockIdx.y;
    const int b  = blockIdx.z;
    const int g  = lane >> 2;
    const int tg = lane & 3;
    const int qq = lane >> 3;
    const int lr = lane & 7;

    {
#pragma unroll
        for (int i = 0; i < 4; i++) {
            int idx = tid + i * 256;
            int row = idx >> 3, c = idx & 7;
            uint32_t off = row * 128 + c * 16;
            uint32_t sw = off ^ ((off >> 3) & 0x70);
            size_t gq = ((size_t)b * 1024 + q0 + row) * 1024 + h * 64 + c * 8;
            CP_ASYNC16(sb + FQH + sw, g_qph + gq);
        }
        CP_COMMIT();
    }

    auto load_stage = [&](int s, int kt) {
        const uint32_t st = sb + FST0 + s * FSTG;
        const int k0 = kt * 128;
#pragma unroll
        for (int i = 0; i < 4; i++) {
            int idx = tid + i * 256;
            int row = idx >> 3, c = idx & 7;
            uint32_t off = row * 128 + c * 16;
            uint32_t sw = off ^ ((off >> 3) & 0x70);
            size_t gk = ((size_t)b * 1024 + k0 + row) * 1024 + h * 64 + c * 8;
            CP_ASYNC16(st + FKH + sw, g_kph + gk);
            CP_ASYNC16(st + FVH + sw, g_vph + gk);
        }
        if (tid < 8)
            CP_ASYNC16(st + FSRC + tid * 16, g_src8 + b * 1024 + k0 + tid * 16);
        CP_COMMIT();
    };

    load_stage(0, 0);

    const unsigned char t0m = g_tgt8[b * 1024 + q0 + w * 16 + g];
    const unsigned char t1m = g_tgt8[b * 1024 + q0 + w * 16 + 8 + g];

    float m0r = -3.0e38f, m1r = -3.0e38f, l0r = 0.0f, l1r = 0.0f;
    float O[8][4];
#pragma unroll
    for (int i = 0; i < 8; i++)
#pragma unroll
        for (int r = 0; r < 4; r++) O[i][r] = 0.0f;

    uint32_t aQh[4][4];

    for (int kt = 0; kt < 8; kt++) {
        CP_WAIT(0);
        __syncthreads();
        if (kt + 1 < 8) load_stage((kt + 1) & 1, kt + 1);

        if (kt == 0) {
#pragma unroll
            for (int kc = 0; kc < 4; kc++) {
                uint32_t off = (uint32_t)(w * 16 + (qq & 1) * 8 + lr) * 128 + (qq >> 1) * 16 + kc * 32;
                uint32_t sw = off ^ ((off >> 3) & 0x70);
                LDSM4(aQh[kc], sb + FQH + sw);
            }
        }

        const uint32_t st = sb + FST0 + (kt & 1) * FSTG;
        char* stp = sm + FST0 + (kt & 1) * FSTG;

#pragma unroll
        for (int sub = 0; sub < 2; sub++) {
            const uint32_t kofs = sub * 64 * 128;

            float C[8][4];
#pragma unroll
            for (int i = 0; i < 8; i++)
#pragma unroll
                for (int r = 0; r < 4; r++) C[i][r] = 0.0f;
#pragma unroll
            for (int ks = 0; ks < 4; ks++) {
#pragma unroll
                for (int j2 = 0; j2 < 4; j2++) {
                    uint32_t bh[4];
                    uint32_t off = kofs + (uint32_t)(j2 * 16 + (qq >> 1) * 8 + lr) * 128 +
                                   (qq & 1) * 16 + ks * 32;
                    uint32_t sw = off ^ ((off >> 3) & 0x70);
                    LDSM4(bh, st + FKH + sw);
                    MMA16816(C[j2 * 2],     aQh[ks], bh[0], bh[1]);
                    MMA16816(C[j2 * 2 + 1], aQh[ks], bh[2], bh[3]);
                }
            }

            float mx0 = -3.0e38f, mx1 = -3.0e38f;
#pragma unroll
            for (int nt = 0; nt < 8; nt++) {
                unsigned char s0 = *(unsigned char*)(stp + FSRC + sub * 64 + nt * 8 + tg * 2);
                unsigned char s1 = *(unsigned char*)(stp + FSRC + sub * 64 + nt * 8 + tg * 2 + 1);
                C[nt][0] = (t0m && s0) ? C[nt][0] * SC2L : NEGV;
                C[nt][1] = (t0m && s1) ? C[nt][1] * SC2L : NEGV;
                C[nt][2] = (t1m && s0) ? C[nt][2] * SC2L : NEGV;
                C[nt][3] = (t1m && s1) ? C[nt][3] * SC2L : NEGV;
                mx0 = fmaxf(mx0, fmaxf(C[nt][0], C[nt][1]));
                mx1 = fmaxf(mx1, fmaxf(C[nt][2], C[nt][3]));
            }
            mx0 = fmaxf(mx0, __shfl_xor_sync(0xFFFFFFFF, mx0, 1));
            mx0 = fmaxf(mx0, __shfl_xor_sync(0xFFFFFFFF, mx0, 2));
            mx1 = fmaxf(mx1, __shfl_xor_sync(0xFFFFFFFF, mx1, 1));
            mx1 = fmaxf(mx1, __shfl_xor_sync(0xFFFFFFFF, mx1, 2));

            float mn0 = fmaxf(m0r, mx0), mn1 = fmaxf(m1r, mx1);
            float f0 = ex2f(m0r - mn0), f1 = ex2f(m1r - mn1);
            m0r = mn0; m1r = mn1;

            float s0 = 0.0f, s1 = 0.0f;
#pragma unroll
            for (int nt = 0; nt < 8; nt++) {
                C[nt][0] = ex2f(C[nt][0] - mn0);
                C[nt][1] = ex2f(C[nt][1] - mn0);
                C[nt][2] = ex2f(C[nt][2] - mn1);
                C[nt][3] = ex2f(C[nt][3] - mn1);
                s0 += C[nt][0] + C[nt][1];
                s1 += C[nt][2] + C[nt][3];
            }
            s0 += __shfl_xor_sync(0xFFFFFFFF, s0, 1);
            s0 += __shfl_xor_sync(0xFFFFFFFF, s0, 2);
            s1 += __shfl_xor_sync(0xFFFFFFFF, s1, 1);
            s1 += __shfl_xor_sync(0xFFFFFFFF, s1, 2);
            l0r = l0r * f0 + s0;
            l1r = l1r * f1 + s1;

#pragma unroll
            for (int nt = 0; nt < 8; nt++) {
                O[nt][0] *= f0; O[nt][1] *= f0;
                O[nt][2] *= f1; O[nt][3] *= f1;
            }

            uint32_t aPh[4][4];
#pragma unroll
            for (int kc = 0; kc < 4; kc++) {
                const int n0 = kc * 2, n1 = kc * 2 + 1;
                aPh[kc][0] = pbf2(C[n0][0], C[n0][1]);
                aPh[kc][1] = pbf2(C[n0][2], C[n0][3]);
                aPh[kc][2] = pbf2(C[n1][0], C[n1][1]);
                aPh[kc][3] = pbf2(C[n1][2], C[n1][3]);
            }

#pragma unroll
            for (int kc = 0; kc < 4; kc++) {
#pragma unroll
                for (int nd = 0; nd < 4; nd++) {
                    uint32_t vh[4];
                    uint32_t off = kofs + (uint32_t)(kc * 16 + (qq & 1) * 8 + lr) * 128 +
                                   (nd * 16 + (qq >> 1) * 8) * 2;
                    uint32_t sw = off ^ ((off >> 3) & 0x70);
                    LDSM4T(vh, st + FVH + sw);
                    MMA16816(O[nd * 2],     aPh[kc], vh[0], vh[1]);
                    MMA16816(O[nd * 2 + 1], aPh[kc], vh[2], vh[3]);
                }
            }
        }
    }

    const float il0 = 1.0f / l0r, il1 = 1.0f / l1r;
    const int r0 = q0 + w * 16 + g;
    const int r1 = r0 + 8;
#pragma unroll
    for (int nt = 0; nt < 8; nt++) {
        const int col = h * 64 + nt * 8 + tg * 2;
        float2 w0 = make_float2(O[nt][0] * il0, O[nt][1] * il0);
        float2 w1 = make_float2(O[nt][2] * il1, O[nt][3] * il1);
        *(float2*)(out + ((size_t)b * 1024 + r0) * 1024 + col) = w0;
        *(float2*)(out + ((size_t)b * 1024 + r1) * 1024 + col) = w1;
    }
}

// ================= kernel_launch =================
extern "C" void kernel_launch(void* const* d_in, const int* in_sizes, int n_in,
                              void* d_out, int out_size)
{
    const float* q    = (const float*)d_in[0];
    const float* k    = (const float*)d_in[1];
    const float* v    = (const float*)d_in[2];
    const float* beta = (const float*)d_in[3];
    const unsigned char* srcm = (const unsigned char*)d_in[4];
    const unsigned char* tgtm = (const unsigned char*)d_in[5];
    const float* Wq = (const float*)d_in[6];
    const float* bq = (const float*)d_in[7];
    const float* Wk = (const float*)d_in[8];
    const float* bk = (const float*)d_in[9];
    const float* Wv = (const float*)d_in[10];
    const float* bv = (const float*)d_in[11];
    float* out = (float*)d_out;

    cudaFuncSetAttribute(gemm_qk,      cudaFuncAttributeMaxDynamicSharedMemorySize, QK_SMEM);
    cudaFuncSetAttribute(gemm_wide<0>, cudaFuncAttributeMaxDynamicSharedMemorySize, W_SMEM);
    cudaFuncSetAttribute(gemm_wide<1>, cudaFuncAttributeMaxDynamicSharedMemorySize, W_SMEM);
    cudaFuncSetAttribute(flash_tc,     cudaFuncAttributeMaxDynamicSharedMemorySize, FSMEM);

    cudaStream_t s1;
    cudaStreamCreateWithFlags(&s1, cudaStreamNonBlocking);
    cudaEvent_t evCV, evBC, evV, evB;
    cudaEventCreateWithFlags(&evCV, cudaEventDisableTiming);
    cudaEventCreateWithFlags(&evBC, cudaEventDisableTiming);
    cudaEventCreateWithFlags(&evV,  cudaEventDisableTiming);
    cudaEventCreateWithFlags(&evB,  cudaEventDisableTiming);

    // main: V-slice conversion first so V-proj can start ASAP
    conv_part<0><<<2304, 256>>>((const float4*)v, (const float4*)Wv, nullptr, nullptr);
    cudaEventRecord(evCV, 0);
    cudaStreamWaitEvent(s1, evCV, 0);

    // side: V projection as early as possible, then beta GEMM
    gemm_wide<0><<<dim3(4, 64), 512, W_SMEM, s1>>>(bv, nullptr);
    cudaEventRecord(evV, s1);

    // main: remaining conversions (run concurrent with V-proj), masks, qk GEMM
    conv_part<1><<<4608, 256>>>((const float4*)q, (const float4*)k,
                                (const float4*)Wq, (const float4*)Wk);
    conv_part<2><<<4096, 256>>>((const float4*)beta, nullptr, nullptr, nullptr);
    cudaEventRecord(evBC, 0);
    mask_convert2<<<2, 1024>>>(srcm, tgtm, Bb * TK);
    gemm_qk<<<dim3(16, 64), 256, QK_SMEM>>>(bq, bk);

    // side: beta GEMM (needs conv-beta + V-proj)
    cudaStreamWaitEvent(s1, evBC, 0);
    gemm_wide<1><<<dim3(2, 8, 16), 512, W_SMEM, s1>>>(nullptr, nullptr);
    cudaEventRecord(evB, s1);

    // main: flash (needs V), then add (needs beta)
    cudaStreamWaitEvent(0, evV, 0);
    flash_tc<<<dim3(TQ / 128, NH, Bb), 256, FSMEM>>>(out);
    cudaStreamWaitEvent(0, evB, 0);
    add_out<<<2048, 256>>>((float4*)out);
}

// round 16
// speedup vs baseline: 1.4858x; 1.0033x over previous
#include <cuda_runtime.h>
#include <cuda_bf16.h>
#include <math.h>
#include <stdint.h>

// Problem constants
#define Bb    8
#define TQ    1024
#define TK    1024
#define DIMX  1024
#define NH    16
#define HD    64
#define SCALE 0.03125f
#define NEGV  -1.0e9f
#define MROWS (Bb * TQ)
#define SC2L  (0.03125f * 1.44269504088896f)

// ================= PTX helpers =================
__device__ __forceinline__ uint32_t smem_u32(const void* p) {
    uint32_t a;
    asm("{ .reg .u64 t; cvta.to.shared.u64 t, %1; cvt.u32.u64 %0, t; }"
        : "=r"(a) : "l"(p));
    return a;
}
#define CP_ASYNC16(dst_u32, src_ptr) \
    asm volatile("cp.async.cg.shared.global [%0], [%1], 16;" \
        :: "r"(dst_u32), "l"(src_ptr))
#define CP_COMMIT() asm volatile("cp.async.commit_group;" ::: "memory")
#define CP_WAIT(n)  asm volatile("cp.async.wait_group %0;" :: "n"(n) : "memory")

#define LDSM4(r, addr) \
    asm volatile("ldmatrix.sync.aligned.m8n8.x4.shared.b16 {%0,%1,%2,%3}, [%4];" \
        : "=r"((r)[0]), "=r"((r)[1]), "=r"((r)[2]), "=r"((r)[3]) : "r"(addr))
#define LDSM4T(r, addr) \
    asm volatile("ldmatrix.sync.aligned.m8n8.x4.trans.shared.b16 {%0,%1,%2,%3}, [%4];" \
        : "=r"((r)[0]), "=r"((r)[1]), "=r"((r)[2]), "=r"((r)[3]) : "r"(addr))

#define MMA16816(c, a, b0, b1) \
    asm volatile("mma.sync.aligned.m16n8k16.row.col.f32.bf16.bf16.f32 " \
        "{%0,%1,%2,%3}, {%4,%5,%6,%7}, {%8,%9}, {%0,%1,%2,%3};" \
        : "+f"((c)[0]), "+f"((c)[1]), "+f"((c)[2]), "+f"((c)[3]) \
        : "r"((a)[0]), "r"((a)[1]), "r"((a)[2]), "r"((a)[3]), "r"(b0), "r"(b1))

__device__ __forceinline__ uint32_t pbf2(float lo, float hi) {
    uint32_t d;
    asm("cvt.rn.bf16x2.f32 %0, %1, %2;" : "=r"(d) : "f"(hi), "f"(lo));
    return d;
}
__device__ __forceinline__ float ex2f(float x) {
    float y;
    asm("ex2.approx.ftz.f32 %0, %1;" : "=f"(y) : "f"(x));
    return y;
}

// ================= scratch =================
__device__ __align__(16) __nv_bfloat16 g_qph[(size_t)MROWS * DIMX];
__device__ __align__(16) __nv_bfloat16 g_kph[(size_t)MROWS * DIMX];
__device__ __align__(16) __nv_bfloat16 g_vph[(size_t)MROWS * DIMX];
__device__ __align__(16) __nv_bfloat16 g_vpl[(size_t)MROWS * DIMX];
__device__ __align__(16) __nv_bfloat16 g_ah[(size_t)24 * 1024 * 1024];   // acts q|k|v
__device__ __align__(16) __nv_bfloat16 g_al[(size_t)24 * 1024 * 1024];
__device__ __align__(16) __nv_bfloat16 g_bth[(size_t)16 * 1024 * 1024];  // beta hi
__device__ __align__(16) __nv_bfloat16 g_btl[(size_t)16 * 1024 * 1024];  // beta lo
__device__ __align__(16) __nv_bfloat16 g_bh[(size_t)3 * 1024 * 1024];
__device__ __align__(16) __nv_bfloat16 g_bl[(size_t)3 * 1024 * 1024];
__device__ __align__(16) float g_bout[(size_t)MROWS * DIMX];             // beta@V result
__device__ unsigned char g_src8[Bb * TK];
__device__ unsigned char g_tgt8[Bb * TQ];

// ================= mask canonicalization =================
__global__ void mask_convert2(const unsigned char* __restrict__ raw0,
                              const unsigned char* __restrict__ raw1, int n)
{
    const unsigned char* raw = blockIdx.x ? raw1 : raw0;
    unsigned char* out = blockIdx.x ? g_tgt8 : g_src8;
    __shared__ int has3F, oddNZ;
    if (threadIdx.x == 0) { has3F = 0; oddNZ = 0; }
    __syncthreads();
    int lf = 0, lo = 0;
    for (int i = threadIdx.x; i < n; i += blockDim.x) {
        unsigned char c = raw[i];
        if (c == 0x3F) lf = 1;
        if ((i & 3) && c) lo = 1;
    }
    if (lf) atomicOr(&has3F, 1);
    if (lo) atomicOr(&oddNZ, 1);
    __syncthreads();
    int mode = has3F ? 2 : (oddNZ ? 0 : 1);
    for (int i = threadIdx.x; i < n; i += blockDim.x) {
        unsigned char v;
        if (mode == 2)      v = (((const float*)raw)[i] != 0.0f) ? 1 : 0;
        else if (mode == 1) v = (((const int*)raw)[i]   != 0)    ? 1 : 0;
        else                v = (raw[i] != 0) ? 1 : 0;
        out[i] = v;
    }
}

// ================= fp32 -> bf16 conversion slices (MLP=4) =================
__device__ __forceinline__ void conv_block(const float4* __restrict__ src,
                                           __nv_bfloat16* __restrict__ hi,
                                           __nv_bfloat16* __restrict__ lo,
                                           bool full, size_t base)
{
    const int tid = threadIdx.x;
    float4 f[4];
#pragma unroll
    for (int u = 0; u < 4; u++) f[u] = src[base + tid + u * 256];
    if (full) {
#pragma unroll
        for (int u = 0; u < 4; u++) {
            size_t i = base + tid + u * 256;
            __nv_bfloat16 h0 = __float2bfloat16_rn(f[u].x);
            __nv_bfloat16 h1 = __float2bfloat16_rn(f[u].y);
            __nv_bfloat16 h2 = __float2bfloat16_rn(f[u].z);
            __nv_bfloat16 h3 = __float2bfloat16_rn(f[u].w);
            __nv_bfloat16 l0 = __float2bfloat16_rn(f[u].x - __bfloat162float(h0));
            __nv_bfloat16 l1 = __float2bfloat16_rn(f[u].y - __bfloat162float(h1));
            __nv_bfloat16 l2 = __float2bfloat16_rn(f[u].z - __bfloat162float(h2));
            __nv_bfloat16 l3 = __float2bfloat16_rn(f[u].w - __bfloat162float(h3));
            __nv_bfloat162* Hp = (__nv_bfloat162*)(hi + 4 * i);
            __nv_bfloat162* Lp = (__nv_bfloat162*)(lo + 4 * i);
            Hp[0] = __halves2bfloat162(h0, h1);
            Hp[1] = __halves2bfloat162(h2, h3);
            Lp[0] = __halves2bfloat162(l0, l1);
            Lp[1] = __halves2bfloat162(l2, l3);
        }
    } else {
#pragma unroll
        for (int u = 0; u < 4; u++) {
            size_t i = base + tid + u * 256;
            __nv_bfloat162* Hp = (__nv_bfloat162*)(hi + 4 * i);
            Hp[0] = __halves2bfloat162(__float2bfloat16_rn(f[u].x), __float2bfloat16_rn(f[u].y));
            Hp[1] = __halves2bfloat162(__float2bfloat16_rn(f[u].z), __float2bfloat16_rn(f[u].w));
        }
    }
}

// MODE 0: v + Wv (2304 blocks).  MODE 1: q,k + Wq,Wk (4608 blocks).  MODE 2: beta (4096).
template <int MODE>
__global__ __launch_bounds__(256)
void conv_part(const float4* __restrict__ p0, const float4* __restrict__ p1,
               const float4* __restrict__ p2, const float4* __restrict__ p3)
{
    const size_t ACT = (size_t)8 * 1024 * 1024;
    const size_t WSEG = (size_t)1024 * 1024;
    int bid = blockIdx.x;
    if (MODE == 0) {
        if (bid < 2048)
            conv_block(p0, g_ah + 2 * ACT, g_al + 2 * ACT, true, (size_t)bid * 1024);
        else
            conv_block(p1, g_bh + 2 * WSEG, g_bl + 2 * WSEG, true, (size_t)(bid - 2048) * 1024);
    } else if (MODE == 1) {
        if (bid < 2048)
            conv_block(p0, g_ah, nullptr, false, (size_t)bid * 1024);
        else if (bid < 4096)
            conv_block(p1, g_ah + ACT, nullptr, false, (size_t)(bid - 2048) * 1024);
        else if (bid < 4352)
            conv_block(p2, g_bh, nullptr, false, (size_t)(bid - 4096) * 1024);
        else
            conv_block(p3, g_bh + WSEG, nullptr, false, (size_t)(bid - 4352) * 1024);
    } else {
        conv_block(p0, g_bth, g_btl, true, (size_t)bid * 1024);
    }
}

// ================= out += g_bout =================
__global__ __launch_bounds__(256)
void add_out(float4* __restrict__ out)
{
    size_t i = (size_t)blockIdx.x * 1024 + threadIdx.x;
    const float4* bo = (const float4*)g_bout;
    float4 a[4], b[4];
#pragma unroll
    for (int u = 0; u < 4; u++) { a[u] = out[i + u * 256]; b[u] = bo[i + u * 256]; }
#pragma unroll
    for (int u = 0; u < 4; u++) {
        a[u].x += b[u].x; a[u].y += b[u].y; a[u].z += b[u].z; a[u].w += b[u].w;
        out[i + u * 256] = a[u];
    }
}

extern __shared__ char smem_raw[];

// ================= gemm_qk: 1-pass bf16, BK=64, 2 CTAs/SM =================
#define QK_STG 32768
#define QK_SMEM (3 * QK_STG)

__global__ __launch_bounds__(256, 2)
void gemm_qk(const float* __restrict__ bias0, const float* __restrict__ bias1)
{
    const uint32_t sb = smem_u32(smem_raw);
    const int tid  = threadIdx.x;
    const int lane = tid & 31;
    const int wid  = tid >> 5;
    const int wm = (wid >> 2) * 64;
    const int wn = (wid & 3) * 32;

    const int seg = blockIdx.x >> 3;
    const int bn  = (blockIdx.x & 7) * 128;
    const int bm  = blockIdx.y * 128;
    const __nv_bfloat16* Ahg = g_ah + (size_t)seg * 8 * 1024 * 1024;
    const __nv_bfloat16* Bhg = g_bh + (size_t)seg * 1024 * 1024;
    const float* bias = seg ? bias1 : bias0;
    __nv_bfloat16* Yh = seg ? g_kph : g_qph;

    float C[4][4][4];
#pragma unroll
    for (int i = 0; i < 4; i++)
#pragma unroll
        for (int j = 0; j < 4; j++)
#pragma unroll
            for (int r = 0; r < 4; r++) C[i][j][r] = 0.0f;

    auto load_stage = [&](int s, int kc) {
        const uint32_t st = sb + s * QK_STG;
        const int koff = kc * 64;
#pragma unroll
        for (int i = 0; i < 4; i++) {
            int idx = tid + i * 256;
            int row = idx >> 3, c = idx & 7;
            uint32_t off = row * 128 + c * 16;
            uint32_t sw = off ^ ((off >> 3) & 0x70);
            CP_ASYNC16(st + sw,         Ahg + (size_t)(bm + row) * 1024 + koff + c * 8);
            CP_ASYNC16(st + 16384 + sw, Bhg + (size_t)(bn + row) * 1024 + koff + c * 8);
        }
        CP_COMMIT();
    };

    const int q  = lane >> 3;
    const int lr = lane & 7;
    const int am_row = wm + (q & 1) * 8 + lr;
    const int a_kq   = (q >> 1) * 16;
    const int bn_row = wn + (q >> 1) * 8 + lr;
    const int b_kq   = (q & 1) * 16;

    load_stage(0, 0);
    load_stage(1, 1);

    for (int kc = 0; kc < 16; kc++) {
        if (kc < 15) CP_WAIT(1); else CP_WAIT(0);
        __syncthreads();
        if (kc + 2 < 16) load_stage((kc + 2) % 3, kc + 2);

        const uint32_t st = sb + (kc % 3) * QK_STG;
#pragma unroll
        for (int ks = 0; ks < 4; ks++) {
            uint32_t aH[4][4], bH[2][4];
#pragma unroll
            for (int i = 0; i < 4; i++) {
                uint32_t off = (uint32_t)(am_row + i * 16) * 128 + a_kq + ks * 32;
                uint32_t sw = off ^ ((off >> 3) & 0x70);
                LDSM4(aH[i], st + sw);
            }
#pragma unroll
            for (int j2 = 0; j2 < 2; j2++) {
                uint32_t off = (uint32_t)(bn_row + j2 * 16) * 128 + b_kq + ks * 32;
                uint32_t sw = off ^ ((off >> 3) & 0x70);
                LDSM4(bH[j2], st + 16384 + sw);
            }
#pragma unroll
            for (int i = 0; i < 4; i++)
#pragma unroll
                for (int j = 0; j < 4; j++) {
                    const int jj = j >> 1, jo = (j & 1) * 2;
                    MMA16816(C[i][j], aH[i], bH[jj][jo], bH[jj][jo + 1]);
                }
        }
    }

    const int g  = lane >> 2;
    const int tg = lane & 3;
#pragma unroll
    for (int i = 0; i < 4; i++)
#pragma unroll
        for (int j = 0; j < 4; j++) {
            const int col = bn + wn + j * 8 + tg * 2;
            const int r0 = bm + wm + i * 16 + g;
            float b0v = bias[col], b1v = bias[col + 1];
            *(uint32_t*)(Yh + (size_t)r0 * 1024 + col) = pbf2(C[i][j][0] + b0v, C[i][j][1] + b1v);
            *(uint32_t*)(Yh + (size_t)(r0 + 8) * 1024 + col) = pbf2(C[i][j][2] + b0v, C[i][j][3] + b1v);
        }
}

// ================= wide 3-pass GEMM: 512 threads, 128x256 tile, 2-stage =================
// MODE 0: V projection (hi/lo out), yoff = bm block offset for batch-split.
// MODE 1: beta@V -> g_bout.
#define W_STG 98304
#define W_SMEM (2 * W_STG)

template <int MODE>
__global__ __launch_bounds__(512, 1)
void gemm_wide(const float* __restrict__ bias2, float* __restrict__ Yf, int yoff)
{
    const uint32_t sb = smem_u32(smem_raw);
    const int tid  = threadIdx.x;
    const int lane = tid & 31;
    const int wid  = tid >> 5;
    const int wm = (wid >> 3) * 64;
    const int wn = (wid & 7) * 32;

    int bm, bn = 0, h = 0, b0 = 0;
    size_t arow0;
    const __nv_bfloat16 *Ahg, *Alg, *Bhg = nullptr, *Blg = nullptr;
    if (MODE == 0) {
        bn = blockIdx.x * 256; bm = (blockIdx.y + yoff) * 128;
        arow0 = (size_t)bm;
        Ahg = g_ah + (size_t)2 * 8 * 1024 * 1024;
        Alg = g_al + (size_t)2 * 8 * 1024 * 1024;
        Bhg = g_bh + (size_t)2 * 1024 * 1024;
        Blg = g_bl + (size_t)2 * 1024 * 1024;
    } else {
        b0 = blockIdx.x * 4; bm = blockIdx.y * 128; h = blockIdx.z;
        arow0 = (size_t)h * 1024 + bm;
        Ahg = g_bth; Alg = g_btl;
    }

    float C[4][4][4];
#pragma unroll
    for (int i = 0; i < 4; i++)
#pragma unroll
        for (int j = 0; j < 4; j++)
#pragma unroll
            for (int r = 0; r < 4; r++) C[i][j][r] = 0.0f;

    auto load_stage = [&](int s, int kc) {
        const uint32_t st = sb + s * W_STG;
        const int koff = kc * 64;
#pragma unroll
        for (int i = 0; i < 4; i++) {
            int idx = tid + i * 512;
            int arr = idx >> 10, r2 = idx & 1023;
            int row = r2 >> 3, c = r2 & 7;
            uint32_t off = row * 128 + c * 16;
            uint32_t sw = off ^ ((off >> 3) & 0x70);
            const __nv_bfloat16* src = arr ? Alg : Ahg;
            CP_ASYNC16(st + arr * 16384 + sw, src + (arow0 + row) * 1024 + koff + c * 8);
        }
#pragma unroll
        for (int i = 0; i < 8; i++) {
            int idx = tid + i * 512;
            if (MODE == 0) {
                int arr = idx >> 11, r2 = idx & 2047;
                int row = r2 >> 3, c = r2 & 7;
                uint32_t off = row * 128 + c * 16;
                uint32_t sw = off ^ ((off >> 3) & 0x70);
                const __nv_bfloat16* src = arr ? Blg : Bhg;
                CP_ASYNC16(st + 32768 + arr * 32768 + sw,
                           src + (size_t)(bn + row) * 1024 + koff + c * 8);
            } else {
                int batch = idx >> 10, rem = idx & 1023;
                int arr = rem >> 9, r2 = rem & 511;
                int row = r2 >> 3, c = r2 & 7;
                uint32_t off = row * 128 + c * 16;
                uint32_t sw = off ^ ((off >> 3) & 0x70);
                const __nv_bfloat16* src = arr ? g_vpl : g_vph;
                CP_ASYNC16(st + 32768 + arr * 32768 + batch * 8192 + sw,
                           src + ((size_t)(b0 + batch) * 1024 + koff + row) * 1024 + h * 64 + c * 8);
            }
        }
        CP_COMMIT();
    };

    const int q  = lane >> 3;
    const int lr = lane & 7;
    const int am_row = wm + (q & 1) * 8 + lr;
    const int a_kq   = (q >> 1) * 16;
    const int bn_row = wn + (q >> 1) * 8 + lr;
    const int b_kq   = (q & 1) * 16;

    load_stage(0, 0);

    for (int kc = 0; kc < 16; kc++) {
        CP_WAIT(0);
        __syncthreads();
        if (kc + 1 < 16) load_stage((kc + 1) & 1, kc + 1);

        const uint32_t st = sb + (kc & 1) * W_STG;
#pragma unroll
        for (int ks = 0; ks < 4; ks++) {
            uint32_t aH[4][4], aL[4][4];
#pragma unroll
            for (int i = 0; i < 4; i++) {
                uint32_t off = (uint32_t)(am_row + i * 16) * 128 + a_kq + ks * 32;
                uint32_t sw = off ^ ((off >> 3) & 0x70);
                LDSM4(aH[i], st + sw);
                LDSM4(aL[i], st + 16384 + sw);
            }
#pragma unroll
            for (int j2 = 0; j2 < 2; j2++) {
                uint32_t bH[4], bL[4];
                if (MODE == 0) {
                    uint32_t off = (uint32_t)(bn_row + j2 * 16) * 128 + b_kq + ks * 32;
                    uint32_t sw = off ^ ((off >> 3) & 0x70);
                    LDSM4(bH, st + 32768 + sw);
                    LDSM4(bL, st + 65536 + sw);
                } else {
                    const int n16 = wn + j2 * 16;
                    const int batch = n16 >> 6, d0 = n16 & 63;
                    uint32_t off = (uint32_t)(ks * 16 + (q & 1) * 8 + lr) * 128 +
                                   (d0 + (q >> 1) * 8) * 2;
                    uint32_t sw = off ^ ((off >> 3) & 0x70);
                    LDSM4T(bH, st + 32768 + batch * 8192 + sw);
                    LDSM4T(bL, st + 65536 + batch * 8192 + sw);
                }
#pragma unroll
                for (int i = 0; i < 4; i++)
#pragma unroll
                    for (int jo = 0; jo < 2; jo++) {
                        float* Cp = C[i][j2 * 2 + jo];
                        MMA16816(Cp, aH[i], bH[jo * 2], bH[jo * 2 + 1]);
                        MMA16816(Cp, aH[i], bL[jo * 2], bL[jo * 2 + 1]);
                        MMA16816(Cp, aL[i], bH[jo * 2], bH[jo * 2 + 1]);
                    }
            }
        }
    }

    const int g  = lane >> 2;
    const int tg = lane & 3;
#pragma unroll
    for (int i = 0; i < 4; i++) {
#pragma unroll
        for (int j = 0; j < 4; j++) {
            const int ncol = wn + j * 8 + tg * 2;
            const int r0 = bm + wm + i * 16 + g;
            const int r1 = r0 + 8;
            if (MODE == 0) {
                const int col = bn + ncol;
                float b0v = bias2[col], b1v = bias2[col + 1];
                float y00 = C[i][j][0] + b0v, y01 = C[i][j][1] + b1v;
                float y10 = C[i][j][2] + b0v, y11 = C[i][j][3] + b1v;
                float l00 = y00 - __bfloat162float(__float2bfloat16_rn(y00));
                float l01 = y01 - __bfloat162float(__float2bfloat16_rn(y01));
                float l10 = y10 - __bfloat162float(__float2bfloat16_rn(y10));
                float l11 = y11 - __bfloat162float(__float2bfloat16_rn(y11));
                *(uint32_t*)(g_vph + (size_t)r0 * 1024 + col) = pbf2(y00, y01);
                *(uint32_t*)(g_vph + (size_t)r1 * 1024 + col) = pbf2(y10, y11);
                *(uint32_t*)(g_vpl + (size_t)r0 * 1024 + col) = pbf2(l00, l01);
                *(uint32_t*)(g_vpl + (size_t)r1 * 1024 + col) = pbf2(l10, l11);
            } else {
                const int bb = b0 + (ncol >> 6);
                const int dd = ncol & 63;
                float* p0 = g_bout + ((size_t)bb * 1024 + r0) * 1024 + h * 64 + dd;
                float* p1 = g_bout + ((size_t)bb * 1024 + r1) * 1024 + h * 64 + dd;
                *(float2*)p0 = make_float2(C[i][j][0], C[i][j][1]);
                *(float2*)p1 = make_float2(C[i][j][2], C[i][j][3]);
            }
        }
    }
}

// ================= flash attention (batch-split via zoff) =================
#define FQH 0
#define FST0 16384
#define FKH 0
#define FVH 16384
#define FSRC 32768
#define FSTG 32896
#define FSMEM (16384 + 2 * FSTG)

__global__ __launch_bounds__(256, 2)
void flash_tc(float* __restrict__ out, int zoff)
{
    char* sm = smem_raw;
    const uint32_t sb = smem_u32(sm);
    const int tid  = threadIdx.x;
    const int lane = tid & 31;
    const int w    = tid >> 5;
    const int q0 = blockIdx.x * 128;
    const int h  = blockIdx.y;
    const int b  = blockIdx.z + zoff;
    const int g  = lane >> 2;
    const int tg = lane & 3;
    const int qq = lane >> 3;
    const int lr = lane & 7;

    {
#pragma unroll
        for (int i = 0; i < 4; i++) {
            int idx = tid + i * 256;
            int row = idx >> 3, c = idx & 7;
            uint32_t off = row * 128 + c * 16;
            uint32_t sw = off ^ ((off >> 3) & 0x70);
            size_t gq = ((size_t)b * 1024 + q0 + row) * 1024 + h * 64 + c * 8;
            CP_ASYNC16(sb + FQH + sw, g_qph + gq);
        }
        CP_COMMIT();
    }

    auto load_stage = [&](int s, int kt) {
        const uint32_t st = sb + FST0 + s * FSTG;
        const int k0 = kt * 128;
#pragma unroll
        for (int i = 0; i < 4; i++) {
            int idx = tid + i * 256;
            int row = idx >> 3, c = idx & 7;
            uint32_t off = row * 128 + c * 16;
            uint32_t sw = off ^ ((off >> 3) & 0x70);
            size_t gk = ((size_t)b * 1024 + k0 + row) * 1024 + h * 64 + c * 8;
            CP_ASYNC16(st + FKH + sw, g_kph + gk);
            CP_ASYNC16(st + FVH + sw, g_vph + gk);
        }
        if (tid < 8)
            CP_ASYNC16(st + FSRC + tid * 16, g_src8 + b * 1024 + k0 + tid * 16);
        CP_COMMIT();
    };

    load_stage(0, 0);

    const unsigned char t0m = g_tgt8[b * 1024 + q0 + w * 16 + g];
    const unsigned char t1m = g_tgt8[b * 1024 + q0 + w * 16 + 8 + g];

    float m0r = -3.0e38f, m1r = -3.0e38f, l0r = 0.0f, l1r = 0.0f;
    float O[8][4];
#pragma unroll
    for (int i = 0; i < 8; i++)
#pragma unroll
        for (int r = 0; r < 4; r++) O[i][r] = 0.0f;

    uint32_t aQh[4][4];

    for (int kt = 0; kt < 8; kt++) {
        CP_WAIT(0);
        __syncthreads();
        if (kt + 1 < 8) load_stage((kt + 1) & 1, kt + 1);

        if (kt == 0) {
#pragma unroll
            for (int kc = 0; kc < 4; kc++) {
                uint32_t off = (uint32_t)(w * 16 + (qq & 1) * 8 + lr) * 128 + (qq >> 1) * 16 + kc * 32;
                uint32_t sw = off ^ ((off >> 3) & 0x70);
                LDSM4(aQh[kc], sb + FQH + sw);
            }
        }

        const uint32_t st = sb + FST0 + (kt & 1) * FSTG;
        char* stp = sm + FST0 + (kt & 1) * FSTG;

#pragma unroll
        for (int sub = 0; sub < 2; sub++) {
            const uint32_t kofs = sub * 64 * 128;

            float C[8][4];
#pragma unroll
            for (int i = 0; i < 8; i++)
#pragma unroll
                for (int r = 0; r < 4; r++) C[i][r] = 0.0f;
#pragma unroll
            for (int ks = 0; ks < 4; ks++) {
#pragma unroll
                for (int j2 = 0; j2 < 4; j2++) {
                    uint32_t bh[4];
                    uint32_t off = kofs + (uint32_t)(j2 * 16 + (qq >> 1) * 8 + lr) * 128 +
                                   (qq & 1) * 16 + ks * 32;
                    uint32_t sw = off ^ ((off >> 3) & 0x70);
                    LDSM4(bh, st + FKH + sw);
                    MMA16816(C[j2 * 2],     aQh[ks], bh[0], bh[1]);
                    MMA16816(C[j2 * 2 + 1], aQh[ks], bh[2], bh[3]);
                }
            }

            float mx0 = -3.0e38f, mx1 = -3.0e38f;
#pragma unroll
            for (int nt = 0; nt < 8; nt++) {
                unsigned char s0 = *(unsigned char*)(stp + FSRC + sub * 64 + nt * 8 + tg * 2);
                unsigned char s1 = *(unsigned char*)(stp + FSRC + sub * 64 + nt * 8 + tg * 2 + 1);
                C[nt][0] = (t0m && s0) ? C[nt][0] * SC2L : NEGV;
                C[nt][1] = (t0m && s1) ? C[nt][1] * SC2L : NEGV;
                C[nt][2] = (t1m && s0) ? C[nt][2] * SC2L : NEGV;
                C[nt][3] = (t1m && s1) ? C[nt][3] * SC2L : NEGV;
                mx0 = fmaxf(mx0, fmaxf(C[nt][0], C[nt][1]));
                mx1 = fmaxf(mx1, fmaxf(C[nt][2], C[nt][3]));
            }
            mx0 = fmaxf(mx0, __shfl_xor_sync(0xFFFFFFFF, mx0, 1));
            mx0 = fmaxf(mx0, __shfl_xor_sync(0xFFFFFFFF, mx0, 2));
            mx1 = fmaxf(mx1, __shfl_xor_sync(0xFFFFFFFF, mx1, 1));
            mx1 = fmaxf(mx1, __shfl_xor_sync(0xFFFFFFFF, mx1, 2));

            float mn0 = fmaxf(m0r, mx0), mn1 = fmaxf(m1r, mx1);
            float f0 = ex2f(m0r - mn0), f1 = ex2f(m1r - mn1);
            m0r = mn0; m1r = mn1;

            float s0 = 0.0f, s1 = 0.0f;
#pragma unroll
            for (int nt = 0; nt < 8; nt++) {
                C[nt][0] = ex2f(C[nt][0] - mn0);
                C[nt][1] = ex2f(C[nt][1] - mn0);
                C[nt][2] = ex2f(C[nt][2] - mn1);
                C[nt][3] = ex2f(C[nt][3] - mn1);
                s0 += C[nt][0] + C[nt][1];
                s1 += C[nt][2] + C[nt][3];
            }
            s0 += __shfl_xor_sync(0xFFFFFFFF, s0, 1);
            s0 += __shfl_xor_sync(0xFFFFFFFF, s0, 2);
            s1 += __shfl_xor_sync(0xFFFFFFFF, s1, 1);
            s1 += __shfl_xor_sync(0xFFFFFFFF, s1, 2);
            l0r = l0r * f0 + s0;
            l1r = l1r * f1 + s1;

#pragma unroll
            for (int nt = 0; nt < 8; nt++) {
                O[nt][0] *= f0; O[nt][1] *= f0;
                O[nt][2] *= f1; O[nt][3] *= f1;
            }

            uint32_t aPh[4][4];
#pragma unroll
            for (int kc = 0; kc < 4; kc++) {
                const int n0 = kc * 2, n1 = kc * 2 + 1;
                aPh[kc][0] = pbf2(C[n0][0], C[n0][1]);
                aPh[kc][1] = pbf2(C[n0][2], C[n0][3]);
                aPh[kc][2] = pbf2(C[n1][0], C[n1][1]);
                aPh[kc][3] = pbf2(C[n1][2], C[n1][3]);
            }

#pragma unroll
            for (int kc = 0; kc < 4; kc++) {
#pragma unroll
                for (int nd = 0; nd < 4; nd++) {
                    uint32_t vh[4];
                    uint32_t off = kofs + (uint32_t)(kc * 16 + (qq & 1) * 8 + lr) * 128 +
                                   (nd * 16 + (qq >> 1) * 8) * 2;
                    uint32_t sw = off ^ ((off >> 3) & 0x70);
                    LDSM4T(vh, st + FVH + sw);
                    MMA16816(O[nd * 2],     aPh[kc], vh[0], vh[1]);
                    MMA16816(O[nd * 2 + 1], aPh[kc], vh[2], vh[3]);
                }
            }
        }
    }

    const float il0 = 1.0f / l0r, il1 = 1.0f / l1r;
    const int r0 = q0 + w * 16 + g;
    const int r1 = r0 + 8;
#pragma unroll
    for (int nt = 0; nt < 8; nt++) {
        const int col = h * 64 + nt * 8 + tg * 2;
        float2 w0 = make_float2(O[nt][0] * il0, O[nt][1] * il0);
        float2 w1 = make_float2(O[nt][2] * il1, O[nt][3] * il1);
        *(float2*)(out + ((size_t)b * 1024 + r0) * 1024 + col) = w0;
        *(float2*)(out + ((size_t)b * 1024 + r1) * 1024 + col) = w1;
    }
}

// ================= kernel_launch =================
extern "C" void kernel_launch(void* const* d_in, const int* in_sizes, int n_in,
                              void* d_out, int out_size)
{
    const float* q    = (const float*)d_in[0];
    const float* k    = (const float*)d_in[1];
    const float* v    = (const float*)d_in[2];
    const float* beta = (const float*)d_in[3];
    const unsigned char* srcm = (const unsigned char*)d_in[4];
    const unsigned char* tgtm = (const unsigned char*)d_in[5];
    const float* Wq = (const float*)d_in[6];
    const float* bq = (const float*)d_in[7];
    const float* Wk = (const float*)d_in[8];
    const float* bk = (const float*)d_in[9];
    const float* Wv = (const float*)d_in[10];
    const float* bv = (const float*)d_in[11];
    float* out = (float*)d_out;

    cudaFuncSetAttribute(gemm_qk,      cudaFuncAttributeMaxDynamicSharedMemorySize, QK_SMEM);
    cudaFuncSetAttribute(gemm_wide<0>, cudaFuncAttributeMaxDynamicSharedMemorySize, W_SMEM);
    cudaFuncSetAttribute(gemm_wide<1>, cudaFuncAttributeMaxDynamicSharedMemorySize, W_SMEM);
    cudaFuncSetAttribute(flash_tc,     cudaFuncAttributeMaxDynamicSharedMemorySize, FSMEM);

    cudaStream_t s1;
    cudaStreamCreateWithFlags(&s1, cudaStreamNonBlocking);
    cudaEvent_t evCV, evBC, evVA, evVB, evB;
    cudaEventCreateWithFlags(&evCV, cudaEventDisableTiming);
    cudaEventCreateWithFlags(&evBC, cudaEventDisableTiming);
    cudaEventCreateWithFlags(&evVA, cudaEventDisableTiming);
    cudaEventCreateWithFlags(&evVB, cudaEventDisableTiming);
    cudaEventCreateWithFlags(&evB,  cudaEventDisableTiming);

    // main: V-slice conversion first so V-proj can start ASAP
    conv_part<0><<<2304, 256>>>((const float4*)v, (const float4*)Wv, nullptr, nullptr);
    cudaEventRecord(evCV, 0);
    cudaStreamWaitEvent(s1, evCV, 0);

    // side: V projection in two batch halves (rows 0..4095 then 4096..8191)
    gemm_wide<0><<<dim3(4, 32), 512, W_SMEM, s1>>>(bv, nullptr, 0);
    cudaEventRecord(evVA, s1);
    gemm_wide<0><<<dim3(4, 32), 512, W_SMEM, s1>>>(bv, nullptr, 32);
    cudaEventRecord(evVB, s1);

    // main: q/k conversions (concurrent with V-proj), masks, qk GEMM
    conv_part<1><<<4608, 256>>>((const float4*)q, (const float4*)k,
                                (const float4*)Wq, (const float4*)Wk);
    mask_convert2<<<2, 1024>>>(srcm, tgtm, Bb * TK);
    gemm_qk<<<dim3(16, 64), 256, QK_SMEM>>>(bq, bk);
    // beta conversion after qk: overlaps the V-proj tail, done before beta-GEMM needs it
    conv_part<2><<<4096, 256>>>((const float4*)beta, nullptr, nullptr, nullptr);
    cudaEventRecord(evBC, 0);

    // side: beta GEMM (needs conv-beta + full V-proj)
    cudaStreamWaitEvent(s1, evBC, 0);
    gemm_wide<1><<<dim3(2, 8, 16), 512, W_SMEM, s1>>>(nullptr, nullptr, 0);
    cudaEventRecord(evB, s1);

    // main: flash in two batch halves, then add (needs beta)
    cudaStreamWaitEvent(0, evVA, 0);
    flash_tc<<<dim3(TQ / 128, NH, 4), 256, FSMEM>>>(out, 0);
    cudaStreamWaitEvent(0, evVB, 0);
    flash_tc<<<dim3(TQ / 128, NH, 4), 256, FSMEM>>>(out, 4);
    cudaStreamWaitEvent(0, evB, 0);
    add_out<<<2048, 256>>>((float4*)out);
}

// round 17
// speedup vs baseline: 1.4859x; 1.0001x over previous
#include <cuda_runtime.h>
#include <cuda_bf16.h>
#include <math.h>
#include <stdint.h>

// Problem constants
#define Bb    8
#define TQ    1024
#define TK    1024
#define DIMX  1024
#define NH    16
#define HD    64
#define SCALE 0.03125f
#define NEGV  -1.0e9f
#define MROWS (Bb * TQ)
#define SC2L  (0.03125f * 1.44269504088896f)

// ================= PTX helpers =================
__device__ __forceinline__ uint32_t smem_u32(const void* p) {
    uint32_t a;
    asm("{ .reg .u64 t; cvta.to.shared.u64 t, %1; cvt.u32.u64 %0, t; }"
        : "=r"(a) : "l"(p));
    return a;
}
#define CP_ASYNC16(dst_u32, src_ptr) \
    asm volatile("cp.async.cg.shared.global [%0], [%1], 16;" \
        :: "r"(dst_u32), "l"(src_ptr))
#define CP_COMMIT() asm volatile("cp.async.commit_group;" ::: "memory")
#define CP_WAIT(n)  asm volatile("cp.async.wait_group %0;" :: "n"(n) : "memory")

#define LDSM4(r, addr) \
    asm volatile("ldmatrix.sync.aligned.m8n8.x4.shared.b16 {%0,%1,%2,%3}, [%4];" \
        : "=r"((r)[0]), "=r"((r)[1]), "=r"((r)[2]), "=r"((r)[3]) : "r"(addr))
#define LDSM4T(r, addr) \
    asm volatile("ldmatrix.sync.aligned.m8n8.x4.trans.shared.b16 {%0,%1,%2,%3}, [%4];" \
        : "=r"((r)[0]), "=r"((r)[1]), "=r"((r)[2]), "=r"((r)[3]) : "r"(addr))

#define MMA16816(c, a, b0, b1) \
    asm volatile("mma.sync.aligned.m16n8k16.row.col.f32.bf16.bf16.f32 " \
        "{%0,%1,%2,%3}, {%4,%5,%6,%7}, {%8,%9}, {%0,%1,%2,%3};" \
        : "+f"((c)[0]), "+f"((c)[1]), "+f"((c)[2]), "+f"((c)[3]) \
        : "r"((a)[0]), "r"((a)[1]), "r"((a)[2]), "r"((a)[3]), "r"(b0), "r"(b1))

__device__ __forceinline__ uint32_t pbf2(float lo, float hi) {
    uint32_t d;
    asm("cvt.rn.bf16x2.f32 %0, %1, %2;" : "=r"(d) : "f"(hi), "f"(lo));
    return d;
}
__device__ __forceinline__ float ex2f(float x) {
    float y;
    asm("ex2.approx.ftz.f32 %0, %1;" : "=f"(y) : "f"(x));
    return y;
}

// ================= scratch =================
__device__ __align__(16) __nv_bfloat16 g_qph[(size_t)MROWS * DIMX];
__device__ __align__(16) __nv_bfloat16 g_kph[(size_t)MROWS * DIMX];
__device__ __align__(16) __nv_bfloat16 g_vph[(size_t)MROWS * DIMX];
__device__ __align__(16) __nv_bfloat16 g_vpl[(size_t)MROWS * DIMX];
__device__ __align__(16) __nv_bfloat16 g_ah[(size_t)24 * 1024 * 1024];   // acts q|k|v
__device__ __align__(16) __nv_bfloat16 g_al[(size_t)24 * 1024 * 1024];
__device__ __align__(16) __nv_bfloat16 g_bth[(size_t)16 * 1024 * 1024];  // beta hi
__device__ __align__(16) __nv_bfloat16 g_btl[(size_t)16 * 1024 * 1024];  // beta lo
__device__ __align__(16) __nv_bfloat16 g_bh[(size_t)3 * 1024 * 1024];
__device__ __align__(16) __nv_bfloat16 g_bl[(size_t)3 * 1024 * 1024];
__device__ __align__(16) float g_bout[(size_t)MROWS * DIMX];             // beta@V result
__device__ unsigned char g_src8[Bb * TK];
__device__ unsigned char g_tgt8[Bb * TQ];

// ================= mask canonicalization =================
__global__ void mask_convert2(const unsigned char* __restrict__ raw0,
                              const unsigned char* __restrict__ raw1, int n)
{
    const unsigned char* raw = blockIdx.x ? raw1 : raw0;
    unsigned char* out = blockIdx.x ? g_tgt8 : g_src8;
    __shared__ int has3F, oddNZ;
    if (threadIdx.x == 0) { has3F = 0; oddNZ = 0; }
    __syncthreads();
    int lf = 0, lo = 0;
    for (int i = threadIdx.x; i < n; i += blockDim.x) {
        unsigned char c = raw[i];
        if (c == 0x3F) lf = 1;
        if ((i & 3) && c) lo = 1;
    }
    if (lf) atomicOr(&has3F, 1);
    if (lo) atomicOr(&oddNZ, 1);
    __syncthreads();
    int mode = has3F ? 2 : (oddNZ ? 0 : 1);
    for (int i = threadIdx.x; i < n; i += blockDim.x) {
        unsigned char v;
        if (mode == 2)      v = (((const float*)raw)[i] != 0.0f) ? 1 : 0;
        else if (mode == 1) v = (((const int*)raw)[i]   != 0)    ? 1 : 0;
        else                v = (raw[i] != 0) ? 1 : 0;
        out[i] = v;
    }
}

// ================= fp32 -> bf16 conversion slices (MLP=4) =================
__device__ __forceinline__ void conv_block(const float4* __restrict__ src,
                                           __nv_bfloat16* __restrict__ hi,
                                           __nv_bfloat16* __restrict__ lo,
                                           bool full, size_t base)
{
    const int tid = threadIdx.x;
    float4 f[4];
#pragma unroll
    for (int u = 0; u < 4; u++) f[u] = src[base + tid + u * 256];
    if (full) {
#pragma unroll
        for (int u = 0; u < 4; u++) {
            size_t i = base + tid + u * 256;
            __nv_bfloat16 h0 = __float2bfloat16_rn(f[u].x);
            __nv_bfloat16 h1 = __float2bfloat16_rn(f[u].y);
            __nv_bfloat16 h2 = __float2bfloat16_rn(f[u].z);
            __nv_bfloat16 h3 = __float2bfloat16_rn(f[u].w);
            __nv_bfloat16 l0 = __float2bfloat16_rn(f[u].x - __bfloat162float(h0));
            __nv_bfloat16 l1 = __float2bfloat16_rn(f[u].y - __bfloat162float(h1));
            __nv_bfloat16 l2 = __float2bfloat16_rn(f[u].z - __bfloat162float(h2));
            __nv_bfloat16 l3 = __float2bfloat16_rn(f[u].w - __bfloat162float(h3));
            __nv_bfloat162* Hp = (__nv_bfloat162*)(hi + 4 * i);
            __nv_bfloat162* Lp = (__nv_bfloat162*)(lo + 4 * i);
            Hp[0] = __halves2bfloat162(h0, h1);
            Hp[1] = __halves2bfloat162(h2, h3);
            Lp[0] = __halves2bfloat162(l0, l1);
            Lp[1] = __halves2bfloat162(l2, l3);
        }
    } else {
#pragma unroll
        for (int u = 0; u < 4; u++) {
            size_t i = base + tid + u * 256;
            __nv_bfloat162* Hp = (__nv_bfloat162*)(hi + 4 * i);
            Hp[0] = __halves2bfloat162(__float2bfloat16_rn(f[u].x), __float2bfloat16_rn(f[u].y));
            Hp[1] = __halves2bfloat162(__float2bfloat16_rn(f[u].z), __float2bfloat16_rn(f[u].w));
        }
    }
}

// MODE 0: v + Wv (2304 blocks).  MODE 1: q,k + Wq,Wk (4608 blocks).  MODE 2: beta (4096).
template <int MODE>
__global__ __launch_bounds__(256)
void conv_part(const float4* __restrict__ p0, const float4* __restrict__ p1,
               const float4* __restrict__ p2, const float4* __restrict__ p3)
{
    const size_t ACT = (size_t)8 * 1024 * 1024;
    const size_t WSEG = (size_t)1024 * 1024;
    int bid = blockIdx.x;
    if (MODE == 0) {
        if (bid < 2048)
            conv_block(p0, g_ah + 2 * ACT, g_al + 2 * ACT, true, (size_t)bid * 1024);
        else
            conv_block(p1, g_bh + 2 * WSEG, g_bl + 2 * WSEG, true, (size_t)(bid - 2048) * 1024);
    } else if (MODE == 1) {
        if (bid < 2048)
            conv_block(p0, g_ah, nullptr, false, (size_t)bid * 1024);
        else if (bid < 4096)
            conv_block(p1, g_ah + ACT, nullptr, false, (size_t)(bid - 2048) * 1024);
        else if (bid < 4352)
            conv_block(p2, g_bh, nullptr, false, (size_t)(bid - 4096) * 1024);
        else
            conv_block(p3, g_bh + WSEG, nullptr, false, (size_t)(bid - 4352) * 1024);
    } else {
        conv_block(p0, g_bth, g_btl, true, (size_t)bid * 1024);
    }
}

// ================= out += g_bout =================
__global__ __launch_bounds__(256)
void add_out(float4* __restrict__ out)
{
    size_t i = (size_t)blockIdx.x * 1024 + threadIdx.x;
    const float4* bo = (const float4*)g_bout;
    float4 a[4], b[4];
#pragma unroll
    for (int u = 0; u < 4; u++) { a[u] = out[i + u * 256]; b[u] = bo[i + u * 256]; }
#pragma unroll
    for (int u = 0; u < 4; u++) {
        a[u].x += b[u].x; a[u].y += b[u].y; a[u].z += b[u].z; a[u].w += b[u].w;
        out[i + u * 256] = a[u];
    }
}

extern __shared__ char smem_raw[];

// ================= gemm_qk: 1-pass bf16, BK=64, 2 CTAs/SM =================
#define QK_STG 32768
#define QK_SMEM (3 * QK_STG)

__global__ __launch_bounds__(256, 2)
void gemm_qk(const float* __restrict__ bias0, const float* __restrict__ bias1)
{
    const uint32_t sb = smem_u32(smem_raw);
    const int tid  = threadIdx.x;
    const int lane = tid & 31;
    const int wid  = tid >> 5;
    const int wm = (wid >> 2) * 64;
    const int wn = (wid & 3) * 32;

    const int seg = blockIdx.x >> 3;
    const int bn  = (blockIdx.x & 7) * 128;
    const int bm  = blockIdx.y * 128;
    const __nv_bfloat16* Ahg = g_ah + (size_t)seg * 8 * 1024 * 1024;
    const __nv_bfloat16* Bhg = g_bh + (size_t)seg * 1024 * 1024;
    const float* bias = seg ? bias1 : bias0;
    __nv_bfloat16* Yh = seg ? g_kph : g_qph;

    float C[4][4][4];
#pragma unroll
    for (int i = 0; i < 4; i++)
#pragma unroll
        for (int j = 0; j < 4; j++)
#pragma unroll
            for (int r = 0; r < 4; r++) C[i][j][r] = 0.0f;

    auto load_stage = [&](int s, int kc) {
        const uint32_t st = sb + s * QK_STG;
        const int koff = kc * 64;
#pragma unroll
        for (int i = 0; i < 4; i++) {
            int idx = tid + i * 256;
            int row = idx >> 3, c = idx & 7;
            uint32_t off = row * 128 + c * 16;
            uint32_t sw = off ^ ((off >> 3) & 0x70);
            CP_ASYNC16(st + sw,         Ahg + (size_t)(bm + row) * 1024 + koff + c * 8);
            CP_ASYNC16(st + 16384 + sw, Bhg + (size_t)(bn + row) * 1024 + koff + c * 8);
        }
        CP_COMMIT();
    };

    const int q  = lane >> 3;
    const int lr = lane & 7;
    const int am_row = wm + (q & 1) * 8 + lr;
    const int a_kq   = (q >> 1) * 16;
    const int bn_row = wn + (q >> 1) * 8 + lr;
    const int b_kq   = (q & 1) * 16;

    load_stage(0, 0);
    load_stage(1, 1);

    for (int kc = 0; kc < 16; kc++) {
        if (kc < 15) CP_WAIT(1); else CP_WAIT(0);
        __syncthreads();
        if (kc + 2 < 16) load_stage((kc + 2) % 3, kc + 2);

        const uint32_t st = sb + (kc % 3) * QK_STG;
#pragma unroll
        for (int ks = 0; ks < 4; ks++) {
            uint32_t aH[4][4], bH[2][4];
#pragma unroll
            for (int i = 0; i < 4; i++) {
                uint32_t off = (uint32_t)(am_row + i * 16) * 128 + a_kq + ks * 32;
                uint32_t sw = off ^ ((off >> 3) & 0x70);
                LDSM4(aH[i], st + sw);
            }
#pragma unroll
            for (int j2 = 0; j2 < 2; j2++) {
                uint32_t off = (uint32_t)(bn_row + j2 * 16) * 128 + b_kq + ks * 32;
                uint32_t sw = off ^ ((off >> 3) & 0x70);
                LDSM4(bH[j2], st + 16384 + sw);
            }
#pragma unroll
            for (int i = 0; i < 4; i++)
#pragma unroll
                for (int j = 0; j < 4; j++) {
                    const int jj = j >> 1, jo = (j & 1) * 2;
                    MMA16816(C[i][j], aH[i], bH[jj][jo], bH[jj][jo + 1]);
                }
        }
    }

    const int g  = lane >> 2;
    const int tg = lane & 3;
#pragma unroll
    for (int i = 0; i < 4; i++)
#pragma unroll
        for (int j = 0; j < 4; j++) {
            const int col = bn + wn + j * 8 + tg * 2;
            const int r0 = bm + wm + i * 16 + g;
            float b0v = bias[col], b1v = bias[col + 1];
            *(uint32_t*)(Yh + (size_t)r0 * 1024 + col) = pbf2(C[i][j][0] + b0v, C[i][j][1] + b1v);
            *(uint32_t*)(Yh + (size_t)(r0 + 8) * 1024 + col) = pbf2(C[i][j][2] + b0v, C[i][j][3] + b1v);
        }
}

// ================= wide 3-pass GEMM: 512 threads, 128x256 tile, 2-stage =================
// MODE 0: V projection (hi/lo out), yoff = bm block offset for batch-split.
// MODE 1: beta@V -> g_bout.
#define W_STG 98304
#define W_SMEM (2 * W_STG)

template <int MODE>
__global__ __launch_bounds__(512, 1)
void gemm_wide(const float* __restrict__ bias2, float* __restrict__ Yf, int yoff)
{
    const uint32_t sb = smem_u32(smem_raw);
    const int tid  = threadIdx.x;
    const int lane = tid & 31;
    const int wid  = tid >> 5;
    const int wm = (wid >> 3) * 64;
    const int wn = (wid & 7) * 32;

    int bm, bn = 0, h = 0, b0 = 0;
    size_t arow0;
    const __nv_bfloat16 *Ahg, *Alg, *Bhg = nullptr, *Blg = nullptr;
    if (MODE == 0) {
        bn = blockIdx.x * 256; bm = (blockIdx.y + yoff) * 128;
        arow0 = (size_t)bm;
        Ahg = g_ah + (size_t)2 * 8 * 1024 * 1024;
        Alg = g_al + (size_t)2 * 8 * 1024 * 1024;
        Bhg = g_bh + (size_t)2 * 1024 * 1024;
        Blg = g_bl + (size_t)2 * 1024 * 1024;
    } else {
        b0 = blockIdx.x * 4; bm = blockIdx.y * 128; h = blockIdx.z;
        arow0 = (size_t)h * 1024 + bm;
        Ahg = g_bth; Alg = g_btl;
    }

    float C[4][4][4];
#pragma unroll
    for (int i = 0; i < 4; i++)
#pragma unroll
        for (int j = 0; j < 4; j++)
#pragma unroll
            for (int r = 0; r < 4; r++) C[i][j][r] = 0.0f;

    auto load_stage = [&](int s, int kc) {
        const uint32_t st = sb + s * W_STG;
        const int koff = kc * 64;
#pragma unroll
        for (int i = 0; i < 4; i++) {
            int idx = tid + i * 512;
            int arr = idx >> 10, r2 = idx & 1023;
            int row = r2 >> 3, c = r2 & 7;
            uint32_t off = row * 128 + c * 16;
            uint32_t sw = off ^ ((off >> 3) & 0x70);
            const __nv_bfloat16* src = arr ? Alg : Ahg;
            CP_ASYNC16(st + arr * 16384 + sw, src + (arow0 + row) * 1024 + koff + c * 8);
        }
#pragma unroll
        for (int i = 0; i < 8; i++) {
            int idx = tid + i * 512;
            if (MODE == 0) {
                int arr = idx >> 11, r2 = idx & 2047;
                int row = r2 >> 3, c = r2 & 7;
                uint32_t off = row * 128 + c * 16;
                uint32_t sw = off ^ ((off >> 3) & 0x70);
                const __nv_bfloat16* src = arr ? Blg : Bhg;
                CP_ASYNC16(st + 32768 + arr * 32768 + sw,
                           src + (size_t)(bn + row) * 1024 + koff + c * 8);
            } else {
                int batch = idx >> 10, rem = idx & 1023;
                int arr = rem >> 9, r2 = rem & 511;
                int row = r2 >> 3, c = r2 & 7;
                uint32_t off = row * 128 + c * 16;
                uint32_t sw = off ^ ((off >> 3) & 0x70);
                const __nv_bfloat16* src = arr ? g_vpl : g_vph;
                CP_ASYNC16(st + 32768 + arr * 32768 + batch * 8192 + sw,
                           src + ((size_t)(b0 + batch) * 1024 + koff + row) * 1024 + h * 64 + c * 8);
            }
        }
        CP_COMMIT();
    };

    const int q  = lane >> 3;
    const int lr = lane & 7;
    const int am_row = wm + (q & 1) * 8 + lr;
    const int a_kq   = (q >> 1) * 16;
    const int bn_row = wn + (q >> 1) * 8 + lr;
    const int b_kq   = (q & 1) * 16;

    load_stage(0, 0);

    for (int kc = 0; kc < 16; kc++) {
        CP_WAIT(0);
        __syncthreads();
        if (kc + 1 < 16) load_stage((kc + 1) & 1, kc + 1);

        const uint32_t st = sb + (kc & 1) * W_STG;
#pragma unroll
        for (int ks = 0; ks < 4; ks++) {
            uint32_t aH[4][4], aL[4][4];
#pragma unroll
            for (int i = 0; i < 4; i++) {
                uint32_t off = (uint32_t)(am_row + i * 16) * 128 + a_kq + ks * 32;
                uint32_t sw = off ^ ((off >> 3) & 0x70);
                LDSM4(aH[i], st + sw);
                LDSM4(aL[i], st + 16384 + sw);
            }
#pragma unroll
            for (int j2 = 0; j2 < 2; j2++) {
                uint32_t bH[4], bL[4];
                if (MODE == 0) {
                    uint32_t off = (uint32_t)(bn_row + j2 * 16) * 128 + b_kq + ks * 32;
                    uint32_t sw = off ^ ((off >> 3) & 0x70);
                    LDSM4(bH, st + 32768 + sw);
                    LDSM4(bL, st + 65536 + sw);
                } else {
                    const int n16 = wn + j2 * 16;
                    const int batch = n16 >> 6, d0 = n16 & 63;
                    uint32_t off = (uint32_t)(ks * 16 + (q & 1) * 8 + lr) * 128 +
                                   (d0 + (q >> 1) * 8) * 2;
                    uint32_t sw = off ^ ((off >> 3) & 0x70);
                    LDSM4T(bH, st + 32768 + batch * 8192 + sw);
                    LDSM4T(bL, st + 65536 + batch * 8192 + sw);
                }
#pragma unroll
                for (int i = 0; i < 4; i++)
#pragma unroll
                    for (int jo = 0; jo < 2; jo++) {
                        float* Cp = C[i][j2 * 2 + jo];
                        MMA16816(Cp, aH[i], bH[jo * 2], bH[jo * 2 + 1]);
                        MMA16816(Cp, aH[i], bL[jo * 2], bL[jo * 2 + 1]);
                        MMA16816(Cp, aL[i], bH[jo * 2], bH[jo * 2 + 1]);
                    }
            }
        }
    }

    const int g  = lane >> 2;
    const int tg = lane & 3;
#pragma unroll
    for (int i = 0; i < 4; i++) {
#pragma unroll
        for (int j = 0; j < 4; j++) {
            const int ncol = wn + j * 8 + tg * 2;
            const int r0 = bm + wm + i * 16 + g;
            const int r1 = r0 + 8;
            if (MODE == 0) {
                const int col = bn + ncol;
                float b0v = bias2[col], b1v = bias2[col + 1];
                float y00 = C[i][j][0] + b0v, y01 = C[i][j][1] + b1v;
                float y10 = C[i][j][2] + b0v, y11 = C[i][j][3] + b1v;
                float l00 = y00 - __bfloat162float(__float2bfloat16_rn(y00));
                float l01 = y01 - __bfloat162float(__float2bfloat16_rn(y01));
                float l10 = y10 - __bfloat162float(__float2bfloat16_rn(y10));
                float l11 = y11 - __bfloat162float(__float2bfloat16_rn(y11));
                *(uint32_t*)(g_vph + (size_t)r0 * 1024 + col) = pbf2(y00, y01);
                *(uint32_t*)(g_vph + (size_t)r1 * 1024 + col) = pbf2(y10, y11);
                *(uint32_t*)(g_vpl + (size_t)r0 * 1024 + col) = pbf2(l00, l01);
                *(uint32_t*)(g_vpl + (size_t)r1 * 1024 + col) = pbf2(l10, l11);
            } else {
                const int bb = b0 + (ncol >> 6);
                const int dd = ncol & 63;
                float* p0 = g_bout + ((size_t)bb * 1024 + r0) * 1024 + h * 64 + dd;
                float* p1 = g_bout + ((size_t)bb * 1024 + r1) * 1024 + h * 64 + dd;
                *(float2*)p0 = make_float2(C[i][j][0], C[i][j][1]);
                *(float2*)p1 = make_float2(C[i][j][2], C[i][j][3]);
            }
        }
    }
}

// ================= flash attention (batch-split via zoff) =================
#define FQH 0
#define FST0 16384
#define FKH 0
#define FVH 16384
#define FSRC 32768
#define FSTG 32896
#define FSMEM (16384 + 2 * FSTG)

__global__ __launch_bounds__(256, 2)
void flash_tc(float* __restrict__ out, int zoff)
{
    char* sm = smem_raw;
    const uint32_t sb = smem_u32(sm);
    const int tid  = threadIdx.x;
    const int lane = tid & 31;
    const int w    = tid >> 5;
    const int q0 = blockIdx.x * 128;
    const int h  = blockIdx.y;
    const int b  = blockIdx.z + zoff;
    const int g  = lane >> 2;
    const int tg = lane & 3;
    const int qq = lane >> 3;
    const int lr = lane & 7;

    {
#pragma unroll
        for (int i = 0; i < 4; i++) {
            int idx = tid + i * 256;
            int row = idx >> 3, c = idx & 7;
            uint32_t off = row * 128 + c * 16;
            uint32_t sw = off ^ ((off >> 3) & 0x70);
            size_t gq = ((size_t)b * 1024 + q0 + row) * 1024 + h * 64 + c * 8;
            CP_ASYNC16(sb + FQH + sw, g_qph + gq);
        }
        CP_COMMIT();
    }

    auto load_stage = [&](int s, int kt) {
        const uint32_t st = sb + FST0 + s * FSTG;
        const int k0 = kt * 128;
#pragma unroll
        for (int i = 0; i < 4; i++) {
            int idx = tid + i * 256;
            int row = idx >> 3, c = idx & 7;
            uint32_t off = row * 128 + c * 16;
            uint32_t sw = off ^ ((off >> 3) & 0x70);
            size_t gk = ((size_t)b * 1024 + k0 + row) * 1024 + h * 64 + c * 8;
            CP_ASYNC16(st + FKH + sw, g_kph + gk);
            CP_ASYNC16(st + FVH + sw, g_vph + gk);
        }
        if (tid < 8)
            CP_ASYNC16(st + FSRC + tid * 16, g_src8 + b * 1024 + k0 + tid * 16);
        CP_COMMIT();
    };

    load_stage(0, 0);

    const unsigned char t0m = g_tgt8[b * 1024 + q0 + w * 16 + g];
    const unsigned char t1m = g_tgt8[b * 1024 + q0 + w * 16 + 8 + g];

    float m0r = -3.0e38f, m1r = -3.0e38f, l0r = 0.0f, l1r = 0.0f;
    float O[8][4];
#pragma unroll
    for (int i = 0; i < 8; i++)
#pragma unroll
        for (int r = 0; r < 4; r++) O[i][r] = 0.0f;

    uint32_t aQh[4][4];

    for (int kt = 0; kt < 8; kt++) {
        CP_WAIT(0);
        __syncthreads();
        if (kt + 1 < 8) load_stage((kt + 1) & 1, kt + 1);

        if (kt == 0) {
#pragma unroll
            for (int kc = 0; kc < 4; kc++) {
                uint32_t off = (uint32_t)(w * 16 + (qq & 1) * 8 + lr) * 128 + (qq >> 1) * 16 + kc * 32;
                uint32_t sw = off ^ ((off >> 3) & 0x70);
                LDSM4(aQh[kc], sb + FQH + sw);
            }
        }

        const uint32_t st = sb + FST0 + (kt & 1) * FSTG;
        char* stp = sm + FST0 + (kt & 1) * FSTG;

#pragma unroll
        for (int sub = 0; sub < 2; sub++) {
            const uint32_t kofs = sub * 64 * 128;

            float C[8][4];
#pragma unroll
            for (int i = 0; i < 8; i++)
#pragma unroll
                for (int r = 0; r < 4; r++) C[i][r] = 0.0f;
#pragma unroll
            for (int ks = 0; ks < 4; ks++) {
#pragma unroll
                for (int j2 = 0; j2 < 4; j2++) {
                    uint32_t bh[4];
                    uint32_t off = kofs + (uint32_t)(j2 * 16 + (qq >> 1) * 8 + lr) * 128 +
                                   (qq & 1) * 16 + ks * 32;
                    uint32_t sw = off ^ ((off >> 3) & 0x70);
                    LDSM4(bh, st + FKH + sw);
                    MMA16816(C[j2 * 2],     aQh[ks], bh[0], bh[1]);
                    MMA16816(C[j2 * 2 + 1], aQh[ks], bh[2], bh[3]);
                }
            }

            float mx0 = -3.0e38f, mx1 = -3.0e38f;
#pragma unroll
            for (int nt = 0; nt < 8; nt++) {
                unsigned char s0 = *(unsigned char*)(stp + FSRC + sub * 64 + nt * 8 + tg * 2);
                unsigned char s1 = *(unsigned char*)(stp + FSRC + sub * 64 + nt * 8 + tg * 2 + 1);
                C[nt][0] = (t0m && s0) ? C[nt][0] * SC2L : NEGV;
                C[nt][1] = (t0m && s1) ? C[nt][1] * SC2L : NEGV;
                C[nt][2] = (t1m && s0) ? C[nt][2] * SC2L : NEGV;
                C[nt][3] = (t1m && s1) ? C[nt][3] * SC2L : NEGV;
                mx0 = fmaxf(mx0, fmaxf(C[nt][0], C[nt][1]));
                mx1 = fmaxf(mx1, fmaxf(C[nt][2], C[nt][3]));
            }
            mx0 = fmaxf(mx0, __shfl_xor_sync(0xFFFFFFFF, mx0, 1));
            mx0 = fmaxf(mx0, __shfl_xor_sync(0xFFFFFFFF, mx0, 2));
            mx1 = fmaxf(mx1, __shfl_xor_sync(0xFFFFFFFF, mx1, 1));
            mx1 = fmaxf(mx1, __shfl_xor_sync(0xFFFFFFFF, mx1, 2));

            float mn0 = fmaxf(m0r, mx0), mn1 = fmaxf(m1r, mx1);
            float f0 = ex2f(m0r - mn0), f1 = ex2f(m1r - mn1);
            m0r = mn0; m1r = mn1;

            float s0 = 0.0f, s1 = 0.0f;
#pragma unroll
            for (int nt = 0; nt < 8; nt++) {
                C[nt][0] = ex2f(C[nt][0] - mn0);
                C[nt][1] = ex2f(C[nt][1] - mn0);
                C[nt][2] = ex2f(C[nt][2] - mn1);
                C[nt][3] = ex2f(C[nt][3] - mn1);
                s0 += C[nt][0] + C[nt][1];
                s1 += C[nt][2] + C[nt][3];
            }
            s0 += __shfl_xor_sync(0xFFFFFFFF, s0, 1);
            s0 += __shfl_xor_sync(0xFFFFFFFF, s0, 2);
            s1 += __shfl_xor_sync(0xFFFFFFFF, s1, 1);
            s1 += __shfl_xor_sync(0xFFFFFFFF, s1, 2);
            l0r = l0r * f0 + s0;
            l1r = l1r * f1 + s1;

#pragma unroll
            for (int nt = 0; nt < 8; nt++) {
                O[nt][0] *= f0; O[nt][1] *= f0;
                O[nt][2] *= f1; O[nt][3] *= f1;
            }

            uint32_t aPh[4][4];
#pragma unroll
            for (int kc = 0; kc < 4; kc++) {
                const int n0 = kc * 2, n1 = kc * 2 + 1;
                aPh[kc][0] = pbf2(C[n0][0], C[n0][1]);
                aPh[kc][1] = pbf2(C[n0][2], C[n0][3]);
                aPh[kc][2] = pbf2(C[n1][0], C[n1][1]);
                aPh[kc][3] = pbf2(C[n1][2], C[n1][3]);
            }

#pragma unroll
            for (int kc = 0; kc < 4; kc++) {
#pragma unroll
                for (int nd = 0; nd < 4; nd++) {
                    uint32_t vh[4];
                    uint32_t off = kofs + (uint32_t)(kc * 16 + (qq & 1) * 8 + lr) * 128 +
                                   (nd * 16 + (qq >> 1) * 8) * 2;
                    uint32_t sw = off ^ ((off >> 3) & 0x70);
                    LDSM4T(vh, st + FVH + sw);
                    MMA16816(O[nd * 2],     aPh[kc], vh[0], vh[1]);
                    MMA16816(O[nd * 2 + 1], aPh[kc], vh[2], vh[3]);
                }
            }
        }
    }

    const float il0 = 1.0f / l0r, il1 = 1.0f / l1r;
    const int r0 = q0 + w * 16 + g;
    const int r1 = r0 + 8;
#pragma unroll
    for (int nt = 0; nt < 8; nt++) {
        const int col = h * 64 + nt * 8 + tg * 2;
        float2 w0 = make_float2(O[nt][0] * il0, O[nt][1] * il0);
        float2 w1 = make_float2(O[nt][2] * il1, O[nt][3] * il1);
        *(float2*)(out + ((size_t)b * 1024 + r0) * 1024 + col) = w0;
        *(float2*)(out + ((size_t)b * 1024 + r1) * 1024 + col) = w1;
    }
}

// ================= kernel_launch =================
extern "C" void kernel_launch(void* const* d_in, const int* in_sizes, int n_in,
                              void* d_out, int out_size)
{
    const float* q    = (const float*)d_in[0];
    const float* k    = (const float*)d_in[1];
    const float* v    = (const float*)d_in[2];
    const float* beta = (const float*)d_in[3];
    const unsigned char* srcm = (const unsigned char*)d_in[4];
    const unsigned char* tgtm = (const unsigned char*)d_in[5];
    const float* Wq = (const float*)d_in[6];
    const float* bq = (const float*)d_in[7];
    const float* Wk = (const float*)d_in[8];
    const float* bk = (const float*)d_in[9];
    const float* Wv = (const float*)d_in[10];
    const float* bv = (const float*)d_in[11];
    float* out = (float*)d_out;

    cudaFuncSetAttribute(gemm_qk,      cudaFuncAttributeMaxDynamicSharedMemorySize, QK_SMEM);
    cudaFuncSetAttribute(gemm_wide<0>, cudaFuncAttributeMaxDynamicSharedMemorySize, W_SMEM);
    cudaFuncSetAttribute(gemm_wide<1>, cudaFuncAttributeMaxDynamicSharedMemorySize, W_SMEM);
    cudaFuncSetAttribute(flash_tc,     cudaFuncAttributeMaxDynamicSharedMemorySize, FSMEM);

    cudaStream_t s1;
    cudaStreamCreateWithFlags(&s1, cudaStreamNonBlocking);
    cudaEvent_t evCV, evBC, evVA, evVB, evB;
    cudaEventCreateWithFlags(&evCV, cudaEventDisableTiming);
    cudaEventCreateWithFlags(&evBC, cudaEventDisableTiming);
    cudaEventCreateWithFlags(&evVA, cudaEventDisableTiming);
    cudaEventCreateWithFlags(&evVB, cudaEventDisableTiming);
    cudaEventCreateWithFlags(&evB,  cudaEventDisableTiming);

    // main: V-slice conversion first so V-proj can start ASAP
    conv_part<0><<<2304, 256>>>((const float4*)v, (const float4*)Wv, nullptr, nullptr);
    cudaEventRecord(evCV, 0);
    cudaStreamWaitEvent(s1, evCV, 0);

    // side: V projection in two batch halves (rows 0..4095 then 4096..8191)
    gemm_wide<0><<<dim3(4, 32), 512, W_SMEM, s1>>>(bv, nullptr, 0);
    cudaEventRecord(evVA, s1);
    gemm_wide<0><<<dim3(4, 32), 512, W_SMEM, s1>>>(bv, nullptr, 32);
    cudaEventRecord(evVB, s1);

    // main: q/k conversions (concurrent with V-proj), masks, qk GEMM
    conv_part<1><<<4608, 256>>>((const float4*)q, (const float4*)k,
                                (const float4*)Wq, (const float4*)Wk);
    mask_convert2<<<2, 1024>>>(srcm, tgtm, Bb * TK);
    gemm_qk<<<dim3(16, 64), 256, QK_SMEM>>>(bq, bk);
    // beta conversion after qk: overlaps the V-proj tail, done before beta-GEMM needs it
    conv_part<2><<<4096, 256>>>((const float4*)beta, nullptr, nullptr, nullptr);
    cudaEventRecord(evBC, 0);

    // side: beta GEMM (needs conv-beta + full V-proj)
    cudaStreamWaitEvent(s1, evBC, 0);
    gemm_wide<1><<<dim3(2, 8, 16), 512, W_SMEM, s1>>>(nullptr, nullptr, 0);
    cudaEventRecord(evB, s1);

    // main: flash in two batch halves, then add (needs beta)
    cudaStreamWaitEvent(0, evVA, 0);
    flash_tc<<<dim3(TQ / 128, NH, 4), 256, FSMEM>>>(out, 0);
    cudaStreamWaitEvent(0, evVB, 0);
    flash_tc<<<dim3(TQ / 128, NH, 4), 256, FSMEM>>>(out, 4);
    cudaStreamWaitEvent(0, evB, 0);
    add_out<<<2048, 256>>>((float4*)out);
}